// round 3
// baseline (speedup 1.0000x reference)
#include <cuda_runtime.h>
#include <cstdint>
#include <cstddef>

// Problem constants
#define NB   4        // batch
#define NP   1024     // local tokens (32x32)
#define DMODEL 256
#define HWG  4096     // global tokens (64x64)
#define NHEADS 8
#define DH   32
// -ln(10000)/256
#define NEG_LOG1E4_OVER_D (-0.035977892078030406f)
#define ATTN_SCALE 0.17677669529663687f   // 1/sqrt(32)

// ---------------- scratch (static device allocations; no cudaMalloc) ----------------
__device__ float g_lf_pe[NB * NP * DMODEL];     // local feat + pos enc  (4 MB)
__device__ float g_gf_pe[NB * HWG * DMODEL];    // transposed global feat + pos enc (16 MB)
__device__ float g_q[NB * NP * DMODEL];
__device__ float g_k[NB * HWG * DMODEL];
__device__ float g_v[NB * HWG * DMODEL];
__device__ float g_attn[NB * NP * DMODEL];

// ---------------- kernel 1: local_feat + positional encoding (32x32 grid) ------------
__global__ __launch_bounds__(256) void pe_local_kernel(const float* __restrict__ in,
                                                       float* __restrict__ out) {
    int idx = blockIdx.x * 256 + threadIdx.x;      // < NB*NP*DMODEL = 2^20
    int d = idx & (DMODEL - 1);
    int p = (idx >> 8) & (NP - 1);
    float x = (float)(p & 31) * (1.0f / 31.0f);
    float y = (float)(p >> 5) * (1.0f / 31.0f);
    float div = __expf((float)(d & ~1) * NEG_LOG1E4_OVER_D);
    float pe = (d & 1) ? __cosf(y * div) : __sinf(x * div);
    out[idx] = in[idx] + pe;
}

// ---------------- kernel 2: transpose global_feat (n,d,hw)->(n,hw,d) + pos enc -------
__global__ __launch_bounds__(256) void transpose_pe_kernel(const float* __restrict__ gf,
                                                           float* __restrict__ out) {
    __shared__ float tile[32][33];
    int n  = blockIdx.z;
    int s0 = blockIdx.x * 32;
    int d0 = blockIdx.y * 32;
    int tx = threadIdx.x, ty = threadIdx.y;
    const float* g = gf + ((size_t)n * DMODEL + d0) * HWG + s0;
#pragma unroll
    for (int k = 0; k < 4; ++k)
        tile[ty + 8 * k][tx] = g[(size_t)(ty + 8 * k) * HWG + tx];   // tile[d_loc][s_loc]
    __syncthreads();
#pragma unroll
    for (int k = 0; k < 4; ++k) {
        int s = s0 + ty + 8 * k;
        int d = d0 + tx;
        float x = (float)(s & 63) * (1.0f / 63.0f);
        float y = (float)(s >> 6) * (1.0f / 63.0f);
        float div = __expf((float)(d & ~1) * NEG_LOG1E4_OVER_D);
        float pe = (d & 1) ? __cosf(y * div) : __sinf(x * div);
        out[((size_t)n * HWG + s) * DMODEL + d] = tile[tx][ty + 8 * k] + pe;
    }
}

// ---------------- kernel 3: C[M,256] = (A (+A2)) @ W^T + bias ------------------------
// BM=BN=64, BK=16, 256 threads, 4x4 microtile per thread.
__global__ __launch_bounds__(256) void gemm256_kernel(const float* __restrict__ A,
                                                      const float* __restrict__ A2,
                                                      const float* __restrict__ W,
                                                      const float* __restrict__ bias,
                                                      float* __restrict__ C) {
    __shared__ float As[16][68];
    __shared__ float Ws[16][68];
    int m0 = blockIdx.x * 64;
    int o0 = blockIdx.y * 64;
    int tid = threadIdx.x;
    int tr = tid >> 4, tc = tid & 15;

    float acc[4][4] = {};
    int lr  = tid >> 2;          // 0..63 (tile row)
    int lc4 = (tid & 3) * 4;     // 0,4,8,12

    const float* Ap  = A + (size_t)(m0 + lr) * DMODEL + lc4;
    const float* A2p = A2 ? A2 + (size_t)(m0 + lr) * DMODEL + lc4 : nullptr;
    const float* Wp  = W + (size_t)(o0 + lr) * DMODEL + lc4;

    for (int k0 = 0; k0 < DMODEL; k0 += 16) {
        float4 av = *(const float4*)(Ap + k0);
        if (A2p) {
            float4 a2 = *(const float4*)(A2p + k0);
            av.x += a2.x; av.y += a2.y; av.z += a2.z; av.w += a2.w;
        }
        float4 wv = *(const float4*)(Wp + k0);
        As[lc4 + 0][lr] = av.x; As[lc4 + 1][lr] = av.y;
        As[lc4 + 2][lr] = av.z; As[lc4 + 3][lr] = av.w;
        Ws[lc4 + 0][lr] = wv.x; Ws[lc4 + 1][lr] = wv.y;
        Ws[lc4 + 2][lr] = wv.z; Ws[lc4 + 3][lr] = wv.w;
        __syncthreads();
#pragma unroll
        for (int kk = 0; kk < 16; ++kk) {
            float4 a = *(const float4*)&As[kk][tr * 4];
            float4 w = *(const float4*)&Ws[kk][tc * 4];
            acc[0][0] += a.x * w.x; acc[0][1] += a.x * w.y; acc[0][2] += a.x * w.z; acc[0][3] += a.x * w.w;
            acc[1][0] += a.y * w.x; acc[1][1] += a.y * w.y; acc[1][2] += a.y * w.z; acc[1][3] += a.y * w.w;
            acc[2][0] += a.z * w.x; acc[2][1] += a.z * w.y; acc[2][2] += a.z * w.z; acc[2][3] += a.z * w.w;
            acc[3][0] += a.w * w.x; acc[3][1] += a.w * w.y; acc[3][2] += a.w * w.z; acc[3][3] += a.w * w.w;
        }
        __syncthreads();
    }

    float4 bv = *(const float4*)(bias + o0 + tc * 4);
#pragma unroll
    for (int i = 0; i < 4; ++i) {
        float4 r;
        r.x = acc[i][0] + bv.x; r.y = acc[i][1] + bv.y;
        r.z = acc[i][2] + bv.z; r.w = acc[i][3] + bv.w;
        *(float4*)(C + (size_t)(m0 + tr * 4 + i) * DMODEL + o0 + tc * 4) = r;
    }
}

// ---------------- kernel 4: flash attention ------------------------------------------
// Per block: (q-tile of 64, head, batch). 256 threads (16x16), 4x4 S microtile/thread.
__global__ __launch_bounds__(256) void flash_attn_kernel(const float* __restrict__ Q,
                                                         const float* __restrict__ K,
                                                         const float* __restrict__ V,
                                                         float* __restrict__ O) {
    __shared__ float Qs[32][68];    // [d][q]   (transposed)
    __shared__ float Ks[32][68];    // [d][k]   (transposed)
    __shared__ float Vs[64][32];    // [k][d]
    __shared__ float Pt[64][68];    // [k][q]   (transposed probabilities)

    int qt = blockIdx.x, h = blockIdx.y, n = blockIdx.z;
    int tid = threadIdx.x;
    int tr = tid >> 4, tc = tid & 15;

    const float* Qb = Q + ((size_t)(n * NP + qt * 64)) * DMODEL + h * DH;
    for (int i = tid; i < 512; i += 256) {          // 64 rows x 8 float4
        int r = i >> 3, c4 = (i & 7) * 4;
        float4 qv = *(const float4*)(Qb + (size_t)r * DMODEL + c4);
        Qs[c4 + 0][r] = qv.x * ATTN_SCALE;
        Qs[c4 + 1][r] = qv.y * ATTN_SCALE;
        Qs[c4 + 2][r] = qv.z * ATTN_SCALE;
        Qs[c4 + 3][r] = qv.w * ATTN_SCALE;
    }

    float m_[4], l_[4], o_[4][2];
#pragma unroll
    for (int i = 0; i < 4; ++i) { m_[i] = -1e30f; l_[i] = 0.0f; o_[i][0] = 0.0f; o_[i][1] = 0.0f; }

    for (int kt = 0; kt < HWG / 64; ++kt) {
        __syncthreads();   // prior iteration's reads of Ks/Vs/Pt (and the Qs stores) complete
        const float* Kb = K + ((size_t)(n * HWG + kt * 64)) * DMODEL + h * DH;
        const float* Vb = V + ((size_t)(n * HWG + kt * 64)) * DMODEL + h * DH;
        for (int i = tid; i < 512; i += 256) {
            int r = i >> 3, c4 = (i & 7) * 4;
            float4 kv = *(const float4*)(Kb + (size_t)r * DMODEL + c4);
            Ks[c4 + 0][r] = kv.x; Ks[c4 + 1][r] = kv.y;
            Ks[c4 + 2][r] = kv.z; Ks[c4 + 3][r] = kv.w;
            float4 vv = *(const float4*)(Vb + (size_t)r * DMODEL + c4);
            *(float4*)&Vs[r][c4] = vv;
        }
        __syncthreads();

        // S = Q K^T  (4x4 per thread, registers)
        float s[4][4] = {};
#pragma unroll
        for (int d = 0; d < 32; ++d) {
            float4 a = *(const float4*)&Qs[d][tr * 4];
            float4 b = *(const float4*)&Ks[d][tc * 4];
            s[0][0] += a.x * b.x; s[0][1] += a.x * b.y; s[0][2] += a.x * b.z; s[0][3] += a.x * b.w;
            s[1][0] += a.y * b.x; s[1][1] += a.y * b.y; s[1][2] += a.y * b.z; s[1][3] += a.y * b.w;
            s[2][0] += a.z * b.x; s[2][1] += a.z * b.y; s[2][2] += a.z * b.z; s[2][3] += a.z * b.w;
            s[3][0] += a.w * b.x; s[3][1] += a.w * b.y; s[3][2] += a.w * b.z; s[3][3] += a.w * b.w;
        }

        // online softmax per q-row (16 threads share a row; width-16 shfl reductions)
#pragma unroll
        for (int i = 0; i < 4; ++i) {
            float mx = fmaxf(fmaxf(s[i][0], s[i][1]), fmaxf(s[i][2], s[i][3]));
            mx = fmaxf(mx, __shfl_xor_sync(0xffffffffu, mx, 1, 16));
            mx = fmaxf(mx, __shfl_xor_sync(0xffffffffu, mx, 2, 16));
            mx = fmaxf(mx, __shfl_xor_sync(0xffffffffu, mx, 4, 16));
            mx = fmaxf(mx, __shfl_xor_sync(0xffffffffu, mx, 8, 16));
            float mn = fmaxf(m_[i], mx);
            float corr = __expf(m_[i] - mn);
            m_[i] = mn;
            float ss = 0.0f;
#pragma unroll
            for (int j = 0; j < 4; ++j) {
                float p = __expf(s[i][j] - mn);
                s[i][j] = p;
                ss += p;
            }
            ss += __shfl_xor_sync(0xffffffffu, ss, 1, 16);
            ss += __shfl_xor_sync(0xffffffffu, ss, 2, 16);
            ss += __shfl_xor_sync(0xffffffffu, ss, 4, 16);
            ss += __shfl_xor_sync(0xffffffffu, ss, 8, 16);
            l_[i] = l_[i] * corr + ss;
            o_[i][0] *= corr;
            o_[i][1] *= corr;
        }

        // stage P transposed: Pt[kcol][qrow]
#pragma unroll
        for (int jj = 0; jj < 4; ++jj) {
            float4 pv = make_float4(s[0][jj], s[1][jj], s[2][jj], s[3][jj]);
            *(float4*)&Pt[tc * 4 + jj][tr * 4] = pv;
        }
        __syncthreads();

        // O += P @ V   (thread owns rows 4tr..4tr+3, cols {2tc, 2tc+1})
#pragma unroll
        for (int j = 0; j < 64; ++j) {
            float4 p  = *(const float4*)&Pt[j][tr * 4];
            float2 vv = *(const float2*)&Vs[j][tc * 2];
            o_[0][0] += p.x * vv.x; o_[0][1] += p.x * vv.y;
            o_[1][0] += p.y * vv.x; o_[1][1] += p.y * vv.y;
            o_[2][0] += p.z * vv.x; o_[2][1] += p.z * vv.y;
            o_[3][0] += p.w * vv.x; o_[3][1] += p.w * vv.y;
        }
    }

    float* Ob = O + ((size_t)(n * NP + qt * 64)) * DMODEL + h * DH;
#pragma unroll
    for (int i = 0; i < 4; ++i) {
        float inv = 1.0f / l_[i];
        float2 r = make_float2(o_[i][0] * inv, o_[i][1] * inv);
        *(float2*)(Ob + (size_t)(tr * 4 + i) * DMODEL + tc * 2) = r;
    }
}

// ---------------- launch ------------------------------------------------------------
extern "C" void kernel_launch(void* const* d_in, const int* in_sizes, int n_in,
                              void* d_out, int out_size) {
    const float* local_feat  = (const float*)d_in[0];
    const float* global_feat = (const float*)d_in[1];
    const float* Wq = (const float*)d_in[2];
    const float* bq = (const float*)d_in[3];
    const float* Wk = (const float*)d_in[4];
    const float* bk = (const float*)d_in[5];
    const float* Wv = (const float*)d_in[6];
    const float* bv = (const float*)d_in[7];
    const float* Wo = (const float*)d_in[8];
    const float* bo = (const float*)d_in[9];
    float* out = (float*)d_out;

    float *lf_pe, *gf_pe, *q, *k, *v, *attn;
    cudaGetSymbolAddress((void**)&lf_pe, g_lf_pe);
    cudaGetSymbolAddress((void**)&gf_pe, g_gf_pe);
    cudaGetSymbolAddress((void**)&q,     g_q);
    cudaGetSymbolAddress((void**)&k,     g_k);
    cudaGetSymbolAddress((void**)&v,     g_v);
    cudaGetSymbolAddress((void**)&attn,  g_attn);

    // 1. positional encodings
    pe_local_kernel<<<(NB * NP * DMODEL) / 256, 256>>>(local_feat, lf_pe);
    transpose_pe_kernel<<<dim3(HWG / 32, DMODEL / 32, NB), dim3(32, 8)>>>(global_feat, gf_pe);

    // 2. Q/K/V projections
    gemm256_kernel<<<dim3((NB * NP) / 64, DMODEL / 64), 256>>>(lf_pe, nullptr, Wq, bq, q);
    gemm256_kernel<<<dim3((NB * HWG) / 64, DMODEL / 64), 256>>>(gf_pe, nullptr, Wk, bk, k);
    gemm256_kernel<<<dim3((NB * HWG) / 64, DMODEL / 64), 256>>>(gf_pe, nullptr, Wv, bv, v);

    // 3. attention
    flash_attn_kernel<<<dim3(NP / 64, NHEADS, NB), 256>>>(q, k, v, attn);

    // 4. output projection with fused residual (lf_pe + attn)
    gemm256_kernel<<<dim3((NB * NP) / 64, DMODEL / 64), 256>>>(lf_pe, attn, Wo, bo, out);
}

// round 5
// speedup vs baseline: 2.1013x; 2.1013x over previous
#include <cuda_runtime.h>
#include <cstdint>
#include <cstddef>

// Problem constants
#define NB   4        // batch
#define NP   1024     // local tokens (32x32)
#define DMODEL 256
#define HWG  4096     // global tokens (64x64)
#define NHEADS 8
#define DH   32
// -ln(10000)/256
#define NEG_LOG1E4_OVER_D (-0.035977892078030406f)
#define ATTN_SCALE 0.17677669529663687f   // 1/sqrt(32)

// ---------------- scratch (static device allocations; no cudaMalloc) ----------------
__device__ float g_lf_pe[NB * NP * DMODEL];     // local feat + pos enc  (4 MB)
__device__ float g_gf_pe[NB * HWG * DMODEL];    // transposed global feat + pos enc (16 MB)
__device__ float g_q[NB * NP * DMODEL];
__device__ float g_k[NB * HWG * DMODEL];
__device__ float g_v[NB * HWG * DMODEL];
__device__ float g_attn[NB * NP * DMODEL];

// ---------------- tf32 helpers -------------------------------------------------------
__device__ __forceinline__ float to_tf32(float x) {
    uint32_t u;
    asm("cvt.rna.tf32.f32 %0, %1;" : "=r"(u) : "f"(x));
    return __uint_as_float(u);
}

// D (in-place C) = A(16x8) * B(8x8) + D, tf32 inputs, f32 accumulate.
__device__ __forceinline__ void mma_tf32(float* d,
                                         uint32_t a0, uint32_t a1, uint32_t a2, uint32_t a3,
                                         uint32_t b0, uint32_t b1) {
    asm volatile(
        "mma.sync.aligned.m16n8k8.row.col.f32.tf32.tf32.f32 "
        "{%0,%1,%2,%3}, {%4,%5,%6,%7}, {%8,%9}, {%0,%1,%2,%3};\n"
        : "+f"(d[0]), "+f"(d[1]), "+f"(d[2]), "+f"(d[3])
        : "r"(a0), "r"(a1), "r"(a2), "r"(a3), "r"(b0), "r"(b1));
}

// ---------------- kernel 1: local_feat + positional encoding (32x32 grid) ------------
__global__ __launch_bounds__(256) void pe_local_kernel(const float* __restrict__ in,
                                                       float* __restrict__ out) {
    int idx = blockIdx.x * 256 + threadIdx.x;      // < NB*NP*DMODEL = 2^20
    int d = idx & (DMODEL - 1);
    int p = (idx >> 8) & (NP - 1);
    float x = (float)(p & 31) * (1.0f / 31.0f);
    float y = (float)(p >> 5) * (1.0f / 31.0f);
    float div = __expf((float)(d & ~1) * NEG_LOG1E4_OVER_D);
    float pe = (d & 1) ? __cosf(y * div) : __sinf(x * div);
    out[idx] = in[idx] + pe;
}

// ---------------- kernel 2: transpose global_feat (n,d,hw)->(n,hw,d) + pos enc -------
__global__ __launch_bounds__(256) void transpose_pe_kernel(const float* __restrict__ gf,
                                                           float* __restrict__ out) {
    __shared__ float tile[32][33];
    int n  = blockIdx.z;
    int s0 = blockIdx.x * 32;
    int d0 = blockIdx.y * 32;
    int tx = threadIdx.x, ty = threadIdx.y;
    const float* g = gf + ((size_t)n * DMODEL + d0) * HWG + s0;
#pragma unroll
    for (int k = 0; k < 4; ++k)
        tile[ty + 8 * k][tx] = g[(size_t)(ty + 8 * k) * HWG + tx];   // tile[d_loc][s_loc]
    __syncthreads();
#pragma unroll
    for (int k = 0; k < 4; ++k) {
        int s = s0 + ty + 8 * k;
        int d = d0 + tx;
        float x = (float)(s & 63) * (1.0f / 63.0f);
        float y = (float)(s >> 6) * (1.0f / 63.0f);
        float div = __expf((float)(d & ~1) * NEG_LOG1E4_OVER_D);
        float pe = (d & 1) ? __cosf(y * div) : __sinf(x * div);
        out[((size_t)n * HWG + s) * DMODEL + d] = tile[tx][ty + 8 * k] + pe;
    }
}

// ---------------- kernel 3: C[M,256] = (A (+A2)) @ W^T + bias ------------------------
// BM=BN=64, BK=16, 256 threads, 4x4 microtile per thread.  (fp32 SIMT; proven correct)
__global__ __launch_bounds__(256) void gemm256_kernel(const float* __restrict__ A,
                                                      const float* __restrict__ A2,
                                                      const float* __restrict__ W,
                                                      const float* __restrict__ bias,
                                                      float* __restrict__ C) {
    __shared__ float As[16][68];
    __shared__ float Ws[16][68];
    int m0 = blockIdx.x * 64;
    int o0 = blockIdx.y * 64;
    int tid = threadIdx.x;
    int tr = tid >> 4, tc = tid & 15;

    float acc[4][4] = {};
    int lr  = tid >> 2;          // 0..63 (tile row)
    int lc4 = (tid & 3) * 4;     // 0,4,8,12

    const float* Ap  = A + (size_t)(m0 + lr) * DMODEL + lc4;
    const float* A2p = A2 ? A2 + (size_t)(m0 + lr) * DMODEL + lc4 : nullptr;
    const float* Wp  = W + (size_t)(o0 + lr) * DMODEL + lc4;

    for (int k0 = 0; k0 < DMODEL; k0 += 16) {
        float4 av = *(const float4*)(Ap + k0);
        if (A2p) {
            float4 a2 = *(const float4*)(A2p + k0);
            av.x += a2.x; av.y += a2.y; av.z += a2.z; av.w += a2.w;
        }
        float4 wv = *(const float4*)(Wp + k0);
        As[lc4 + 0][lr] = av.x; As[lc4 + 1][lr] = av.y;
        As[lc4 + 2][lr] = av.z; As[lc4 + 3][lr] = av.w;
        Ws[lc4 + 0][lr] = wv.x; Ws[lc4 + 1][lr] = wv.y;
        Ws[lc4 + 2][lr] = wv.z; Ws[lc4 + 3][lr] = wv.w;
        __syncthreads();
#pragma unroll
        for (int kk = 0; kk < 16; ++kk) {
            float4 a = *(const float4*)&As[kk][tr * 4];
            float4 w = *(const float4*)&Ws[kk][tc * 4];
            acc[0][0] += a.x * w.x; acc[0][1] += a.x * w.y; acc[0][2] += a.x * w.z; acc[0][3] += a.x * w.w;
            acc[1][0] += a.y * w.x; acc[1][1] += a.y * w.y; acc[1][2] += a.y * w.z; acc[1][3] += a.y * w.w;
            acc[2][0] += a.z * w.x; acc[2][1] += a.z * w.y; acc[2][2] += a.z * w.z; acc[2][3] += a.z * w.w;
            acc[3][0] += a.w * w.x; acc[3][1] += a.w * w.y; acc[3][2] += a.w * w.z; acc[3][3] += a.w * w.w;
        }
        __syncthreads();
    }

    float4 bv = *(const float4*)(bias + o0 + tc * 4);
#pragma unroll
    for (int i = 0; i < 4; ++i) {
        float4 r;
        r.x = acc[i][0] + bv.x; r.y = acc[i][1] + bv.y;
        r.z = acc[i][2] + bv.z; r.w = acc[i][3] + bv.w;
        *(float4*)(C + (size_t)(m0 + tr * 4 + i) * DMODEL + o0 + tc * 4) = r;
    }
}

// ---------------- kernel 4: flash attention, tf32 tensor-core version ----------------
// Block = (q-tile 64, head, batch); 4 warps; warp owns 16 q-rows.
// m16n8k8 tf32 mma for both Q·K^T and P·V.
__global__ __launch_bounds__(128) void flash_attn_mma_kernel(const float* __restrict__ Q,
                                                             const float* __restrict__ K,
                                                             const float* __restrict__ V,
                                                             float* __restrict__ O) {
    __shared__ float Ks[64][36];   // [key][d]  pad 4 -> K B-frag loads conflict-free
    __shared__ float Vs[64][36];   // [key][d]  (2-way conflict on B-frag loads)
    __shared__ float Ps[64][68];   // [q][key]  pad 4 -> A-frag loads conflict-free

    int qt = blockIdx.x, h = blockIdx.y, n = blockIdx.z;
    int tid  = threadIdx.x;
    int warp = tid >> 5, lane = tid & 31;
    int g = lane >> 2;     // group id (row within 8)
    int c = lane & 3;      // thread-in-group (col within 4)

    // ---- preload Q fragments (reused for all 64 key tiles) ----
    const float* Qb = Q + ((size_t)(n * NP + qt * 64 + warp * 16)) * DMODEL + h * DH;
    uint32_t qf[4][4];
#pragma unroll
    for (int ks = 0; ks < 4; ++ks) {
        qf[ks][0] = __float_as_uint(to_tf32(Qb[(size_t)g       * DMODEL + ks * 8 + c    ] * ATTN_SCALE));
        qf[ks][1] = __float_as_uint(to_tf32(Qb[(size_t)(g + 8) * DMODEL + ks * 8 + c    ] * ATTN_SCALE));
        qf[ks][2] = __float_as_uint(to_tf32(Qb[(size_t)g       * DMODEL + ks * 8 + c + 4] * ATTN_SCALE));
        qf[ks][3] = __float_as_uint(to_tf32(Qb[(size_t)(g + 8) * DMODEL + ks * 8 + c + 4] * ATTN_SCALE));
    }

    // online softmax state: thread covers rows (warp*16+g) -> m0/l0 and (+8) -> m1/l1
    float m0 = -1e30f, m1 = -1e30f, l0 = 0.0f, l1 = 0.0f;
    float oacc[4][4] = {};   // [d-ntile][creg]: 16 q-rows x 32 d

    const float* Kb0 = K + (size_t)n * HWG * DMODEL + h * DH;
    const float* Vb0 = V + (size_t)n * HWG * DMODEL + h * DH;

    for (int kt = 0; kt < HWG / 64; ++kt) {
        __syncthreads();    // previous iteration's Ks/Vs reads complete
        const float* Kb = Kb0 + (size_t)kt * 64 * DMODEL;
        const float* Vb = Vb0 + (size_t)kt * 64 * DMODEL;
#pragma unroll
        for (int i = tid; i < 512; i += 128) {     // 64 rows x 8 float4 per matrix
            int r = i >> 3, c4 = (i & 7) * 4;
            float4 kv = *(const float4*)(Kb + (size_t)r * DMODEL + c4);
            float4 vv = *(const float4*)(Vb + (size_t)r * DMODEL + c4);
            kv.x = to_tf32(kv.x); kv.y = to_tf32(kv.y); kv.z = to_tf32(kv.z); kv.w = to_tf32(kv.w);
            vv.x = to_tf32(vv.x); vv.y = to_tf32(vv.y); vv.z = to_tf32(vv.z); vv.w = to_tf32(vv.w);
            *(float4*)&Ks[r][c4] = kv;
            *(float4*)&Vs[r][c4] = vv;
        }
        __syncthreads();

        // ---- S = Q K^T : 8 key n-tiles x 4 d k-steps ----
        float sacc[8][4];
#pragma unroll
        for (int nt = 0; nt < 8; ++nt) {
            sacc[nt][0] = 0.f; sacc[nt][1] = 0.f; sacc[nt][2] = 0.f; sacc[nt][3] = 0.f;
#pragma unroll
            for (int ks = 0; ks < 4; ++ks) {
                uint32_t b0 = __float_as_uint(Ks[nt * 8 + g][ks * 8 + c]);
                uint32_t b1 = __float_as_uint(Ks[nt * 8 + g][ks * 8 + c + 4]);
                mma_tf32(sacc[nt], qf[ks][0], qf[ks][1], qf[ks][2], qf[ks][3], b0, b1);
            }
        }

        // ---- online softmax (rows r0 = warp*16+g, r1 = r0+8) ----
        float mx0 = -1e30f, mx1 = -1e30f;
#pragma unroll
        for (int nt = 0; nt < 8; ++nt) {
            mx0 = fmaxf(mx0, fmaxf(sacc[nt][0], sacc[nt][1]));
            mx1 = fmaxf(mx1, fmaxf(sacc[nt][2], sacc[nt][3]));
        }
        mx0 = fmaxf(mx0, __shfl_xor_sync(0xffffffffu, mx0, 1));
        mx0 = fmaxf(mx0, __shfl_xor_sync(0xffffffffu, mx0, 2));
        mx1 = fmaxf(mx1, __shfl_xor_sync(0xffffffffu, mx1, 1));
        mx1 = fmaxf(mx1, __shfl_xor_sync(0xffffffffu, mx1, 2));
        float nm0 = fmaxf(m0, mx0), nm1 = fmaxf(m1, mx1);
        float corr0 = __expf(m0 - nm0), corr1 = __expf(m1 - nm1);
        m0 = nm0; m1 = nm1;

        float s0 = 0.0f, s1 = 0.0f;
        int pr0 = warp * 16 + g, pr1 = pr0 + 8;
#pragma unroll
        for (int nt = 0; nt < 8; ++nt) {
            float p0 = __expf(sacc[nt][0] - m0);
            float p1 = __expf(sacc[nt][1] - m0);
            float p2 = __expf(sacc[nt][2] - m1);
            float p3 = __expf(sacc[nt][3] - m1);
            s0 += p0 + p1; s1 += p2 + p3;
            *(float2*)&Ps[pr0][nt * 8 + 2 * c] = make_float2(p0, p1);
            *(float2*)&Ps[pr1][nt * 8 + 2 * c] = make_float2(p2, p3);
        }
        s0 += __shfl_xor_sync(0xffffffffu, s0, 1);
        s0 += __shfl_xor_sync(0xffffffffu, s0, 2);
        s1 += __shfl_xor_sync(0xffffffffu, s1, 1);
        s1 += __shfl_xor_sync(0xffffffffu, s1, 2);
        l0 = l0 * corr0 + s0;
        l1 = l1 * corr1 + s1;
#pragma unroll
        for (int dt = 0; dt < 4; ++dt) {
            oacc[dt][0] *= corr0; oacc[dt][1] *= corr0;
            oacc[dt][2] *= corr1; oacc[dt][3] *= corr1;
        }
        __syncwarp();    // Ps rows are warp-private: warp-level sync suffices

        // ---- O += P V : 8 key k-steps x 4 d n-tiles ----
#pragma unroll
        for (int ks = 0; ks < 8; ++ks) {
            uint32_t a0 = __float_as_uint(Ps[pr0][ks * 8 + c]);
            uint32_t a1 = __float_as_uint(Ps[pr1][ks * 8 + c]);
            uint32_t a2 = __float_as_uint(Ps[pr0][ks * 8 + c + 4]);
            uint32_t a3 = __float_as_uint(Ps[pr1][ks * 8 + c + 4]);
#pragma unroll
            for (int dt = 0; dt < 4; ++dt) {
                uint32_t b0 = __float_as_uint(Vs[ks * 8 + c][dt * 8 + g]);
                uint32_t b1 = __float_as_uint(Vs[ks * 8 + c + 4][dt * 8 + g]);
                mma_tf32(oacc[dt], a0, a1, a2, a3, b0, b1);
            }
        }
    }

    // ---- epilogue: divide by l, store ----
    float inv0 = 1.0f / l0, inv1 = 1.0f / l1;
    float* Ob = O + ((size_t)(n * NP + qt * 64 + warp * 16)) * DMODEL + h * DH;
#pragma unroll
    for (int dt = 0; dt < 4; ++dt) {
        *(float2*)(Ob + (size_t)g       * DMODEL + dt * 8 + 2 * c) =
            make_float2(oacc[dt][0] * inv0, oacc[dt][1] * inv0);
        *(float2*)(Ob + (size_t)(g + 8) * DMODEL + dt * 8 + 2 * c) =
            make_float2(oacc[dt][2] * inv1, oacc[dt][3] * inv1);
    }
}

// ---------------- launch ------------------------------------------------------------
extern "C" void kernel_launch(void* const* d_in, const int* in_sizes, int n_in,
                              void* d_out, int out_size) {
    const float* local_feat  = (const float*)d_in[0];
    const float* global_feat = (const float*)d_in[1];
    const float* Wq = (const float*)d_in[2];
    const float* bq = (const float*)d_in[3];
    const float* Wk = (const float*)d_in[4];
    const float* bk = (const float*)d_in[5];
    const float* Wv = (const float*)d_in[6];
    const float* bv = (const float*)d_in[7];
    const float* Wo = (const float*)d_in[8];
    const float* bo = (const float*)d_in[9];
    float* out = (float*)d_out;

    float *lf_pe, *gf_pe, *q, *k, *v, *attn;
    cudaGetSymbolAddress((void**)&lf_pe, g_lf_pe);
    cudaGetSymbolAddress((void**)&gf_pe, g_gf_pe);
    cudaGetSymbolAddress((void**)&q,     g_q);
    cudaGetSymbolAddress((void**)&k,     g_k);
    cudaGetSymbolAddress((void**)&v,     g_v);
    cudaGetSymbolAddress((void**)&attn,  g_attn);

    // 1. positional encodings
    pe_local_kernel<<<(NB * NP * DMODEL) / 256, 256>>>(local_feat, lf_pe);
    transpose_pe_kernel<<<dim3(HWG / 32, DMODEL / 32, NB), dim3(32, 8)>>>(global_feat, gf_pe);

    // 2. Q/K/V projections
    gemm256_kernel<<<dim3((NB * NP) / 64, DMODEL / 64), 256>>>(lf_pe, nullptr, Wq, bq, q);
    gemm256_kernel<<<dim3((NB * HWG) / 64, DMODEL / 64), 256>>>(gf_pe, nullptr, Wk, bk, k);
    gemm256_kernel<<<dim3((NB * HWG) / 64, DMODEL / 64), 256>>>(gf_pe, nullptr, Wv, bv, v);

    // 3. attention (tf32 tensor cores)
    flash_attn_mma_kernel<<<dim3(NP / 64, NHEADS, NB), 128>>>(q, k, v, attn);

    // 4. output projection with fused residual (lf_pe + attn)
    gemm256_kernel<<<dim3((NB * NP) / 64, DMODEL / 64), 256>>>(lf_pe, attn, Wo, bo, out);
}

// round 7
// speedup vs baseline: 2.8061x; 1.3354x over previous
#include <cuda_runtime.h>
#include <cstdint>
#include <cstddef>

// Problem constants
#define NB   4        // batch
#define NP   1024     // local tokens (32x32)
#define DMODEL 256
#define HWG  4096     // global tokens (64x64)
#define NHEADS 8
#define DH   32
// -ln(10000)/256
#define NEG_LOG1E4_OVER_D (-0.035977892078030406f)
#define ATTN_SCALE 0.17677669529663687f   // 1/sqrt(32)

// ---------------- scratch (static device allocations; no cudaMalloc) ----------------
__device__ float g_lf_pe[NB * NP * DMODEL];     // local feat + pos enc  (4 MB)
__device__ float g_gf_pe[NB * HWG * DMODEL];    // transposed global feat + pos enc (16 MB)
__device__ float g_q[NB * NP * DMODEL];
__device__ float g_k[NB * HWG * DMODEL];
__device__ float g_v[NB * HWG * DMODEL];
__device__ float g_attn[NB * NP * DMODEL];

// ---------------- tf32 helpers -------------------------------------------------------
__device__ __forceinline__ float to_tf32(float x) {
    uint32_t u;
    asm("cvt.rna.tf32.f32 %0, %1;" : "=r"(u) : "f"(x));
    return __uint_as_float(u);
}

// D (in-place C) = A(16x8) * B(8x8) + D, tf32 inputs, f32 accumulate.
__device__ __forceinline__ void mma_tf32(float* d,
                                         uint32_t a0, uint32_t a1, uint32_t a2, uint32_t a3,
                                         uint32_t b0, uint32_t b1) {
    asm volatile(
        "mma.sync.aligned.m16n8k8.row.col.f32.tf32.tf32.f32 "
        "{%0,%1,%2,%3}, {%4,%5,%6,%7}, {%8,%9}, {%0,%1,%2,%3};\n"
        : "+f"(d[0]), "+f"(d[1]), "+f"(d[2]), "+f"(d[3])
        : "r"(a0), "r"(a1), "r"(a2), "r"(a3), "r"(b0), "r"(b1));
}

// ---------------- kernel 1: local_feat + positional encoding (32x32 grid) ------------
__global__ __launch_bounds__(256) void pe_local_kernel(const float* __restrict__ in,
                                                       float* __restrict__ out) {
    int idx = blockIdx.x * 256 + threadIdx.x;      // < NB*NP*DMODEL = 2^20
    int d = idx & (DMODEL - 1);
    int p = (idx >> 8) & (NP - 1);
    float x = (float)(p & 31) * (1.0f / 31.0f);
    float y = (float)(p >> 5) * (1.0f / 31.0f);
    float div = __expf((float)(d & ~1) * NEG_LOG1E4_OVER_D);
    float pe = (d & 1) ? __cosf(y * div) : __sinf(x * div);
    out[idx] = in[idx] + pe;
}

// ---------------- kernel 2: transpose global_feat (n,d,hw)->(n,hw,d) + pos enc -------
__global__ __launch_bounds__(256) void transpose_pe_kernel(const float* __restrict__ gf,
                                                           float* __restrict__ out) {
    __shared__ float tile[32][33];
    int n  = blockIdx.z;
    int s0 = blockIdx.x * 32;
    int d0 = blockIdx.y * 32;
    int tx = threadIdx.x, ty = threadIdx.y;
    const float* g = gf + ((size_t)n * DMODEL + d0) * HWG + s0;
#pragma unroll
    for (int k = 0; k < 4; ++k)
        tile[ty + 8 * k][tx] = g[(size_t)(ty + 8 * k) * HWG + tx];   // tile[d_loc][s_loc]
    __syncthreads();
#pragma unroll
    for (int k = 0; k < 4; ++k) {
        int s = s0 + ty + 8 * k;
        int d = d0 + tx;
        float x = (float)(s & 63) * (1.0f / 63.0f);
        float y = (float)(s >> 6) * (1.0f / 63.0f);
        float div = __expf((float)(d & ~1) * NEG_LOG1E4_OVER_D);
        float pe = (d & 1) ? __cosf(y * div) : __sinf(x * div);
        out[((size_t)n * HWG + s) * DMODEL + d] = tile[tx][ty + 8 * k] + pe;
    }
}

// ---------------- kernel 3: tf32 tensor-core GEMM  C[M,256] = (A (+A2)) @ W^T + b ----
// Block tile 128(M) x 64(N), BK=32, 8 warps in 4x2 grid, warp tile 32x32.
// Register-prefetch double buffering of the next K-chunk.
__global__ __launch_bounds__(256) void gemm_tf32_kernel(const float* __restrict__ A,
                                                        const float* __restrict__ A2,
                                                        const float* __restrict__ W,
                                                        const float* __restrict__ bias,
                                                        float* __restrict__ C) {
    __shared__ float As[128][36];   // [m][k]  stride 36 -> frag LDS conflict-free
    __shared__ float Ws[64][36];    // [n][k]

    int m0 = blockIdx.x * 128, o0 = blockIdx.y * 64;
    int tid = threadIdx.x;
    int warp = tid >> 5, lane = tid & 31;
    int g = lane >> 2, c = lane & 3;
    int wm = (warp & 3) * 32;       // warp m offset within block
    int wn = (warp >> 2) * 32;      // warp n offset within block

    int lr  = tid >> 3;             // 0..31 (staging row)
    int lk4 = (tid & 7) * 4;        // 0,4,...,28 (staging k offset)

    const float* Ap  = A + (size_t)(m0 + lr) * DMODEL + lk4;
    const float* A2p = A2 ? A2 + (size_t)(m0 + lr) * DMODEL + lk4 : nullptr;
    const float* Wp  = W + (size_t)(o0 + lr) * DMODEL + lk4;

    float4 ra[4], rw[2];

    // prefetch K-chunk 0
#pragma unroll
    for (int i = 0; i < 4; ++i) {
        float4 v = *(const float4*)(Ap + (size_t)(32 * i) * DMODEL);
        if (A2p) {
            float4 u = *(const float4*)(A2p + (size_t)(32 * i) * DMODEL);
            v.x += u.x; v.y += u.y; v.z += u.z; v.w += u.w;
        }
        ra[i] = v;
    }
#pragma unroll
    for (int i = 0; i < 2; ++i)
        rw[i] = *(const float4*)(Wp + (size_t)(32 * i) * DMODEL);

    float acc[2][4][4] = {};

    for (int kc = 0; kc < 8; ++kc) {
        // stage current chunk to smem (tf32-convert once here)
#pragma unroll
        for (int i = 0; i < 4; ++i) {
            float4 v = ra[i];
            v.x = to_tf32(v.x); v.y = to_tf32(v.y); v.z = to_tf32(v.z); v.w = to_tf32(v.w);
            *(float4*)&As[lr + 32 * i][lk4] = v;
        }
#pragma unroll
        for (int i = 0; i < 2; ++i) {
            float4 v = rw[i];
            v.x = to_tf32(v.x); v.y = to_tf32(v.y); v.z = to_tf32(v.z); v.w = to_tf32(v.w);
            *(float4*)&Ws[lr + 32 * i][lk4] = v;
        }
        __syncthreads();

        // prefetch next chunk (LDG latency hidden behind the mma loop)
        if (kc < 7) {
            int ko = (kc + 1) * 32;
#pragma unroll
            for (int i = 0; i < 4; ++i) {
                float4 v = *(const float4*)(Ap + ko + (size_t)(32 * i) * DMODEL);
                if (A2p) {
                    float4 u = *(const float4*)(A2p + ko + (size_t)(32 * i) * DMODEL);
                    v.x += u.x; v.y += u.y; v.z += u.z; v.w += u.w;
                }
                ra[i] = v;
            }
#pragma unroll
            for (int i = 0; i < 2; ++i)
                rw[i] = *(const float4*)(Wp + ko + (size_t)(32 * i) * DMODEL);
        }

        // compute: 4 k-steps of 8
#pragma unroll
        for (int ks = 0; ks < 4; ++ks) {
            int k = ks * 8;
            uint32_t af[2][4];
#pragma unroll
            for (int mt = 0; mt < 2; ++mt) {
                int r = wm + mt * 16;
                af[mt][0] = __float_as_uint(As[r + g    ][k + c    ]);
                af[mt][1] = __float_as_uint(As[r + g + 8][k + c    ]);
                af[mt][2] = __float_as_uint(As[r + g    ][k + c + 4]);
                af[mt][3] = __float_as_uint(As[r + g + 8][k + c + 4]);
            }
#pragma unroll
            for (int nt = 0; nt < 4; ++nt) {
                uint32_t b0 = __float_as_uint(Ws[wn + nt * 8 + g][k + c    ]);
                uint32_t b1 = __float_as_uint(Ws[wn + nt * 8 + g][k + c + 4]);
                mma_tf32(acc[0][nt], af[0][0], af[0][1], af[0][2], af[0][3], b0, b1);
                mma_tf32(acc[1][nt], af[1][0], af[1][1], af[1][2], af[1][3], b0, b1);
            }
        }
        __syncthreads();
    }

    // epilogue: bias + store
#pragma unroll
    for (int nt = 0; nt < 4; ++nt) {
        float2 bv = *(const float2*)(bias + o0 + wn + nt * 8 + 2 * c);
#pragma unroll
        for (int mt = 0; mt < 2; ++mt) {
            int row = m0 + wm + mt * 16 + g;
            float* Cp = C + (size_t)row * DMODEL + o0 + wn + nt * 8 + 2 * c;
            *(float2*)Cp = make_float2(acc[mt][nt][0] + bv.x, acc[mt][nt][1] + bv.y);
            *(float2*)(Cp + (size_t)8 * DMODEL) =
                make_float2(acc[mt][nt][2] + bv.x, acc[mt][nt][3] + bv.y);
        }
    }
}

// ---------------- kernel 4: flash attention, tf32 tensor-core version ----------------
// Block = (q-tile 64, head, batch); 4 warps; warp owns 16 q-rows.
// m16n8k8 tf32 mma for both Q·K^T and P·V.
__global__ __launch_bounds__(128) void flash_attn_mma_kernel(const float* __restrict__ Q,
                                                             const float* __restrict__ K,
                                                             const float* __restrict__ V,
                                                             float* __restrict__ O) {
    __shared__ float Ks[64][36];   // [key][d]  pad 4 -> K B-frag loads conflict-free
    __shared__ float Vs[64][36];   // [key][d]
    __shared__ float Ps[64][68];   // [q][key]  pad 4 -> A-frag loads conflict-free

    int qt = blockIdx.x, h = blockIdx.y, n = blockIdx.z;
    int tid  = threadIdx.x;
    int warp = tid >> 5, lane = tid & 31;
    int g = lane >> 2;     // group id (row within 8)
    int c = lane & 3;      // thread-in-group (col within 4)

    // ---- preload Q fragments (reused for all 64 key tiles) ----
    const float* Qb = Q + ((size_t)(n * NP + qt * 64 + warp * 16)) * DMODEL + h * DH;
    uint32_t qf[4][4];
#pragma unroll
    for (int ks = 0; ks < 4; ++ks) {
        qf[ks][0] = __float_as_uint(to_tf32(Qb[(size_t)g       * DMODEL + ks * 8 + c    ] * ATTN_SCALE));
        qf[ks][1] = __float_as_uint(to_tf32(Qb[(size_t)(g + 8) * DMODEL + ks * 8 + c    ] * ATTN_SCALE));
        qf[ks][2] = __float_as_uint(to_tf32(Qb[(size_t)g       * DMODEL + ks * 8 + c + 4] * ATTN_SCALE));
        qf[ks][3] = __float_as_uint(to_tf32(Qb[(size_t)(g + 8) * DMODEL + ks * 8 + c + 4] * ATTN_SCALE));
    }

    // online softmax state: thread covers rows (warp*16+g) -> m0/l0 and (+8) -> m1/l1
    float m0 = -1e30f, m1 = -1e30f, l0 = 0.0f, l1 = 0.0f;
    float oacc[4][4] = {};   // [d-ntile][creg]: 16 q-rows x 32 d

    const float* Kb0 = K + (size_t)n * HWG * DMODEL + h * DH;
    const float* Vb0 = V + (size_t)n * HWG * DMODEL + h * DH;

    for (int kt = 0; kt < HWG / 64; ++kt) {
        __syncthreads();    // previous iteration's Ks/Vs reads complete
        const float* Kb = Kb0 + (size_t)kt * 64 * DMODEL;
        const float* Vb = Vb0 + (size_t)kt * 64 * DMODEL;
#pragma unroll
        for (int i = tid; i < 512; i += 128) {     // 64 rows x 8 float4 per matrix
            int r = i >> 3, c4 = (i & 7) * 4;
            float4 kv = *(const float4*)(Kb + (size_t)r * DMODEL + c4);
            float4 vv = *(const float4*)(Vb + (size_t)r * DMODEL + c4);
            kv.x = to_tf32(kv.x); kv.y = to_tf32(kv.y); kv.z = to_tf32(kv.z); kv.w = to_tf32(kv.w);
            vv.x = to_tf32(vv.x); vv.y = to_tf32(vv.y); vv.z = to_tf32(vv.z); vv.w = to_tf32(vv.w);
            *(float4*)&Ks[r][c4] = kv;
            *(float4*)&Vs[r][c4] = vv;
        }
        __syncthreads();

        // ---- S = Q K^T : 8 key n-tiles x 4 d k-steps ----
        float sacc[8][4];
#pragma unroll
        for (int nt = 0; nt < 8; ++nt) {
            sacc[nt][0] = 0.f; sacc[nt][1] = 0.f; sacc[nt][2] = 0.f; sacc[nt][3] = 0.f;
#pragma unroll
            for (int ks = 0; ks < 4; ++ks) {
                uint32_t b0 = __float_as_uint(Ks[nt * 8 + g][ks * 8 + c]);
                uint32_t b1 = __float_as_uint(Ks[nt * 8 + g][ks * 8 + c + 4]);
                mma_tf32(sacc[nt], qf[ks][0], qf[ks][1], qf[ks][2], qf[ks][3], b0, b1);
            }
        }

        // ---- online softmax (rows r0 = warp*16+g, r1 = r0+8) ----
        float mx0 = -1e30f, mx1 = -1e30f;
#pragma unroll
        for (int nt = 0; nt < 8; ++nt) {
            mx0 = fmaxf(mx0, fmaxf(sacc[nt][0], sacc[nt][1]));
            mx1 = fmaxf(mx1, fmaxf(sacc[nt][2], sacc[nt][3]));
        }
        mx0 = fmaxf(mx0, __shfl_xor_sync(0xffffffffu, mx0, 1));
        mx0 = fmaxf(mx0, __shfl_xor_sync(0xffffffffu, mx0, 2));
        mx1 = fmaxf(mx1, __shfl_xor_sync(0xffffffffu, mx1, 1));
        mx1 = fmaxf(mx1, __shfl_xor_sync(0xffffffffu, mx1, 2));
        float nm0 = fmaxf(m0, mx0), nm1 = fmaxf(m1, mx1);
        float corr0 = __expf(m0 - nm0), corr1 = __expf(m1 - nm1);
        m0 = nm0; m1 = nm1;

        float s0 = 0.0f, s1 = 0.0f;
        int pr0 = warp * 16 + g, pr1 = pr0 + 8;
#pragma unroll
        for (int nt = 0; nt < 8; ++nt) {
            float p0 = __expf(sacc[nt][0] - m0);
            float p1 = __expf(sacc[nt][1] - m0);
            float p2 = __expf(sacc[nt][2] - m1);
            float p3 = __expf(sacc[nt][3] - m1);
            s0 += p0 + p1; s1 += p2 + p3;
            *(float2*)&Ps[pr0][nt * 8 + 2 * c] = make_float2(p0, p1);
            *(float2*)&Ps[pr1][nt * 8 + 2 * c] = make_float2(p2, p3);
        }
        s0 += __shfl_xor_sync(0xffffffffu, s0, 1);
        s0 += __shfl_xor_sync(0xffffffffu, s0, 2);
        s1 += __shfl_xor_sync(0xffffffffu, s1, 1);
        s1 += __shfl_xor_sync(0xffffffffu, s1, 2);
        l0 = l0 * corr0 + s0;
        l1 = l1 * corr1 + s1;
#pragma unroll
        for (int dt = 0; dt < 4; ++dt) {
            oacc[dt][0] *= corr0; oacc[dt][1] *= corr0;
            oacc[dt][2] *= corr1; oacc[dt][3] *= corr1;
        }
        __syncwarp();    // Ps rows are warp-private: warp-level sync suffices

        // ---- O += P V : 8 key k-steps x 4 d n-tiles ----
#pragma unroll
        for (int ks = 0; ks < 8; ++ks) {
            uint32_t a0 = __float_as_uint(Ps[pr0][ks * 8 + c]);
            uint32_t a1 = __float_as_uint(Ps[pr1][ks * 8 + c]);
            uint32_t a2 = __float_as_uint(Ps[pr0][ks * 8 + c + 4]);
            uint32_t a3 = __float_as_uint(Ps[pr1][ks * 8 + c + 4]);
#pragma unroll
            for (int dt = 0; dt < 4; ++dt) {
                uint32_t b0 = __float_as_uint(Vs[ks * 8 + c][dt * 8 + g]);
                uint32_t b1 = __float_as_uint(Vs[ks * 8 + c + 4][dt * 8 + g]);
                mma_tf32(oacc[dt], a0, a1, a2, a3, b0, b1);
            }
        }
    }

    // ---- epilogue: divide by l, store ----
    float inv0 = 1.0f / l0, inv1 = 1.0f / l1;
    float* Ob = O + ((size_t)(n * NP + qt * 64 + warp * 16)) * DMODEL + h * DH;
#pragma unroll
    for (int dt = 0; dt < 4; ++dt) {
        *(float2*)(Ob + (size_t)g       * DMODEL + dt * 8 + 2 * c) =
            make_float2(oacc[dt][0] * inv0, oacc[dt][1] * inv0);
        *(float2*)(Ob + (size_t)(g + 8) * DMODEL + dt * 8 + 2 * c) =
            make_float2(oacc[dt][2] * inv1, oacc[dt][3] * inv1);
    }
}

// ---------------- launch ------------------------------------------------------------
extern "C" void kernel_launch(void* const* d_in, const int* in_sizes, int n_in,
                              void* d_out, int out_size) {
    const float* local_feat  = (const float*)d_in[0];
    const float* global_feat = (const float*)d_in[1];
    const float* Wq = (const float*)d_in[2];
    const float* bq = (const float*)d_in[3];
    const float* Wk = (const float*)d_in[4];
    const float* bk = (const float*)d_in[5];
    const float* Wv = (const float*)d_in[6];
    const float* bv = (const float*)d_in[7];
    const float* Wo = (const float*)d_in[8];
    const float* bo = (const float*)d_in[9];
    float* out = (float*)d_out;

    float *lf_pe, *gf_pe, *q, *k, *v, *attn;
    cudaGetSymbolAddress((void**)&lf_pe, g_lf_pe);
    cudaGetSymbolAddress((void**)&gf_pe, g_gf_pe);
    cudaGetSymbolAddress((void**)&q,     g_q);
    cudaGetSymbolAddress((void**)&k,     g_k);
    cudaGetSymbolAddress((void**)&v,     g_v);
    cudaGetSymbolAddress((void**)&attn,  g_attn);

    // 1. positional encodings
    pe_local_kernel<<<(NB * NP * DMODEL) / 256, 256>>>(local_feat, lf_pe);
    transpose_pe_kernel<<<dim3(HWG / 32, DMODEL / 32, NB), dim3(32, 8)>>>(global_feat, gf_pe);

    // 2. Q/K/V projections (tf32 tensor cores)
    gemm_tf32_kernel<<<dim3((NB * NP) / 128, DMODEL / 64), 256>>>(lf_pe, nullptr, Wq, bq, q);
    gemm_tf32_kernel<<<dim3((NB * HWG) / 128, DMODEL / 64), 256>>>(gf_pe, nullptr, Wk, bk, k);
    gemm_tf32_kernel<<<dim3((NB * HWG) / 128, DMODEL / 64), 256>>>(gf_pe, nullptr, Wv, bv, v);

    // 3. attention (tf32 tensor cores)
    flash_attn_mma_kernel<<<dim3(NP / 64, NHEADS, NB), 128>>>(q, k, v, attn);

    // 4. output projection with fused residual (lf_pe + attn), tf32 tensor cores
    gemm_tf32_kernel<<<dim3((NB * NP) / 128, DMODEL / 64), 256>>>(lf_pe, attn, Wo, bo, out);
}

// round 8
// speedup vs baseline: 3.4953x; 1.2456x over previous
#include <cuda_runtime.h>
#include <cstdint>
#include <cstddef>

// Problem constants
#define NB   4        // batch
#define NP   1024     // local tokens (32x32)
#define DMODEL 256
#define HWG  4096     // global tokens (64x64)
#define NHEADS 8
#define DH   32
// -ln(10000)/256
#define NEG_LOG1E4_OVER_D (-0.035977892078030406f)
#define ATTN_SCALE 0.17677669529663687f            // 1/sqrt(32)
#define LOG2E 1.4426950408889634f
#define QSCALE (0.25501643154277775f)              // ATTN_SCALE * LOG2E

// ---------------- scratch (static device allocations; no cudaMalloc) ----------------
__device__ float g_lf_pe[NB * NP * DMODEL];
__device__ float g_gf_pe[NB * HWG * DMODEL];
__device__ float g_q[NB * NP * DMODEL];
__device__ float g_k[NB * HWG * DMODEL];
__device__ float g_v[NB * HWG * DMODEL];
__device__ float g_attn[NB * NP * DMODEL];

// ---------------- helpers ------------------------------------------------------------
__device__ __forceinline__ float to_tf32(float x) {
    uint32_t u;
    asm("cvt.rna.tf32.f32 %0, %1;" : "=r"(u) : "f"(x));
    return __uint_as_float(u);
}
__device__ __forceinline__ float ex2(float x) {
    float y;
    asm("ex2.approx.f32 %0, %1;" : "=f"(y) : "f"(x));
    return y;
}
__device__ __forceinline__ void mma_tf32(float* d,
                                         uint32_t a0, uint32_t a1, uint32_t a2, uint32_t a3,
                                         uint32_t b0, uint32_t b1) {
    asm volatile(
        "mma.sync.aligned.m16n8k8.row.col.f32.tf32.tf32.f32 "
        "{%0,%1,%2,%3}, {%4,%5,%6,%7}, {%8,%9}, {%0,%1,%2,%3};\n"
        : "+f"(d[0]), "+f"(d[1]), "+f"(d[2]), "+f"(d[3])
        : "r"(a0), "r"(a1), "r"(a2), "r"(a3), "r"(b0), "r"(b1));
}
__device__ __forceinline__ void cp16(const void* smem_dst, const void* gmem_src) {
    uint32_t d = (uint32_t)__cvta_generic_to_shared(smem_dst);
    asm volatile("cp.async.ca.shared.global [%0], [%1], 16;" :: "r"(d), "l"(gmem_src));
}
__device__ __forceinline__ void cp_commit() { asm volatile("cp.async.commit_group;"); }
__device__ __forceinline__ void cp_wait1()  { asm volatile("cp.async.wait_group 1;"); }
__device__ __forceinline__ void cp_wait0()  { asm volatile("cp.async.wait_group 0;"); }

// ---------------- kernel 1: local_feat + positional encoding ------------------------
__global__ __launch_bounds__(256) void pe_local_kernel(const float* __restrict__ in,
                                                       float* __restrict__ out) {
    int idx = blockIdx.x * 256 + threadIdx.x;
    int d = idx & (DMODEL - 1);
    int p = (idx >> 8) & (NP - 1);
    float x = (float)(p & 31) * (1.0f / 31.0f);
    float y = (float)(p >> 5) * (1.0f / 31.0f);
    float div = __expf((float)(d & ~1) * NEG_LOG1E4_OVER_D);
    float pe = (d & 1) ? __cosf(y * div) : __sinf(x * div);
    out[idx] = in[idx] + pe;
}

// ---------------- kernel 2: transpose global_feat + pos enc -------------------------
__global__ __launch_bounds__(256) void transpose_pe_kernel(const float* __restrict__ gf,
                                                           float* __restrict__ out) {
    __shared__ float tile[32][33];
    int n  = blockIdx.z;
    int s0 = blockIdx.x * 32;
    int d0 = blockIdx.y * 32;
    int tx = threadIdx.x, ty = threadIdx.y;
    const float* g = gf + ((size_t)n * DMODEL + d0) * HWG + s0;
#pragma unroll
    for (int k = 0; k < 4; ++k)
        tile[ty + 8 * k][tx] = g[(size_t)(ty + 8 * k) * HWG + tx];
    __syncthreads();
#pragma unroll
    for (int k = 0; k < 4; ++k) {
        int s = s0 + ty + 8 * k;
        int d = d0 + tx;
        float x = (float)(s & 63) * (1.0f / 63.0f);
        float y = (float)(s >> 6) * (1.0f / 63.0f);
        float div = __expf((float)(d & ~1) * NEG_LOG1E4_OVER_D);
        float pe = (d & 1) ? __cosf(y * div) : __sinf(x * div);
        out[((size_t)n * HWG + s) * DMODEL + d] = tile[tx][ty + 8 * k] + pe;
    }
}

// ---------------- kernel 3a: cp.async 2-stage tf32 GEMM  C = A @ W^T + b ------------
// 128x64 block tile, BK=32, 8 warps (4x2), warp tile 32x32.
// oscale applied after bias; oround -> tf32-round the stored value.
__global__ __launch_bounds__(256, 2) void gemm_tf32_ca_kernel(const float* __restrict__ A,
                                                              const float* __restrict__ W,
                                                              const float* __restrict__ bias,
                                                              float* __restrict__ C,
                                                              float oscale, int oround) {
    extern __shared__ float sm[];
    float (*As)[128][36] = (float(*)[128][36])sm;                 // 2 stages
    float (*Ws)[64][36]  = (float(*)[64][36])(sm + 2 * 128 * 36);

    int m0 = blockIdx.x * 128, o0 = blockIdx.y * 64;
    int tid = threadIdx.x;
    int warp = tid >> 5, lane = tid & 31;
    int g = lane >> 2, c = lane & 3;
    int wm = (warp & 3) * 32;
    int wn = (warp >> 2) * 32;

    int sr = tid >> 3;              // 0..31 staging row
    int sc4 = (tid & 7) * 4;        // staging k offset

    const float* Ap = A + (size_t)(m0 + sr) * DMODEL + sc4;
    const float* Wp = W + (size_t)(o0 + sr) * DMODEL + sc4;

    // stage chunk 0
#pragma unroll
    for (int j = 0; j < 4; ++j)
        cp16(&As[0][sr + 32 * j][sc4], Ap + (size_t)(32 * j) * DMODEL);
#pragma unroll
    for (int j = 0; j < 2; ++j)
        cp16(&Ws[0][sr + 32 * j][sc4], Wp + (size_t)(32 * j) * DMODEL);
    cp_commit();

    float acc[2][4][4] = {};

    for (int kc = 0; kc < 8; ++kc) {
        int buf = kc & 1;
        __syncthreads();                       // everyone done reading buf^1
        if (kc < 7) {
            int ko = (kc + 1) * 32;
#pragma unroll
            for (int j = 0; j < 4; ++j)
                cp16(&As[buf ^ 1][sr + 32 * j][sc4], Ap + ko + (size_t)(32 * j) * DMODEL);
#pragma unroll
            for (int j = 0; j < 2; ++j)
                cp16(&Ws[buf ^ 1][sr + 32 * j][sc4], Wp + ko + (size_t)(32 * j) * DMODEL);
            cp_commit();
            cp_wait1();
        } else {
            cp_wait0();
        }
        __syncthreads();

#pragma unroll
        for (int ks = 0; ks < 4; ++ks) {
            int k = ks * 8;
            uint32_t af[2][4];
#pragma unroll
            for (int mt = 0; mt < 2; ++mt) {
                int r = wm + mt * 16;
                af[mt][0] = __float_as_uint(to_tf32(As[buf][r + g    ][k + c    ]));
                af[mt][1] = __float_as_uint(to_tf32(As[buf][r + g + 8][k + c    ]));
                af[mt][2] = __float_as_uint(to_tf32(As[buf][r + g    ][k + c + 4]));
                af[mt][3] = __float_as_uint(to_tf32(As[buf][r + g + 8][k + c + 4]));
            }
#pragma unroll
            for (int nt = 0; nt < 4; ++nt) {
                uint32_t b0 = __float_as_uint(to_tf32(Ws[buf][wn + nt * 8 + g][k + c    ]));
                uint32_t b1 = __float_as_uint(to_tf32(Ws[buf][wn + nt * 8 + g][k + c + 4]));
                mma_tf32(acc[0][nt], af[0][0], af[0][1], af[0][2], af[0][3], b0, b1);
                mma_tf32(acc[1][nt], af[1][0], af[1][1], af[1][2], af[1][3], b0, b1);
            }
        }
    }

    // epilogue: bias, scale, optional tf32 round, store
#pragma unroll
    for (int nt = 0; nt < 4; ++nt) {
        float2 bv = *(const float2*)(bias + o0 + wn + nt * 8 + 2 * c);
#pragma unroll
        for (int mt = 0; mt < 2; ++mt) {
            float v0 = (acc[mt][nt][0] + bv.x) * oscale;
            float v1 = (acc[mt][nt][1] + bv.y) * oscale;
            float v2 = (acc[mt][nt][2] + bv.x) * oscale;
            float v3 = (acc[mt][nt][3] + bv.y) * oscale;
            if (oround) { v0 = to_tf32(v0); v1 = to_tf32(v1); v2 = to_tf32(v2); v3 = to_tf32(v3); }
            int row = m0 + wm + mt * 16 + g;
            float* Cp = C + (size_t)row * DMODEL + o0 + wn + nt * 8 + 2 * c;
            *(float2*)Cp = make_float2(v0, v1);
            *(float2*)(Cp + (size_t)8 * DMODEL) = make_float2(v2, v3);
        }
    }
}

// ---------------- kernel 3b: register-prefetch tf32 GEMM with fused A2 add (O-proj) --
__global__ __launch_bounds__(256) void gemm_tf32_kernel(const float* __restrict__ A,
                                                        const float* __restrict__ A2,
                                                        const float* __restrict__ W,
                                                        const float* __restrict__ bias,
                                                        float* __restrict__ C) {
    __shared__ float As[128][36];
    __shared__ float Ws[64][36];

    int m0 = blockIdx.x * 128, o0 = blockIdx.y * 64;
    int tid = threadIdx.x;
    int warp = tid >> 5, lane = tid & 31;
    int g = lane >> 2, c = lane & 3;
    int wm = (warp & 3) * 32;
    int wn = (warp >> 2) * 32;

    int lr  = tid >> 3;
    int lk4 = (tid & 7) * 4;

    const float* Ap  = A + (size_t)(m0 + lr) * DMODEL + lk4;
    const float* A2p = A2 + (size_t)(m0 + lr) * DMODEL + lk4;
    const float* Wp  = W + (size_t)(o0 + lr) * DMODEL + lk4;

    float4 ra[4], rw[2];
#pragma unroll
    for (int i = 0; i < 4; ++i) {
        float4 v = *(const float4*)(Ap + (size_t)(32 * i) * DMODEL);
        float4 u = *(const float4*)(A2p + (size_t)(32 * i) * DMODEL);
        v.x += u.x; v.y += u.y; v.z += u.z; v.w += u.w;
        ra[i] = v;
    }
#pragma unroll
    for (int i = 0; i < 2; ++i)
        rw[i] = *(const float4*)(Wp + (size_t)(32 * i) * DMODEL);

    float acc[2][4][4] = {};

    for (int kc = 0; kc < 8; ++kc) {
#pragma unroll
        for (int i = 0; i < 4; ++i) {
            float4 v = ra[i];
            v.x = to_tf32(v.x); v.y = to_tf32(v.y); v.z = to_tf32(v.z); v.w = to_tf32(v.w);
            *(float4*)&As[lr + 32 * i][lk4] = v;
        }
#pragma unroll
        for (int i = 0; i < 2; ++i) {
            float4 v = rw[i];
            v.x = to_tf32(v.x); v.y = to_tf32(v.y); v.z = to_tf32(v.z); v.w = to_tf32(v.w);
            *(float4*)&Ws[lr + 32 * i][lk4] = v;
        }
        __syncthreads();

        if (kc < 7) {
            int ko = (kc + 1) * 32;
#pragma unroll
            for (int i = 0; i < 4; ++i) {
                float4 v = *(const float4*)(Ap + ko + (size_t)(32 * i) * DMODEL);
                float4 u = *(const float4*)(A2p + ko + (size_t)(32 * i) * DMODEL);
                v.x += u.x; v.y += u.y; v.z += u.z; v.w += u.w;
                ra[i] = v;
            }
#pragma unroll
            for (int i = 0; i < 2; ++i)
                rw[i] = *(const float4*)(Wp + ko + (size_t)(32 * i) * DMODEL);
        }

#pragma unroll
        for (int ks = 0; ks < 4; ++ks) {
            int k = ks * 8;
            uint32_t af[2][4];
#pragma unroll
            for (int mt = 0; mt < 2; ++mt) {
                int r = wm + mt * 16;
                af[mt][0] = __float_as_uint(As[r + g    ][k + c    ]);
                af[mt][1] = __float_as_uint(As[r + g + 8][k + c    ]);
                af[mt][2] = __float_as_uint(As[r + g    ][k + c + 4]);
                af[mt][3] = __float_as_uint(As[r + g + 8][k + c + 4]);
            }
#pragma unroll
            for (int nt = 0; nt < 4; ++nt) {
                uint32_t b0 = __float_as_uint(Ws[wn + nt * 8 + g][k + c    ]);
                uint32_t b1 = __float_as_uint(Ws[wn + nt * 8 + g][k + c + 4]);
                mma_tf32(acc[0][nt], af[0][0], af[0][1], af[0][2], af[0][3], b0, b1);
                mma_tf32(acc[1][nt], af[1][0], af[1][1], af[1][2], af[1][3], b0, b1);
            }
        }
        __syncthreads();
    }

#pragma unroll
    for (int nt = 0; nt < 4; ++nt) {
        float2 bv = *(const float2*)(bias + o0 + wn + nt * 8 + 2 * c);
#pragma unroll
        for (int mt = 0; mt < 2; ++mt) {
            int row = m0 + wm + mt * 16 + g;
            float* Cp = C + (size_t)row * DMODEL + o0 + wn + nt * 8 + 2 * c;
            *(float2*)Cp = make_float2(acc[mt][nt][0] + bv.x, acc[mt][nt][1] + bv.y);
            *(float2*)(Cp + (size_t)8 * DMODEL) =
                make_float2(acc[mt][nt][2] + bv.x, acc[mt][nt][3] + bv.y);
        }
    }
}

// ---------------- kernel 4: flash attention v2 ---------------------------------------
// BQ=128 (8 warps), cp.async double-buffered K/V, shfl-based P fragment conversion,
// Q pre-scaled by 1/sqrt(DH)*log2(e) and pre-rounded; K/V pre-rounded by their GEMMs.
__global__ __launch_bounds__(256, 2) void flash_attn_mma2_kernel(const float* __restrict__ Q,
                                                                 const float* __restrict__ K,
                                                                 const float* __restrict__ V,
                                                                 float* __restrict__ O) {
    __shared__ float Ks[2][64][36];   // banks (4g+c) -> QK B-frag conflict-free
    __shared__ float Vs[2][64][40];   // banks (8c+g) -> PV B-frag conflict-free

    int qt = blockIdx.x, h = blockIdx.y, n = blockIdx.z;
    int tid  = threadIdx.x;
    int warp = tid >> 5, lane = tid & 31;
    int g = lane >> 2, c = lane & 3;

    // ---- preload Q fragments (already scaled + tf32-rounded by producer GEMM) ----
    const float* Qb = Q + ((size_t)(n * NP + qt * 128 + warp * 16)) * DMODEL + h * DH;
    uint32_t qf[4][4];
#pragma unroll
    for (int ks = 0; ks < 4; ++ks) {
        qf[ks][0] = __float_as_uint(Qb[(size_t)g       * DMODEL + ks * 8 + c    ]);
        qf[ks][1] = __float_as_uint(Qb[(size_t)(g + 8) * DMODEL + ks * 8 + c    ]);
        qf[ks][2] = __float_as_uint(Qb[(size_t)g       * DMODEL + ks * 8 + c + 4]);
        qf[ks][3] = __float_as_uint(Qb[(size_t)(g + 8) * DMODEL + ks * 8 + c + 4]);
    }

    const float* Kb0 = K + (size_t)n * HWG * DMODEL + h * DH;
    const float* Vb0 = V + (size_t)n * HWG * DMODEL + h * DH;

    int sr = tid >> 3;               // 0..31
    int sc4 = (tid & 7) * 4;

    // stage tile 0 into buffer 0
    {
        const float* Kb = Kb0;
        const float* Vb = Vb0;
        cp16(&Ks[0][sr][sc4],      Kb + (size_t)sr * DMODEL + sc4);
        cp16(&Ks[0][sr + 32][sc4], Kb + (size_t)(sr + 32) * DMODEL + sc4);
        cp16(&Vs[0][sr][sc4],      Vb + (size_t)sr * DMODEL + sc4);
        cp16(&Vs[0][sr + 32][sc4], Vb + (size_t)(sr + 32) * DMODEL + sc4);
        cp_commit();
    }

    float m0 = -1e30f, m1 = -1e30f, l0 = 0.0f, l1 = 0.0f;
    float oacc[4][4] = {};

    for (int kt = 0; kt < HWG / 64; ++kt) {
        int buf = kt & 1;
        __syncthreads();                      // all warps done reading buf^1
        if (kt < HWG / 64 - 1) {
            const float* Kb = Kb0 + (size_t)(kt + 1) * 64 * DMODEL;
            const float* Vb = Vb0 + (size_t)(kt + 1) * 64 * DMODEL;
            cp16(&Ks[buf ^ 1][sr][sc4],      Kb + (size_t)sr * DMODEL + sc4);
            cp16(&Ks[buf ^ 1][sr + 32][sc4], Kb + (size_t)(sr + 32) * DMODEL + sc4);
            cp16(&Vs[buf ^ 1][sr][sc4],      Vb + (size_t)sr * DMODEL + sc4);
            cp16(&Vs[buf ^ 1][sr + 32][sc4], Vb + (size_t)(sr + 32) * DMODEL + sc4);
            cp_commit();
            cp_wait1();
        } else {
            cp_wait0();
        }
        __syncthreads();

        // ---- S = Q K^T (log2-scaled scores) ----
        float sacc[8][4];
#pragma unroll
        for (int nt = 0; nt < 8; ++nt) {
            sacc[nt][0] = 0.f; sacc[nt][1] = 0.f; sacc[nt][2] = 0.f; sacc[nt][3] = 0.f;
#pragma unroll
            for (int ks = 0; ks < 4; ++ks) {
                uint32_t b0 = __float_as_uint(Ks[buf][nt * 8 + g][ks * 8 + c]);
                uint32_t b1 = __float_as_uint(Ks[buf][nt * 8 + g][ks * 8 + c + 4]);
                mma_tf32(sacc[nt], qf[ks][0], qf[ks][1], qf[ks][2], qf[ks][3], b0, b1);
            }
        }

        // ---- online softmax in log2 domain ----
        float mx0 = -1e30f, mx1 = -1e30f;
#pragma unroll
        for (int nt = 0; nt < 8; ++nt) {
            mx0 = fmaxf(mx0, fmaxf(sacc[nt][0], sacc[nt][1]));
            mx1 = fmaxf(mx1, fmaxf(sacc[nt][2], sacc[nt][3]));
        }
        mx0 = fmaxf(mx0, __shfl_xor_sync(0xffffffffu, mx0, 1));
        mx0 = fmaxf(mx0, __shfl_xor_sync(0xffffffffu, mx0, 2));
        mx1 = fmaxf(mx1, __shfl_xor_sync(0xffffffffu, mx1, 1));
        mx1 = fmaxf(mx1, __shfl_xor_sync(0xffffffffu, mx1, 2));
        float nm0 = fmaxf(m0, mx0), nm1 = fmaxf(m1, mx1);
        float corr0 = ex2(m0 - nm0), corr1 = ex2(m1 - nm1);
        m0 = nm0; m1 = nm1;

        float s0 = 0.0f, s1 = 0.0f;
#pragma unroll
        for (int nt = 0; nt < 8; ++nt) {
            float p0 = ex2(sacc[nt][0] - m0);
            float p1 = ex2(sacc[nt][1] - m0);
            float p2 = ex2(sacc[nt][2] - m1);
            float p3 = ex2(sacc[nt][3] - m1);
            s0 += p0 + p1; s1 += p2 + p3;
            sacc[nt][0] = p0; sacc[nt][1] = p1; sacc[nt][2] = p2; sacc[nt][3] = p3;
        }
        s0 += __shfl_xor_sync(0xffffffffu, s0, 1);
        s0 += __shfl_xor_sync(0xffffffffu, s0, 2);
        s1 += __shfl_xor_sync(0xffffffffu, s1, 1);
        s1 += __shfl_xor_sync(0xffffffffu, s1, 2);
        l0 = l0 * corr0 + s0;
        l1 = l1 * corr1 + s1;
#pragma unroll
        for (int dt = 0; dt < 4; ++dt) {
            oacc[dt][0] *= corr0; oacc[dt][1] *= corr0;
            oacc[dt][2] *= corr1; oacc[dt][3] *= corr1;
        }

        // ---- O += P V ; C-frag (cols 2c,2c+1) -> A-frag (cols c,c+4) via shfl ----
        int s0l = (lane & ~3) | (c >> 1);     // source lane for col c
        int s2l = s0l + 2;                    // source lane for col c+4
        bool odd = (c & 1);
#pragma unroll
        for (int ks = 0; ks < 8; ++ks) {
            float p0 = sacc[ks][0], p1 = sacc[ks][1];
            float p2 = sacc[ks][2], p3 = sacc[ks][3];
            float e00 = __shfl_sync(0xffffffffu, p0, s0l);
            float e01 = __shfl_sync(0xffffffffu, p1, s0l);
            float e20 = __shfl_sync(0xffffffffu, p0, s2l);
            float e21 = __shfl_sync(0xffffffffu, p1, s2l);
            float f00 = __shfl_sync(0xffffffffu, p2, s0l);
            float f01 = __shfl_sync(0xffffffffu, p3, s0l);
            float f20 = __shfl_sync(0xffffffffu, p2, s2l);
            float f21 = __shfl_sync(0xffffffffu, p3, s2l);
            uint32_t a0 = __float_as_uint(odd ? e01 : e00);   // P[g][8ks+c]
            uint32_t a1 = __float_as_uint(odd ? f01 : f00);   // P[g+8][8ks+c]
            uint32_t a2 = __float_as_uint(odd ? e21 : e20);   // P[g][8ks+c+4]
            uint32_t a3 = __float_as_uint(odd ? f21 : f20);   // P[g+8][8ks+c+4]
#pragma unroll
            for (int dt = 0; dt < 4; ++dt) {
                uint32_t b0 = __float_as_uint(Vs[buf][ks * 8 + c    ][dt * 8 + g]);
                uint32_t b1 = __float_as_uint(Vs[buf][ks * 8 + c + 4][dt * 8 + g]);
                mma_tf32(oacc[dt], a0, a1, a2, a3, b0, b1);
            }
        }
    }

    // ---- epilogue ----
    float inv0 = 1.0f / l0, inv1 = 1.0f / l1;
    float* Ob = O + ((size_t)(n * NP + qt * 128 + warp * 16)) * DMODEL + h * DH;
#pragma unroll
    for (int dt = 0; dt < 4; ++dt) {
        *(float2*)(Ob + (size_t)g       * DMODEL + dt * 8 + 2 * c) =
            make_float2(oacc[dt][0] * inv0, oacc[dt][1] * inv0);
        *(float2*)(Ob + (size_t)(g + 8) * DMODEL + dt * 8 + 2 * c) =
            make_float2(oacc[dt][2] * inv1, oacc[dt][3] * inv1);
    }
}

// ---------------- launch ------------------------------------------------------------
extern "C" void kernel_launch(void* const* d_in, const int* in_sizes, int n_in,
                              void* d_out, int out_size) {
    const float* local_feat  = (const float*)d_in[0];
    const float* global_feat = (const float*)d_in[1];
    const float* Wq = (const float*)d_in[2];
    const float* bq = (const float*)d_in[3];
    const float* Wk = (const float*)d_in[4];
    const float* bk = (const float*)d_in[5];
    const float* Wv = (const float*)d_in[6];
    const float* bv = (const float*)d_in[7];
    const float* Wo = (const float*)d_in[8];
    const float* bo = (const float*)d_in[9];
    float* out = (float*)d_out;

    float *lf_pe, *gf_pe, *q, *k, *v, *attn;
    cudaGetSymbolAddress((void**)&lf_pe, g_lf_pe);
    cudaGetSymbolAddress((void**)&gf_pe, g_gf_pe);
    cudaGetSymbolAddress((void**)&q,     g_q);
    cudaGetSymbolAddress((void**)&k,     g_k);
    cudaGetSymbolAddress((void**)&v,     g_v);
    cudaGetSymbolAddress((void**)&attn,  g_attn);

    // dynamic smem for the cp.async GEMM: 2 stages of (128+64)x36 floats = 55296 B
    const int GEMM_SMEM = (2 * 128 * 36 + 2 * 64 * 36) * (int)sizeof(float);
    static bool attr_set = false;
    if (!attr_set) {
        cudaFuncSetAttribute(gemm_tf32_ca_kernel,
                             cudaFuncAttributeMaxDynamicSharedMemorySize, GEMM_SMEM);
        attr_set = true;
    }

    // 1. positional encodings
    pe_local_kernel<<<(NB * NP * DMODEL) / 256, 256>>>(local_feat, lf_pe);
    transpose_pe_kernel<<<dim3(HWG / 32, DMODEL / 32, NB), dim3(32, 8)>>>(global_feat, gf_pe);

    // 2. projections: Q pre-scaled by 1/sqrt(DH)*log2e + rounded; K/V rounded
    gemm_tf32_ca_kernel<<<dim3((NB * NP) / 128, DMODEL / 64), 256, GEMM_SMEM>>>(
        lf_pe, Wq, bq, q, QSCALE, 1);
    gemm_tf32_ca_kernel<<<dim3((NB * HWG) / 128, DMODEL / 64), 256, GEMM_SMEM>>>(
        gf_pe, Wk, bk, k, 1.0f, 1);
    gemm_tf32_ca_kernel<<<dim3((NB * HWG) / 128, DMODEL / 64), 256, GEMM_SMEM>>>(
        gf_pe, Wv, bv, v, 1.0f, 1);

    // 3. attention
    flash_attn_mma2_kernel<<<dim3(NP / 128, NHEADS, NB), 256>>>(q, k, v, attn);

    // 4. output projection with fused residual
    gemm_tf32_kernel<<<dim3((NB * NP) / 128, DMODEL / 64), 256>>>(lf_pe, attn, Wo, bo, out);
}

// round 11
// speedup vs baseline: 3.6561x; 1.0460x over previous
#include <cuda_runtime.h>
#include <cstdint>
#include <cstddef>

// Problem constants
#define NB   4        // batch
#define NP   1024     // local tokens (32x32)
#define DMODEL 256
#define HWG  4096     // global tokens (64x64)
#define NHEADS 8
#define DH   32
// -ln(10000)/256
#define NEG_LOG1E4_OVER_D (-0.035977892078030406f)
#define ATTN_SCALE 0.17677669529663687f            // 1/sqrt(32)
#define LOG2E 1.4426950408889634f
#define QSCALE (0.25501643154277775f)              // ATTN_SCALE * LOG2E

// ---------------- scratch (static device allocations; no cudaMalloc) ----------------
__device__ float g_lf_pe[NB * NP * DMODEL];
__device__ float g_gf_pe[NB * HWG * DMODEL];
__device__ float g_q[NB * NP * DMODEL];
__device__ float g_k[NB * HWG * DMODEL];
__device__ float g_v[NB * HWG * DMODEL];
__device__ float g_attn[NB * NP * DMODEL];
__device__ float g_wq[DMODEL * DMODEL];
__device__ float g_wk[DMODEL * DMODEL];
__device__ float g_wv[DMODEL * DMODEL];

// ---------------- helpers ------------------------------------------------------------
__device__ __forceinline__ float to_tf32(float x) {
    uint32_t u;
    asm("cvt.rna.tf32.f32 %0, %1;" : "=r"(u) : "f"(x));
    return __uint_as_float(u);
}
__device__ __forceinline__ float ex2(float x) {
    float y;
    asm("ex2.approx.f32 %0, %1;" : "=f"(y) : "f"(x));
    return y;
}
__device__ __forceinline__ void mma_tf32(float* d,
                                         uint32_t a0, uint32_t a1, uint32_t a2, uint32_t a3,
                                         uint32_t b0, uint32_t b1) {
    asm volatile(
        "mma.sync.aligned.m16n8k8.row.col.f32.tf32.tf32.f32 "
        "{%0,%1,%2,%3}, {%4,%5,%6,%7}, {%8,%9}, {%0,%1,%2,%3};\n"
        : "+f"(d[0]), "+f"(d[1]), "+f"(d[2]), "+f"(d[3])
        : "r"(a0), "r"(a1), "r"(a2), "r"(a3), "r"(b0), "r"(b1));
}
__device__ __forceinline__ void cp16(const void* smem_dst, const void* gmem_src) {
    uint32_t d = (uint32_t)__cvta_generic_to_shared(smem_dst);
    asm volatile("cp.async.ca.shared.global [%0], [%1], 16;" :: "r"(d), "l"(gmem_src));
}
__device__ __forceinline__ void cp_commit() { asm volatile("cp.async.commit_group;"); }
__device__ __forceinline__ void cp_wait1()  { asm volatile("cp.async.wait_group 1;"); }
__device__ __forceinline__ void cp_wait0()  { asm volatile("cp.async.wait_group 0;"); }

// ---------------- kernel 0: tf32-round Wq/Wk/Wv ---------------------------------------
__global__ __launch_bounds__(256) void round_w_kernel(const float* __restrict__ Wq,
                                                      const float* __restrict__ Wk,
                                                      const float* __restrict__ Wv,
                                                      float* __restrict__ wq,
                                                      float* __restrict__ wk,
                                                      float* __restrict__ wv) {
    int i = (blockIdx.x * 256 + threadIdx.x) * 4;       // 65536 elements / 4
    float4 a = *(const float4*)(Wq + i);
    float4 b = *(const float4*)(Wk + i);
    float4 c = *(const float4*)(Wv + i);
    a.x = to_tf32(a.x); a.y = to_tf32(a.y); a.z = to_tf32(a.z); a.w = to_tf32(a.w);
    b.x = to_tf32(b.x); b.y = to_tf32(b.y); b.z = to_tf32(b.z); b.w = to_tf32(b.w);
    c.x = to_tf32(c.x); c.y = to_tf32(c.y); c.z = to_tf32(c.z); c.w = to_tf32(c.w);
    *(float4*)(wq + i) = a;
    *(float4*)(wk + i) = b;
    *(float4*)(wv + i) = c;
}

// ---------------- kernel 1: local_feat + positional encoding (tf32-rounded out) ------
__global__ __launch_bounds__(256) void pe_local_kernel(const float* __restrict__ in,
                                                       float* __restrict__ out) {
    int idx = blockIdx.x * 256 + threadIdx.x;
    int d = idx & (DMODEL - 1);
    int p = (idx >> 8) & (NP - 1);
    float x = (float)(p & 31) * (1.0f / 31.0f);
    float y = (float)(p >> 5) * (1.0f / 31.0f);
    float div = __expf((float)(d & ~1) * NEG_LOG1E4_OVER_D);
    float pe = (d & 1) ? __cosf(y * div) : __sinf(x * div);
    out[idx] = to_tf32(in[idx] + pe);
}

// ---------------- kernel 2: transpose global_feat + pos enc (tf32-rounded out) -------
__global__ __launch_bounds__(256) void transpose_pe_kernel(const float* __restrict__ gf,
                                                           float* __restrict__ out) {
    __shared__ float tile[32][33];
    int n  = blockIdx.z;
    int s0 = blockIdx.x * 32;
    int d0 = blockIdx.y * 32;
    int tx = threadIdx.x, ty = threadIdx.y;
    const float* g = gf + ((size_t)n * DMODEL + d0) * HWG + s0;
#pragma unroll
    for (int k = 0; k < 4; ++k)
        tile[ty + 8 * k][tx] = g[(size_t)(ty + 8 * k) * HWG + tx];
    __syncthreads();
#pragma unroll
    for (int k = 0; k < 4; ++k) {
        int s = s0 + ty + 8 * k;
        int d = d0 + tx;
        float x = (float)(s & 63) * (1.0f / 63.0f);
        float y = (float)(s >> 6) * (1.0f / 63.0f);
        float div = __expf((float)(d & ~1) * NEG_LOG1E4_OVER_D);
        float pe = (d & 1) ? __cosf(y * div) : __sinf(x * div);
        out[((size_t)n * HWG + s) * DMODEL + d] = to_tf32(tile[tx][ty + 8 * k] + pe);
    }
}

// ---------------- kernel 3a: cp.async 2-stage tf32 GEMM (pre-rounded inputs) ---------
// 128x64 block tile, BK=32, 8 warps (4x2), warp tile 32x32.  No cvt in hot loop.
__global__ __launch_bounds__(256, 2) void gemm_tf32_ca_kernel(const float* __restrict__ A,
                                                              const float* __restrict__ W,
                                                              const float* __restrict__ bias,
                                                              float* __restrict__ C,
                                                              float oscale, int oround) {
    extern __shared__ float sm[];
    float (*As)[128][36] = (float(*)[128][36])sm;
    float (*Ws)[64][36]  = (float(*)[64][36])(sm + 2 * 128 * 36);

    int m0 = blockIdx.x * 128, o0 = blockIdx.y * 64;
    int tid = threadIdx.x;
    int warp = tid >> 5, lane = tid & 31;
    int g = lane >> 2, c = lane & 3;
    int wm = (warp & 3) * 32;
    int wn = (warp >> 2) * 32;

    int sr = tid >> 3;
    int sc4 = (tid & 7) * 4;

    const float* Ap = A + (size_t)(m0 + sr) * DMODEL + sc4;
    const float* Wp = W + (size_t)(o0 + sr) * DMODEL + sc4;

#pragma unroll
    for (int j = 0; j < 4; ++j)
        cp16(&As[0][sr + 32 * j][sc4], Ap + (size_t)(32 * j) * DMODEL);
#pragma unroll
    for (int j = 0; j < 2; ++j)
        cp16(&Ws[0][sr + 32 * j][sc4], Wp + (size_t)(32 * j) * DMODEL);
    cp_commit();

    float acc[2][4][4] = {};

    for (int kc = 0; kc < 8; ++kc) {
        int buf = kc & 1;
        __syncthreads();
        if (kc < 7) {
            int ko = (kc + 1) * 32;
#pragma unroll
            for (int j = 0; j < 4; ++j)
                cp16(&As[buf ^ 1][sr + 32 * j][sc4], Ap + ko + (size_t)(32 * j) * DMODEL);
#pragma unroll
            for (int j = 0; j < 2; ++j)
                cp16(&Ws[buf ^ 1][sr + 32 * j][sc4], Wp + ko + (size_t)(32 * j) * DMODEL);
            cp_commit();
            cp_wait1();
        } else {
            cp_wait0();
        }
        __syncthreads();

#pragma unroll
        for (int ks = 0; ks < 4; ++ks) {
            int k = ks * 8;
            uint32_t af[2][4];
#pragma unroll
            for (int mt = 0; mt < 2; ++mt) {
                int r = wm + mt * 16;
                af[mt][0] = __float_as_uint(As[buf][r + g    ][k + c    ]);
                af[mt][1] = __float_as_uint(As[buf][r + g + 8][k + c    ]);
                af[mt][2] = __float_as_uint(As[buf][r + g    ][k + c + 4]);
                af[mt][3] = __float_as_uint(As[buf][r + g + 8][k + c + 4]);
            }
#pragma unroll
            for (int nt = 0; nt < 4; ++nt) {
                uint32_t b0 = __float_as_uint(Ws[buf][wn + nt * 8 + g][k + c    ]);
                uint32_t b1 = __float_as_uint(Ws[buf][wn + nt * 8 + g][k + c + 4]);
                mma_tf32(acc[0][nt], af[0][0], af[0][1], af[0][2], af[0][3], b0, b1);
                mma_tf32(acc[1][nt], af[1][0], af[1][1], af[1][2], af[1][3], b0, b1);
            }
        }
    }

#pragma unroll
    for (int nt = 0; nt < 4; ++nt) {
        float2 bv = *(const float2*)(bias + o0 + wn + nt * 8 + 2 * c);
#pragma unroll
        for (int mt = 0; mt < 2; ++mt) {
            float v0 = (acc[mt][nt][0] + bv.x) * oscale;
            float v1 = (acc[mt][nt][1] + bv.y) * oscale;
            float v2 = (acc[mt][nt][2] + bv.x) * oscale;
            float v3 = (acc[mt][nt][3] + bv.y) * oscale;
            if (oround) { v0 = to_tf32(v0); v1 = to_tf32(v1); v2 = to_tf32(v2); v3 = to_tf32(v3); }
            int row = m0 + wm + mt * 16 + g;
            float* Cp = C + (size_t)row * DMODEL + o0 + wn + nt * 8 + 2 * c;
            *(float2*)Cp = make_float2(v0, v1);
            *(float2*)(Cp + (size_t)8 * DMODEL) = make_float2(v2, v3);
        }
    }
}

// ---------------- kernel 3c: fused K+V projection (shared A staging) -----------------
// Per block: 128(M) x 64(N) of BOTH K = gf@Wk^T+bk and V = gf@Wv^T+bv.
__global__ __launch_bounds__(256, 2) void gemm_kv_kernel(const float* __restrict__ A,
                                                         const float* __restrict__ Wk,
                                                         const float* __restrict__ Wv,
                                                         const float* __restrict__ bk,
                                                         const float* __restrict__ bv,
                                                         float* __restrict__ K,
                                                         float* __restrict__ V) {
    extern __shared__ float sm[];
    float (*As)[128][36]  = (float(*)[128][36])sm;                    // 2 stages
    float (*Wks)[64][36]  = (float(*)[64][36])(sm + 2 * 128 * 36);
    float (*Wvs)[64][36]  = (float(*)[64][36])(sm + 2 * 128 * 36 + 2 * 64 * 36);

    int m0 = blockIdx.x * 128, o0 = blockIdx.y * 64;
    int tid = threadIdx.x;
    int warp = tid >> 5, lane = tid & 31;
    int g = lane >> 2, c = lane & 3;
    int wm = (warp & 3) * 32;
    int wn = (warp >> 2) * 32;

    int sr = tid >> 3;
    int sc4 = (tid & 7) * 4;

    const float* Ap  = A + (size_t)(m0 + sr) * DMODEL + sc4;
    const float* Wkp = Wk + (size_t)(o0 + sr) * DMODEL + sc4;
    const float* Wvp = Wv + (size_t)(o0 + sr) * DMODEL + sc4;

#pragma unroll
    for (int j = 0; j < 4; ++j)
        cp16(&As[0][sr + 32 * j][sc4], Ap + (size_t)(32 * j) * DMODEL);
#pragma unroll
    for (int j = 0; j < 2; ++j) {
        cp16(&Wks[0][sr + 32 * j][sc4], Wkp + (size_t)(32 * j) * DMODEL);
        cp16(&Wvs[0][sr + 32 * j][sc4], Wvp + (size_t)(32 * j) * DMODEL);
    }
    cp_commit();

    float ack[2][4][4] = {};
    float acv[2][4][4] = {};

    for (int kc = 0; kc < 8; ++kc) {
        int buf = kc & 1;
        __syncthreads();
        if (kc < 7) {
            int ko = (kc + 1) * 32;
#pragma unroll
            for (int j = 0; j < 4; ++j)
                cp16(&As[buf ^ 1][sr + 32 * j][sc4], Ap + ko + (size_t)(32 * j) * DMODEL);
#pragma unroll
            for (int j = 0; j < 2; ++j) {
                cp16(&Wks[buf ^ 1][sr + 32 * j][sc4], Wkp + ko + (size_t)(32 * j) * DMODEL);
                cp16(&Wvs[buf ^ 1][sr + 32 * j][sc4], Wvp + ko + (size_t)(32 * j) * DMODEL);
            }
            cp_commit();
            cp_wait1();
        } else {
            cp_wait0();
        }
        __syncthreads();

#pragma unroll
        for (int ks = 0; ks < 4; ++ks) {
            int k = ks * 8;
            uint32_t af[2][4];
#pragma unroll
            for (int mt = 0; mt < 2; ++mt) {
                int r = wm + mt * 16;
                af[mt][0] = __float_as_uint(As[buf][r + g    ][k + c    ]);
                af[mt][1] = __float_as_uint(As[buf][r + g + 8][k + c    ]);
                af[mt][2] = __float_as_uint(As[buf][r + g    ][k + c + 4]);
                af[mt][3] = __float_as_uint(As[buf][r + g + 8][k + c + 4]);
            }
#pragma unroll
            for (int nt = 0; nt < 4; ++nt) {
                uint32_t k0 = __float_as_uint(Wks[buf][wn + nt * 8 + g][k + c    ]);
                uint32_t k1 = __float_as_uint(Wks[buf][wn + nt * 8 + g][k + c + 4]);
                uint32_t v0 = __float_as_uint(Wvs[buf][wn + nt * 8 + g][k + c    ]);
                uint32_t v1 = __float_as_uint(Wvs[buf][wn + nt * 8 + g][k + c + 4]);
                mma_tf32(ack[0][nt], af[0][0], af[0][1], af[0][2], af[0][3], k0, k1);
                mma_tf32(ack[1][nt], af[1][0], af[1][1], af[1][2], af[1][3], k0, k1);
                mma_tf32(acv[0][nt], af[0][0], af[0][1], af[0][2], af[0][3], v0, v1);
                mma_tf32(acv[1][nt], af[1][0], af[1][1], af[1][2], af[1][3], v0, v1);
            }
        }
    }

#pragma unroll
    for (int nt = 0; nt < 4; ++nt) {
        float2 bkv = *(const float2*)(bk + o0 + wn + nt * 8 + 2 * c);
        float2 bvv = *(const float2*)(bv + o0 + wn + nt * 8 + 2 * c);
#pragma unroll
        for (int mt = 0; mt < 2; ++mt) {
            int row = m0 + wm + mt * 16 + g;
            size_t off = (size_t)row * DMODEL + o0 + wn + nt * 8 + 2 * c;
            *(float2*)(K + off) = make_float2(to_tf32(ack[mt][nt][0] + bkv.x),
                                              to_tf32(ack[mt][nt][1] + bkv.y));
            *(float2*)(K + off + (size_t)8 * DMODEL) =
                make_float2(to_tf32(ack[mt][nt][2] + bkv.x), to_tf32(ack[mt][nt][3] + bkv.y));
            *(float2*)(V + off) = make_float2(to_tf32(acv[mt][nt][0] + bvv.x),
                                              to_tf32(acv[mt][nt][1] + bvv.y));
            *(float2*)(V + off + (size_t)8 * DMODEL) =
                make_float2(to_tf32(acv[mt][nt][2] + bvv.x), to_tf32(acv[mt][nt][3] + bvv.y));
        }
    }
}

// ---------------- kernel 3b: register-prefetch tf32 GEMM with fused A2 add (O-proj) --
__global__ __launch_bounds__(256) void gemm_tf32_kernel(const float* __restrict__ A,
                                                        const float* __restrict__ A2,
                                                        const float* __restrict__ W,
                                                        const float* __restrict__ bias,
                                                        float* __restrict__ C) {
    __shared__ float As[128][36];
    __shared__ float Ws[64][36];

    int m0 = blockIdx.x * 128, o0 = blockIdx.y * 64;
    int tid = threadIdx.x;
    int warp = tid >> 5, lane = tid & 31;
    int g = lane >> 2, c = lane & 3;
    int wm = (warp & 3) * 32;
    int wn = (warp >> 2) * 32;

    int lr  = tid >> 3;
    int lk4 = (tid & 7) * 4;

    const float* Ap  = A + (size_t)(m0 + lr) * DMODEL + lk4;
    const float* A2p = A2 + (size_t)(m0 + lr) * DMODEL + lk4;
    const float* Wp  = W + (size_t)(o0 + lr) * DMODEL + lk4;

    float4 ra[4], rw[2];
#pragma unroll
    for (int i = 0; i < 4; ++i) {
        float4 v = *(const float4*)(Ap + (size_t)(32 * i) * DMODEL);
        float4 u = *(const float4*)(A2p + (size_t)(32 * i) * DMODEL);
        v.x += u.x; v.y += u.y; v.z += u.z; v.w += u.w;
        ra[i] = v;
    }
#pragma unroll
    for (int i = 0; i < 2; ++i)
        rw[i] = *(const float4*)(Wp + (size_t)(32 * i) * DMODEL);

    float acc[2][4][4] = {};

    for (int kc = 0; kc < 8; ++kc) {
#pragma unroll
        for (int i = 0; i < 4; ++i) {
            float4 v = ra[i];
            v.x = to_tf32(v.x); v.y = to_tf32(v.y); v.z = to_tf32(v.z); v.w = to_tf32(v.w);
            *(float4*)&As[lr + 32 * i][lk4] = v;
        }
#pragma unroll
        for (int i = 0; i < 2; ++i) {
            float4 v = rw[i];
            v.x = to_tf32(v.x); v.y = to_tf32(v.y); v.z = to_tf32(v.z); v.w = to_tf32(v.w);
            *(float4*)&Ws[lr + 32 * i][lk4] = v;
        }
        __syncthreads();

        if (kc < 7) {
            int ko = (kc + 1) * 32;
#pragma unroll
            for (int i = 0; i < 4; ++i) {
                float4 v = *(const float4*)(Ap + ko + (size_t)(32 * i) * DMODEL);
                float4 u = *(const float4*)(A2p + ko + (size_t)(32 * i) * DMODEL);
                v.x += u.x; v.y += u.y; v.z += u.z; v.w += u.w;
                ra[i] = v;
            }
#pragma unroll
            for (int i = 0; i < 2; ++i)
                rw[i] = *(const float4*)(Wp + ko + (size_t)(32 * i) * DMODEL);
        }

#pragma unroll
        for (int ks = 0; ks < 4; ++ks) {
            int k = ks * 8;
            uint32_t af[2][4];
#pragma unroll
            for (int mt = 0; mt < 2; ++mt) {
                int r = wm + mt * 16;
                af[mt][0] = __float_as_uint(As[r + g    ][k + c    ]);
                af[mt][1] = __float_as_uint(As[r + g + 8][k + c    ]);
                af[mt][2] = __float_as_uint(As[r + g    ][k + c + 4]);
                af[mt][3] = __float_as_uint(As[r + g + 8][k + c + 4]);
            }
#pragma unroll
            for (int nt = 0; nt < 4; ++nt) {
                uint32_t b0 = __float_as_uint(Ws[wn + nt * 8 + g][k + c    ]);
                uint32_t b1 = __float_as_uint(Ws[wn + nt * 8 + g][k + c + 4]);
                mma_tf32(acc[0][nt], af[0][0], af[0][1], af[0][2], af[0][3], b0, b1);
                mma_tf32(acc[1][nt], af[1][0], af[1][1], af[1][2], af[1][3], b0, b1);
            }
        }
        __syncthreads();
    }

#pragma unroll
    for (int nt = 0; nt < 4; ++nt) {
        float2 bv = *(const float2*)(bias + o0 + wn + nt * 8 + 2 * c);
#pragma unroll
        for (int mt = 0; mt < 2; ++mt) {
            int row = m0 + wm + mt * 16 + g;
            float* Cp = C + (size_t)row * DMODEL + o0 + wn + nt * 8 + 2 * c;
            *(float2*)Cp = make_float2(acc[mt][nt][0] + bv.x, acc[mt][nt][1] + bv.y);
            *(float2*)(Cp + (size_t)8 * DMODEL) =
                make_float2(acc[mt][nt][2] + bv.x, acc[mt][nt][3] + bv.y);
        }
    }
}

// ---------------- kernel 4: flash attention (deferred l reduction) -------------------
__global__ __launch_bounds__(256, 2) void flash_attn_mma2_kernel(const float* __restrict__ Q,
                                                                 const float* __restrict__ K,
                                                                 const float* __restrict__ V,
                                                                 float* __restrict__ O) {
    __shared__ float Ks[2][64][36];   // banks (4g+c) -> QK B-frag conflict-free
    __shared__ float Vs[2][64][40];   // banks (8c+g) -> PV B-frag conflict-free

    int qt = blockIdx.x, h = blockIdx.y, n = blockIdx.z;
    int tid  = threadIdx.x;
    int warp = tid >> 5, lane = tid & 31;
    int g = lane >> 2, c = lane & 3;

    const float* Qb = Q + ((size_t)(n * NP + qt * 128 + warp * 16)) * DMODEL + h * DH;
    uint32_t qf[4][4];
#pragma unroll
    for (int ks = 0; ks < 4; ++ks) {
        qf[ks][0] = __float_as_uint(Qb[(size_t)g       * DMODEL + ks * 8 + c    ]);
        qf[ks][1] = __float_as_uint(Qb[(size_t)(g + 8) * DMODEL + ks * 8 + c    ]);
        qf[ks][2] = __float_as_uint(Qb[(size_t)g       * DMODEL + ks * 8 + c + 4]);
        qf[ks][3] = __float_as_uint(Qb[(size_t)(g + 8) * DMODEL + ks * 8 + c + 4]);
    }

    const float* Kb0 = K + (size_t)n * HWG * DMODEL + h * DH;
    const float* Vb0 = V + (size_t)n * HWG * DMODEL + h * DH;

    int sr = tid >> 3;
    int sc4 = (tid & 7) * 4;

    {
        cp16(&Ks[0][sr][sc4],      Kb0 + (size_t)sr * DMODEL + sc4);
        cp16(&Ks[0][sr + 32][sc4], Kb0 + (size_t)(sr + 32) * DMODEL + sc4);
        cp16(&Vs[0][sr][sc4],      Vb0 + (size_t)sr * DMODEL + sc4);
        cp16(&Vs[0][sr + 32][sc4], Vb0 + (size_t)(sr + 32) * DMODEL + sc4);
        cp_commit();
    }

    float m0 = -1e30f, m1 = -1e30f;
    float l0 = 0.0f, l1 = 0.0f;      // per-thread partial sums; reduced at the end
    float oacc[4][4] = {};

    for (int kt = 0; kt < HWG / 64; ++kt) {
        int buf = kt & 1;
        __syncthreads();
        if (kt < HWG / 64 - 1) {
            const float* Kb = Kb0 + (size_t)(kt + 1) * 64 * DMODEL;
            const float* Vb = Vb0 + (size_t)(kt + 1) * 64 * DMODEL;
            cp16(&Ks[buf ^ 1][sr][sc4],      Kb + (size_t)sr * DMODEL + sc4);
            cp16(&Ks[buf ^ 1][sr + 32][sc4], Kb + (size_t)(sr + 32) * DMODEL + sc4);
            cp16(&Vs[buf ^ 1][sr][sc4],      Vb + (size_t)sr * DMODEL + sc4);
            cp16(&Vs[buf ^ 1][sr + 32][sc4], Vb + (size_t)(sr + 32) * DMODEL + sc4);
            cp_commit();
            cp_wait1();
        } else {
            cp_wait0();
        }
        __syncthreads();

        // ---- S = Q K^T (log2-scaled scores) ----
        float sacc[8][4];
#pragma unroll
        for (int nt = 0; nt < 8; ++nt) {
            sacc[nt][0] = 0.f; sacc[nt][1] = 0.f; sacc[nt][2] = 0.f; sacc[nt][3] = 0.f;
#pragma unroll
            for (int ks = 0; ks < 4; ++ks) {
                uint32_t b0 = __float_as_uint(Ks[buf][nt * 8 + g][ks * 8 + c]);
                uint32_t b1 = __float_as_uint(Ks[buf][nt * 8 + g][ks * 8 + c + 4]);
                mma_tf32(sacc[nt], qf[ks][0], qf[ks][1], qf[ks][2], qf[ks][3], b0, b1);
            }
        }

        // ---- online softmax (log2 domain); l kept as per-thread partials ----
        float mx0 = -1e30f, mx1 = -1e30f;
#pragma unroll
        for (int nt = 0; nt < 8; ++nt) {
            mx0 = fmaxf(mx0, fmaxf(sacc[nt][0], sacc[nt][1]));
            mx1 = fmaxf(mx1, fmaxf(sacc[nt][2], sacc[nt][3]));
        }
        mx0 = fmaxf(mx0, __shfl_xor_sync(0xffffffffu, mx0, 1));
        mx0 = fmaxf(mx0, __shfl_xor_sync(0xffffffffu, mx0, 2));
        mx1 = fmaxf(mx1, __shfl_xor_sync(0xffffffffu, mx1, 1));
        mx1 = fmaxf(mx1, __shfl_xor_sync(0xffffffffu, mx1, 2));
        float nm0 = fmaxf(m0, mx0), nm1 = fmaxf(m1, mx1);
        float corr0 = ex2(m0 - nm0), corr1 = ex2(m1 - nm1);
        m0 = nm0; m1 = nm1;

        float s0 = 0.0f, s1 = 0.0f;
#pragma unroll
        for (int nt = 0; nt < 8; ++nt) {
            float p0 = ex2(sacc[nt][0] - m0);
            float p1 = ex2(sacc[nt][1] - m0);
            float p2 = ex2(sacc[nt][2] - m1);
            float p3 = ex2(sacc[nt][3] - m1);
            s0 += p0 + p1; s1 += p2 + p3;
            sacc[nt][0] = p0; sacc[nt][1] = p1; sacc[nt][2] = p2; sacc[nt][3] = p3;
        }
        l0 = l0 * corr0 + s0;
        l1 = l1 * corr1 + s1;
#pragma unroll
        for (int dt = 0; dt < 4; ++dt) {
            oacc[dt][0] *= corr0; oacc[dt][1] *= corr0;
            oacc[dt][2] *= corr1; oacc[dt][3] *= corr1;
        }

        // ---- O += P V ; C-frag (cols 2c,2c+1) -> A-frag (cols c,c+4) via shfl ----
        int s0l = (lane & ~3) | (c >> 1);
        int s2l = s0l + 2;
        bool odd = (c & 1);
#pragma unroll
        for (int ks = 0; ks < 8; ++ks) {
            float p0 = sacc[ks][0], p1 = sacc[ks][1];
            float p2 = sacc[ks][2], p3 = sacc[ks][3];
            float e00 = __shfl_sync(0xffffffffu, p0, s0l);
            float e01 = __shfl_sync(0xffffffffu, p1, s0l);
            float e20 = __shfl_sync(0xffffffffu, p0, s2l);
            float e21 = __shfl_sync(0xffffffffu, p1, s2l);
            float f00 = __shfl_sync(0xffffffffu, p2, s0l);
            float f01 = __shfl_sync(0xffffffffu, p3, s0l);
            float f20 = __shfl_sync(0xffffffffu, p2, s2l);
            float f21 = __shfl_sync(0xffffffffu, p3, s2l);
            uint32_t a0 = __float_as_uint(odd ? e01 : e00);
            uint32_t a1 = __float_as_uint(odd ? f01 : f00);
            uint32_t a2 = __float_as_uint(odd ? e21 : e20);
            uint32_t a3 = __float_as_uint(odd ? f21 : f20);
#pragma unroll
            for (int dt = 0; dt < 4; ++dt) {
                uint32_t b0 = __float_as_uint(Vs[buf][ks * 8 + c    ][dt * 8 + g]);
                uint32_t b1 = __float_as_uint(Vs[buf][ks * 8 + c + 4][dt * 8 + g]);
                mma_tf32(oacc[dt], a0, a1, a2, a3, b0, b1);
            }
        }
    }

    // ---- final l reduction across the 4 lanes of each row group ----
    l0 += __shfl_xor_sync(0xffffffffu, l0, 1);
    l0 += __shfl_xor_sync(0xffffffffu, l0, 2);
    l1 += __shfl_xor_sync(0xffffffffu, l1, 1);
    l1 += __shfl_xor_sync(0xffffffffu, l1, 2);

    float inv0 = 1.0f / l0, inv1 = 1.0f / l1;
    float* Ob = O + ((size_t)(n * NP + qt * 128 + warp * 16)) * DMODEL + h * DH;
#pragma unroll
    for (int dt = 0; dt < 4; ++dt) {
        *(float2*)(Ob + (size_t)g       * DMODEL + dt * 8 + 2 * c) =
            make_float2(oacc[dt][0] * inv0, oacc[dt][1] * inv0);
        *(float2*)(Ob + (size_t)(g + 8) * DMODEL + dt * 8 + 2 * c) =
            make_float2(oacc[dt][2] * inv1, oacc[dt][3] * inv1);
    }
}

// ---------------- launch ------------------------------------------------------------
extern "C" void kernel_launch(void* const* d_in, const int* in_sizes, int n_in,
                              void* d_out, int out_size) {
    const float* local_feat  = (const float*)d_in[0];
    const float* global_feat = (const float*)d_in[1];
    const float* Wq = (const float*)d_in[2];
    const float* bq = (const float*)d_in[3];
    const float* Wk = (const float*)d_in[4];
    const float* bk = (const float*)d_in[5];
    const float* Wv = (const float*)d_in[6];
    const float* bv = (const float*)d_in[7];
    const float* Wo = (const float*)d_in[8];
    const float* bo = (const float*)d_in[9];
    float* out = (float*)d_out;

    float *lf_pe, *gf_pe, *q, *k, *v, *attn, *wq, *wk, *wv;
    cudaGetSymbolAddress((void**)&lf_pe, g_lf_pe);
    cudaGetSymbolAddress((void**)&gf_pe, g_gf_pe);
    cudaGetSymbolAddress((void**)&q,     g_q);
    cudaGetSymbolAddress((void**)&k,     g_k);
    cudaGetSymbolAddress((void**)&v,     g_v);
    cudaGetSymbolAddress((void**)&attn,  g_attn);
    cudaGetSymbolAddress((void**)&wq,    g_wq);
    cudaGetSymbolAddress((void**)&wk,    g_wk);
    cudaGetSymbolAddress((void**)&wv,    g_wv);

    const int GEMM_SMEM = (2 * 128 * 36 + 2 * 64 * 36) * (int)sizeof(float);    // 55296
    const int KV_SMEM   = (2 * 128 * 36 + 4 * 64 * 36) * (int)sizeof(float);    // 73728
    static bool attr_set = false;
    if (!attr_set) {
        cudaFuncSetAttribute(gemm_tf32_ca_kernel,
                             cudaFuncAttributeMaxDynamicSharedMemorySize, GEMM_SMEM);
        cudaFuncSetAttribute(gemm_kv_kernel,
                             cudaFuncAttributeMaxDynamicSharedMemorySize, KV_SMEM);
        attr_set = true;
    }

    // 0. round weights to tf32 once per call (cheap, off hot path)
    round_w_kernel<<<DMODEL * DMODEL / (256 * 4), 256>>>(Wq, Wk, Wv, wq, wk, wv);

    // 1. positional encodings (tf32-rounded outputs)
    pe_local_kernel<<<(NB * NP * DMODEL) / 256, 256>>>(local_feat, lf_pe);
    transpose_pe_kernel<<<dim3(HWG / 32, DMODEL / 32, NB), dim3(32, 8)>>>(global_feat, gf_pe);

    // 2. projections: Q (pre-scaled by 1/sqrt(DH)*log2e, rounded); K+V fused
    gemm_tf32_ca_kernel<<<dim3((NB * NP) / 128, DMODEL / 64), 256, GEMM_SMEM>>>(
        lf_pe, wq, bq, q, QSCALE, 1);
    gemm_kv_kernel<<<dim3((NB * HWG) / 128, DMODEL / 64), 256, KV_SMEM>>>(
        gf_pe, wk, wv, bk, bv, k, v);

    // 3. attention
    flash_attn_mma2_kernel<<<dim3(NP / 128, NHEADS, NB), 256>>>(q, k, v, attn);

    // 4. output projection with fused residual
    gemm_tf32_kernel<<<dim3((NB * NP) / 128, DMODEL / 64), 256>>>(lf_pe, attn, Wo, bo, out);
}

// round 12
// speedup vs baseline: 4.8082x; 1.3151x over previous
#include <cuda_runtime.h>
#include <cstdint>
#include <cstddef>

// Problem constants
#define NB   4        // batch
#define NP   1024     // local tokens (32x32)
#define DMODEL 256
#define HWG  4096     // global tokens (64x64)
#define NHEADS 8
#define DH   32
// -ln(10000)/256
#define NEG_LOG1E4_OVER_D (-0.035977892078030406f)
#define ATTN_SCALE 0.17677669529663687f            // 1/sqrt(32)
#define LOG2E 1.4426950408889634f
#define QSCALE (0.25501643154277775f)              // ATTN_SCALE * LOG2E

// ---------------- scratch (static device allocations; no cudaMalloc) ----------------
__device__ float g_lf_pe[NB * NP * DMODEL];
__device__ float g_gf_pe[NB * HWG * DMODEL];
__device__ float g_q[NB * NP * DMODEL];
__device__ float g_k[NB * HWG * DMODEL];
__device__ uint16_t g_vt[NB * DMODEL * HWG];       // V^T in bf16: [n][d][key]
__device__ float g_attn[NB * NP * DMODEL];
__device__ float g_wq[DMODEL * DMODEL];
__device__ float g_wk[DMODEL * DMODEL];
__device__ float g_wv[DMODEL * DMODEL];

// ---------------- helpers ------------------------------------------------------------
__device__ __forceinline__ float to_tf32(float x) {
    uint32_t u;
    asm("cvt.rna.tf32.f32 %0, %1;" : "=r"(u) : "f"(x));
    return __uint_as_float(u);
}
__device__ __forceinline__ float ex2(float x) {
    float y;
    asm("ex2.approx.f32 %0, %1;" : "=f"(y) : "f"(x));
    return y;
}
// pack two f32 into bf16x2: lo -> lower 16 bits, hi -> upper 16 bits
__device__ __forceinline__ uint32_t pack_bf16(float lo, float hi) {
    uint32_t r;
    asm("cvt.rn.bf16x2.f32 %0, %1, %2;" : "=r"(r) : "f"(hi), "f"(lo));
    return r;
}
__device__ __forceinline__ uint16_t bf16u(float x) {
    uint16_t r;
    asm("cvt.rn.bf16.f32 %0, %1;" : "=h"(r) : "f"(x));
    return r;
}
__device__ __forceinline__ void mma_tf32(float* d,
                                         uint32_t a0, uint32_t a1, uint32_t a2, uint32_t a3,
                                         uint32_t b0, uint32_t b1) {
    asm volatile(
        "mma.sync.aligned.m16n8k8.row.col.f32.tf32.tf32.f32 "
        "{%0,%1,%2,%3}, {%4,%5,%6,%7}, {%8,%9}, {%0,%1,%2,%3};\n"
        : "+f"(d[0]), "+f"(d[1]), "+f"(d[2]), "+f"(d[3])
        : "r"(a0), "r"(a1), "r"(a2), "r"(a3), "r"(b0), "r"(b1));
}
__device__ __forceinline__ void mma_bf16(float* d,
                                         uint32_t a0, uint32_t a1, uint32_t a2, uint32_t a3,
                                         uint32_t b0, uint32_t b1) {
    asm volatile(
        "mma.sync.aligned.m16n8k16.row.col.f32.bf16.bf16.f32 "
        "{%0,%1,%2,%3}, {%4,%5,%6,%7}, {%8,%9}, {%0,%1,%2,%3};\n"
        : "+f"(d[0]), "+f"(d[1]), "+f"(d[2]), "+f"(d[3])
        : "r"(a0), "r"(a1), "r"(a2), "r"(a3), "r"(b0), "r"(b1));
}
__device__ __forceinline__ void cp16(const void* smem_dst, const void* gmem_src) {
    uint32_t d = (uint32_t)__cvta_generic_to_shared(smem_dst);
    asm volatile("cp.async.ca.shared.global [%0], [%1], 16;" :: "r"(d), "l"(gmem_src));
}
__device__ __forceinline__ void cp_commit() { asm volatile("cp.async.commit_group;"); }
__device__ __forceinline__ void cp_wait1()  { asm volatile("cp.async.wait_group 1;"); }
__device__ __forceinline__ void cp_wait0()  { asm volatile("cp.async.wait_group 0;"); }

// ---------------- kernel 0: tf32-round Wq/Wk/Wv ---------------------------------------
__global__ __launch_bounds__(256) void round_w_kernel(const float* __restrict__ Wq,
                                                      const float* __restrict__ Wk,
                                                      const float* __restrict__ Wv,
                                                      float* __restrict__ wq,
                                                      float* __restrict__ wk,
                                                      float* __restrict__ wv) {
    int i = (blockIdx.x * 256 + threadIdx.x) * 4;
    float4 a = *(const float4*)(Wq + i);
    float4 b = *(const float4*)(Wk + i);
    float4 c = *(const float4*)(Wv + i);
    a.x = to_tf32(a.x); a.y = to_tf32(a.y); a.z = to_tf32(a.z); a.w = to_tf32(a.w);
    b.x = to_tf32(b.x); b.y = to_tf32(b.y); b.z = to_tf32(b.z); b.w = to_tf32(b.w);
    c.x = to_tf32(c.x); c.y = to_tf32(c.y); c.z = to_tf32(c.z); c.w = to_tf32(c.w);
    *(float4*)(wq + i) = a;
    *(float4*)(wk + i) = b;
    *(float4*)(wv + i) = c;
}

// ---------------- kernel 1: local_feat + positional encoding (tf32-rounded out) ------
__global__ __launch_bounds__(256) void pe_local_kernel(const float* __restrict__ in,
                                                       float* __restrict__ out) {
    int idx = blockIdx.x * 256 + threadIdx.x;
    int d = idx & (DMODEL - 1);
    int p = (idx >> 8) & (NP - 1);
    float x = (float)(p & 31) * (1.0f / 31.0f);
    float y = (float)(p >> 5) * (1.0f / 31.0f);
    float div = __expf((float)(d & ~1) * NEG_LOG1E4_OVER_D);
    float pe = (d & 1) ? __cosf(y * div) : __sinf(x * div);
    out[idx] = to_tf32(in[idx] + pe);
}

// ---------------- kernel 2: transpose global_feat + pos enc (tf32-rounded out) -------
__global__ __launch_bounds__(256) void transpose_pe_kernel(const float* __restrict__ gf,
                                                           float* __restrict__ out) {
    __shared__ float tile[32][33];
    int n  = blockIdx.z;
    int s0 = blockIdx.x * 32;
    int d0 = blockIdx.y * 32;
    int tx = threadIdx.x, ty = threadIdx.y;
    const float* g = gf + ((size_t)n * DMODEL + d0) * HWG + s0;
#pragma unroll
    for (int k = 0; k < 4; ++k)
        tile[ty + 8 * k][tx] = g[(size_t)(ty + 8 * k) * HWG + tx];
    __syncthreads();
#pragma unroll
    for (int k = 0; k < 4; ++k) {
        int s = s0 + ty + 8 * k;
        int d = d0 + tx;
        float x = (float)(s & 63) * (1.0f / 63.0f);
        float y = (float)(s >> 6) * (1.0f / 63.0f);
        float div = __expf((float)(d & ~1) * NEG_LOG1E4_OVER_D);
        float pe = (d & 1) ? __cosf(y * div) : __sinf(x * div);
        out[((size_t)n * HWG + s) * DMODEL + d] = to_tf32(tile[tx][ty + 8 * k] + pe);
    }
}

// ---------------- kernel 3a: cp.async 2-stage tf32 GEMM (pre-rounded inputs) ---------
__global__ __launch_bounds__(256, 2) void gemm_tf32_ca_kernel(const float* __restrict__ A,
                                                              const float* __restrict__ W,
                                                              const float* __restrict__ bias,
                                                              float* __restrict__ C,
                                                              float oscale, int oround) {
    extern __shared__ float sm[];
    float (*As)[128][36] = (float(*)[128][36])sm;
    float (*Ws)[64][36]  = (float(*)[64][36])(sm + 2 * 128 * 36);

    int m0 = blockIdx.x * 128, o0 = blockIdx.y * 64;
    int tid = threadIdx.x;
    int warp = tid >> 5, lane = tid & 31;
    int g = lane >> 2, c = lane & 3;
    int wm = (warp & 3) * 32;
    int wn = (warp >> 2) * 32;

    int sr = tid >> 3;
    int sc4 = (tid & 7) * 4;

    const float* Ap = A + (size_t)(m0 + sr) * DMODEL + sc4;
    const float* Wp = W + (size_t)(o0 + sr) * DMODEL + sc4;

#pragma unroll
    for (int j = 0; j < 4; ++j)
        cp16(&As[0][sr + 32 * j][sc4], Ap + (size_t)(32 * j) * DMODEL);
#pragma unroll
    for (int j = 0; j < 2; ++j)
        cp16(&Ws[0][sr + 32 * j][sc4], Wp + (size_t)(32 * j) * DMODEL);
    cp_commit();

    float acc[2][4][4] = {};

    for (int kc = 0; kc < 8; ++kc) {
        int buf = kc & 1;
        __syncthreads();
        if (kc < 7) {
            int ko = (kc + 1) * 32;
#pragma unroll
            for (int j = 0; j < 4; ++j)
                cp16(&As[buf ^ 1][sr + 32 * j][sc4], Ap + ko + (size_t)(32 * j) * DMODEL);
#pragma unroll
            for (int j = 0; j < 2; ++j)
                cp16(&Ws[buf ^ 1][sr + 32 * j][sc4], Wp + ko + (size_t)(32 * j) * DMODEL);
            cp_commit();
            cp_wait1();
        } else {
            cp_wait0();
        }
        __syncthreads();

#pragma unroll
        for (int ks = 0; ks < 4; ++ks) {
            int k = ks * 8;
            uint32_t af[2][4];
#pragma unroll
            for (int mt = 0; mt < 2; ++mt) {
                int r = wm + mt * 16;
                af[mt][0] = __float_as_uint(As[buf][r + g    ][k + c    ]);
                af[mt][1] = __float_as_uint(As[buf][r + g + 8][k + c    ]);
                af[mt][2] = __float_as_uint(As[buf][r + g    ][k + c + 4]);
                af[mt][3] = __float_as_uint(As[buf][r + g + 8][k + c + 4]);
            }
#pragma unroll
            for (int nt = 0; nt < 4; ++nt) {
                uint32_t b0 = __float_as_uint(Ws[buf][wn + nt * 8 + g][k + c    ]);
                uint32_t b1 = __float_as_uint(Ws[buf][wn + nt * 8 + g][k + c + 4]);
                mma_tf32(acc[0][nt], af[0][0], af[0][1], af[0][2], af[0][3], b0, b1);
                mma_tf32(acc[1][nt], af[1][0], af[1][1], af[1][2], af[1][3], b0, b1);
            }
        }
    }

#pragma unroll
    for (int nt = 0; nt < 4; ++nt) {
        float2 bv = *(const float2*)(bias + o0 + wn + nt * 8 + 2 * c);
#pragma unroll
        for (int mt = 0; mt < 2; ++mt) {
            float v0 = (acc[mt][nt][0] + bv.x) * oscale;
            float v1 = (acc[mt][nt][1] + bv.y) * oscale;
            float v2 = (acc[mt][nt][2] + bv.x) * oscale;
            float v3 = (acc[mt][nt][3] + bv.y) * oscale;
            if (oround) { v0 = to_tf32(v0); v1 = to_tf32(v1); v2 = to_tf32(v2); v3 = to_tf32(v3); }
            int row = m0 + wm + mt * 16 + g;
            float* Cp = C + (size_t)row * DMODEL + o0 + wn + nt * 8 + 2 * c;
            *(float2*)Cp = make_float2(v0, v1);
            *(float2*)(Cp + (size_t)8 * DMODEL) = make_float2(v2, v3);
        }
    }
}

// ---------------- kernel 3c: fused K+V projection --------------------------------------
// K -> fp32 tf32-rounded [key][d];  V -> bf16 TRANSPOSED Vt[n][d][key] via smem transpose.
__global__ __launch_bounds__(256, 2) void gemm_kv_kernel(const float* __restrict__ A,
                                                         const float* __restrict__ Wk,
                                                         const float* __restrict__ Wv,
                                                         const float* __restrict__ bk,
                                                         const float* __restrict__ bv,
                                                         float* __restrict__ K,
                                                         uint16_t* __restrict__ Vt) {
    extern __shared__ float sm[];
    float (*As)[128][36]  = (float(*)[128][36])sm;                    // 2 stages
    float (*Wks)[64][36]  = (float(*)[64][36])(sm + 2 * 128 * 36);
    float (*Wvs)[64][36]  = (float(*)[64][36])(sm + 2 * 128 * 36 + 2 * 64 * 36);

    int m0 = blockIdx.x * 128, o0 = blockIdx.y * 64;
    int tid = threadIdx.x;
    int warp = tid >> 5, lane = tid & 31;
    int g = lane >> 2, c = lane & 3;
    int wm = (warp & 3) * 32;
    int wn = (warp >> 2) * 32;

    int sr = tid >> 3;
    int sc4 = (tid & 7) * 4;

    const float* Ap  = A + (size_t)(m0 + sr) * DMODEL + sc4;
    const float* Wkp = Wk + (size_t)(o0 + sr) * DMODEL + sc4;
    const float* Wvp = Wv + (size_t)(o0 + sr) * DMODEL + sc4;

#pragma unroll
    for (int j = 0; j < 4; ++j)
        cp16(&As[0][sr + 32 * j][sc4], Ap + (size_t)(32 * j) * DMODEL);
#pragma unroll
    for (int j = 0; j < 2; ++j) {
        cp16(&Wks[0][sr + 32 * j][sc4], Wkp + (size_t)(32 * j) * DMODEL);
        cp16(&Wvs[0][sr + 32 * j][sc4], Wvp + (size_t)(32 * j) * DMODEL);
    }
    cp_commit();

    float ack[2][4][4] = {};
    float acv[2][4][4] = {};

    for (int kc = 0; kc < 8; ++kc) {
        int buf = kc & 1;
        __syncthreads();
        if (kc < 7) {
            int ko = (kc + 1) * 32;
#pragma unroll
            for (int j = 0; j < 4; ++j)
                cp16(&As[buf ^ 1][sr + 32 * j][sc4], Ap + ko + (size_t)(32 * j) * DMODEL);
#pragma unroll
            for (int j = 0; j < 2; ++j) {
                cp16(&Wks[buf ^ 1][sr + 32 * j][sc4], Wkp + ko + (size_t)(32 * j) * DMODEL);
                cp16(&Wvs[buf ^ 1][sr + 32 * j][sc4], Wvp + ko + (size_t)(32 * j) * DMODEL);
            }
            cp_commit();
            cp_wait1();
        } else {
            cp_wait0();
        }
        __syncthreads();

#pragma unroll
        for (int ks = 0; ks < 4; ++ks) {
            int k = ks * 8;
            uint32_t af[2][4];
#pragma unroll
            for (int mt = 0; mt < 2; ++mt) {
                int r = wm + mt * 16;
                af[mt][0] = __float_as_uint(As[buf][r + g    ][k + c    ]);
                af[mt][1] = __float_as_uint(As[buf][r + g + 8][k + c    ]);
                af[mt][2] = __float_as_uint(As[buf][r + g    ][k + c + 4]);
                af[mt][3] = __float_as_uint(As[buf][r + g + 8][k + c + 4]);
            }
#pragma unroll
            for (int nt = 0; nt < 4; ++nt) {
                uint32_t k0 = __float_as_uint(Wks[buf][wn + nt * 8 + g][k + c    ]);
                uint32_t k1 = __float_as_uint(Wks[buf][wn + nt * 8 + g][k + c + 4]);
                uint32_t v0 = __float_as_uint(Wvs[buf][wn + nt * 8 + g][k + c    ]);
                uint32_t v1 = __float_as_uint(Wvs[buf][wn + nt * 8 + g][k + c + 4]);
                mma_tf32(ack[0][nt], af[0][0], af[0][1], af[0][2], af[0][3], k0, k1);
                mma_tf32(ack[1][nt], af[1][0], af[1][1], af[1][2], af[1][3], k0, k1);
                mma_tf32(acv[0][nt], af[0][0], af[0][1], af[0][2], af[0][3], v0, v1);
                mma_tf32(acv[1][nt], af[1][0], af[1][1], af[1][2], af[1][3], v0, v1);
            }
        }
    }

    // ---- K epilogue: fp32 (tf32-rounded) [key][d] ----
#pragma unroll
    for (int nt = 0; nt < 4; ++nt) {
        float2 bkv = *(const float2*)(bk + o0 + wn + nt * 8 + 2 * c);
#pragma unroll
        for (int mt = 0; mt < 2; ++mt) {
            int row = m0 + wm + mt * 16 + g;
            size_t off = (size_t)row * DMODEL + o0 + wn + nt * 8 + 2 * c;
            *(float2*)(K + off) = make_float2(to_tf32(ack[mt][nt][0] + bkv.x),
                                              to_tf32(ack[mt][nt][1] + bkv.y));
            *(float2*)(K + off + (size_t)8 * DMODEL) =
                make_float2(to_tf32(ack[mt][nt][2] + bkv.x), to_tf32(ack[mt][nt][3] + bkv.y));
        }
    }

    // ---- V epilogue: bf16 transpose through smem (reuse As region) ----
    __syncthreads();
    uint16_t* vts = (uint16_t*)sm;     // [64][136] (d x key), stride 136 -> 16B-aligned rows
#pragma unroll
    for (int nt = 0; nt < 4; ++nt) {
        float2 bvv = *(const float2*)(bv + o0 + wn + nt * 8 + 2 * c);
        int d = wn + nt * 8 + 2 * c;
#pragma unroll
        for (int mt = 0; mt < 2; ++mt) {
            int key = wm + mt * 16 + g;
            vts[(d    ) * 136 + key    ] = bf16u(acv[mt][nt][0] + bvv.x);
            vts[(d + 1) * 136 + key    ] = bf16u(acv[mt][nt][1] + bvv.y);
            vts[(d    ) * 136 + key + 8] = bf16u(acv[mt][nt][2] + bvv.x);
            vts[(d + 1) * 136 + key + 8] = bf16u(acv[mt][nt][3] + bvv.y);
        }
    }
    __syncthreads();

    int dr = tid >> 2, kb = (tid & 3) * 32;
    int nb = m0 >> 12, key0 = m0 & (HWG - 1);
    uint16_t* dst = Vt + ((size_t)(nb * DMODEL + o0 + dr)) * HWG + key0 + kb;
#pragma unroll
    for (int j = 0; j < 4; ++j)
        *(uint4*)(dst + j * 8) = *(const uint4*)&vts[dr * 136 + kb + j * 8];
}

// ---------------- kernel 3b: register-prefetch tf32 GEMM with fused A2 add (O-proj) --
__global__ __launch_bounds__(256) void gemm_tf32_kernel(const float* __restrict__ A,
                                                        const float* __restrict__ A2,
                                                        const float* __restrict__ W,
                                                        const float* __restrict__ bias,
                                                        float* __restrict__ C) {
    __shared__ float As[128][36];
    __shared__ float Ws[64][36];

    int m0 = blockIdx.x * 128, o0 = blockIdx.y * 64;
    int tid = threadIdx.x;
    int warp = tid >> 5, lane = tid & 31;
    int g = lane >> 2, c = lane & 3;
    int wm = (warp & 3) * 32;
    int wn = (warp >> 2) * 32;

    int lr  = tid >> 3;
    int lk4 = (tid & 7) * 4;

    const float* Ap  = A + (size_t)(m0 + lr) * DMODEL + lk4;
    const float* A2p = A2 + (size_t)(m0 + lr) * DMODEL + lk4;
    const float* Wp  = W + (size_t)(o0 + lr) * DMODEL + lk4;

    float4 ra[4], rw[2];
#pragma unroll
    for (int i = 0; i < 4; ++i) {
        float4 v = *(const float4*)(Ap + (size_t)(32 * i) * DMODEL);
        float4 u = *(const float4*)(A2p + (size_t)(32 * i) * DMODEL);
        v.x += u.x; v.y += u.y; v.z += u.z; v.w += u.w;
        ra[i] = v;
    }
#pragma unroll
    for (int i = 0; i < 2; ++i)
        rw[i] = *(const float4*)(Wp + (size_t)(32 * i) * DMODEL);

    float acc[2][4][4] = {};

    for (int kc = 0; kc < 8; ++kc) {
#pragma unroll
        for (int i = 0; i < 4; ++i) {
            float4 v = ra[i];
            v.x = to_tf32(v.x); v.y = to_tf32(v.y); v.z = to_tf32(v.z); v.w = to_tf32(v.w);
            *(float4*)&As[lr + 32 * i][lk4] = v;
        }
#pragma unroll
        for (int i = 0; i < 2; ++i) {
            float4 v = rw[i];
            v.x = to_tf32(v.x); v.y = to_tf32(v.y); v.z = to_tf32(v.z); v.w = to_tf32(v.w);
            *(float4*)&Ws[lr + 32 * i][lk4] = v;
        }
        __syncthreads();

        if (kc < 7) {
            int ko = (kc + 1) * 32;
#pragma unroll
            for (int i = 0; i < 4; ++i) {
                float4 v = *(const float4*)(Ap + ko + (size_t)(32 * i) * DMODEL);
                float4 u = *(const float4*)(A2p + ko + (size_t)(32 * i) * DMODEL);
                v.x += u.x; v.y += u.y; v.z += u.z; v.w += u.w;
                ra[i] = v;
            }
#pragma unroll
            for (int i = 0; i < 2; ++i)
                rw[i] = *(const float4*)(Wp + ko + (size_t)(32 * i) * DMODEL);
        }

#pragma unroll
        for (int ks = 0; ks < 4; ++ks) {
            int k = ks * 8;
            uint32_t af[2][4];
#pragma unroll
            for (int mt = 0; mt < 2; ++mt) {
                int r = wm + mt * 16;
                af[mt][0] = __float_as_uint(As[r + g    ][k + c    ]);
                af[mt][1] = __float_as_uint(As[r + g + 8][k + c    ]);
                af[mt][2] = __float_as_uint(As[r + g    ][k + c + 4]);
                af[mt][3] = __float_as_uint(As[r + g + 8][k + c + 4]);
            }
#pragma unroll
            for (int nt = 0; nt < 4; ++nt) {
                uint32_t b0 = __float_as_uint(Ws[wn + nt * 8 + g][k + c    ]);
                uint32_t b1 = __float_as_uint(Ws[wn + nt * 8 + g][k + c + 4]);
                mma_tf32(acc[0][nt], af[0][0], af[0][1], af[0][2], af[0][3], b0, b1);
                mma_tf32(acc[1][nt], af[1][0], af[1][1], af[1][2], af[1][3], b0, b1);
            }
        }
        __syncthreads();
    }

#pragma unroll
    for (int nt = 0; nt < 4; ++nt) {
        float2 bv = *(const float2*)(bias + o0 + wn + nt * 8 + 2 * c);
#pragma unroll
        for (int mt = 0; mt < 2; ++mt) {
            int row = m0 + wm + mt * 16 + g;
            float* Cp = C + (size_t)row * DMODEL + o0 + wn + nt * 8 + 2 * c;
            *(float2*)Cp = make_float2(acc[mt][nt][0] + bv.x, acc[mt][nt][1] + bv.y);
            *(float2*)(Cp + (size_t)8 * DMODEL) =
                make_float2(acc[mt][nt][2] + bv.x, acc[mt][nt][3] + bv.y);
        }
    }
}

// ---------------- kernel 4: flash attention, tf32 QK + bf16 PV (no shfl) -------------
__global__ __launch_bounds__(256, 2) void flash_attn_mma3_kernel(const float* __restrict__ Q,
                                                                 const float* __restrict__ K,
                                                                 const uint16_t* __restrict__ Vt,
                                                                 float* __restrict__ O) {
    __shared__ float Ks[2][64][36];        // [key][d] fp32; banks 4g+c conflict-free
    __shared__ uint32_t Vs[2][32][36];     // [d][key-pair] bf16x2; banks 4g+c conflict-free

    int qt = blockIdx.x, h = blockIdx.y, n = blockIdx.z;
    int tid  = threadIdx.x;
    int warp = tid >> 5, lane = tid & 31;
    int g = lane >> 2, c = lane & 3;

    const float* Qb = Q + ((size_t)(n * NP + qt * 128 + warp * 16)) * DMODEL + h * DH;
    uint32_t qf[4][4];
#pragma unroll
    for (int ks = 0; ks < 4; ++ks) {
        qf[ks][0] = __float_as_uint(Qb[(size_t)g       * DMODEL + ks * 8 + c    ]);
        qf[ks][1] = __float_as_uint(Qb[(size_t)(g + 8) * DMODEL + ks * 8 + c    ]);
        qf[ks][2] = __float_as_uint(Qb[(size_t)g       * DMODEL + ks * 8 + c + 4]);
        qf[ks][3] = __float_as_uint(Qb[(size_t)(g + 8) * DMODEL + ks * 8 + c + 4]);
    }

    const float* Kb0 = K + (size_t)n * HWG * DMODEL + h * DH;
    const uint16_t* Vt0 = Vt + ((size_t)(n * DMODEL + h * DH)) * HWG;

    int sr = tid >> 3;                 // 0..31
    int sc4 = (tid & 7) * 4;           // K staging col (floats)
    int vrow = tid >> 3;               // 0..31 (d)
    int vcol = (tid & 7) * 8;          // key offset (bf16 elements)

    {
        cp16(&Ks[0][sr][sc4],      Kb0 + (size_t)sr * DMODEL + sc4);
        cp16(&Ks[0][sr + 32][sc4], Kb0 + (size_t)(sr + 32) * DMODEL + sc4);
        cp16(&Vs[0][vrow][vcol / 2], Vt0 + (size_t)vrow * HWG + vcol);
        cp_commit();
    }

    float m0 = -1e30f, m1 = -1e30f;
    float l0 = 0.0f, l1 = 0.0f;
    float oacc[4][4] = {};

    for (int kt = 0; kt < HWG / 64; ++kt) {
        int buf = kt & 1;
        __syncthreads();
        if (kt < HWG / 64 - 1) {
            const float* Kb = Kb0 + (size_t)(kt + 1) * 64 * DMODEL;
            const uint16_t* Vb = Vt0 + (kt + 1) * 64;
            cp16(&Ks[buf ^ 1][sr][sc4],      Kb + (size_t)sr * DMODEL + sc4);
            cp16(&Ks[buf ^ 1][sr + 32][sc4], Kb + (size_t)(sr + 32) * DMODEL + sc4);
            cp16(&Vs[buf ^ 1][vrow][vcol / 2], Vb + (size_t)vrow * HWG + vcol);
            cp_commit();
            cp_wait1();
        } else {
            cp_wait0();
        }
        __syncthreads();

        // ---- S = Q K^T (log2-scaled scores), tf32 ----
        float sacc[8][4];
#pragma unroll
        for (int nt = 0; nt < 8; ++nt) {
            sacc[nt][0] = 0.f; sacc[nt][1] = 0.f; sacc[nt][2] = 0.f; sacc[nt][3] = 0.f;
#pragma unroll
            for (int ks = 0; ks < 4; ++ks) {
                uint32_t b0 = __float_as_uint(Ks[buf][nt * 8 + g][ks * 8 + c]);
                uint32_t b1 = __float_as_uint(Ks[buf][nt * 8 + g][ks * 8 + c + 4]);
                mma_tf32(sacc[nt], qf[ks][0], qf[ks][1], qf[ks][2], qf[ks][3], b0, b1);
            }
        }

        // ---- online softmax (log2 domain); l as per-thread partials ----
        float mx0 = -1e30f, mx1 = -1e30f;
#pragma unroll
        for (int nt = 0; nt < 8; ++nt) {
            mx0 = fmaxf(mx0, fmaxf(sacc[nt][0], sacc[nt][1]));
            mx1 = fmaxf(mx1, fmaxf(sacc[nt][2], sacc[nt][3]));
        }
        mx0 = fmaxf(mx0, __shfl_xor_sync(0xffffffffu, mx0, 1));
        mx0 = fmaxf(mx0, __shfl_xor_sync(0xffffffffu, mx0, 2));
        mx1 = fmaxf(mx1, __shfl_xor_sync(0xffffffffu, mx1, 1));
        mx1 = fmaxf(mx1, __shfl_xor_sync(0xffffffffu, mx1, 2));
        float nm0 = fmaxf(m0, mx0), nm1 = fmaxf(m1, mx1);
        float corr0 = ex2(m0 - nm0), corr1 = ex2(m1 - nm1);
        m0 = nm0; m1 = nm1;

        float s0 = 0.0f, s1 = 0.0f;
#pragma unroll
        for (int nt = 0; nt < 8; ++nt) {
            float p0 = ex2(sacc[nt][0] - m0);
            float p1 = ex2(sacc[nt][1] - m0);
            float p2 = ex2(sacc[nt][2] - m1);
            float p3 = ex2(sacc[nt][3] - m1);
            s0 += p0 + p1; s1 += p2 + p3;
            sacc[nt][0] = p0; sacc[nt][1] = p1; sacc[nt][2] = p2; sacc[nt][3] = p3;
        }
        l0 = l0 * corr0 + s0;
        l1 = l1 * corr1 + s1;
#pragma unroll
        for (int dt = 0; dt < 4; ++dt) {
            oacc[dt][0] *= corr0; oacc[dt][1] *= corr0;
            oacc[dt][2] *= corr1; oacc[dt][3] *= corr1;
        }

        // ---- O += P V : bf16 m16n8k16; C-frag packs DIRECTLY into A-frag ----
#pragma unroll
        for (int ks = 0; ks < 4; ++ks) {       // 4 k-steps of 16 keys
            uint32_t a0 = pack_bf16(sacc[2 * ks    ][0], sacc[2 * ks    ][1]); // row g,   k 2c,2c+1
            uint32_t a1 = pack_bf16(sacc[2 * ks    ][2], sacc[2 * ks    ][3]); // row g+8, k 2c,2c+1
            uint32_t a2 = pack_bf16(sacc[2 * ks + 1][0], sacc[2 * ks + 1][1]); // row g,   k 2c+8,+9
            uint32_t a3 = pack_bf16(sacc[2 * ks + 1][2], sacc[2 * ks + 1][3]); // row g+8, k 2c+8,+9
#pragma unroll
            for (int dt = 0; dt < 4; ++dt) {
                uint32_t b0 = Vs[buf][dt * 8 + g][ks * 8 + c    ];   // keys 16ks+2c,2c+1 @ d
                uint32_t b1 = Vs[buf][dt * 8 + g][ks * 8 + c + 4];   // keys 16ks+2c+8,+9 @ d
                mma_bf16(oacc[dt], a0, a1, a2, a3, b0, b1);
            }
        }
    }

    // ---- final l reduction across the 4 lanes of each row group ----
    l0 += __shfl_xor_sync(0xffffffffu, l0, 1);
    l0 += __shfl_xor_sync(0xffffffffu, l0, 2);
    l1 += __shfl_xor_sync(0xffffffffu, l1, 1);
    l1 += __shfl_xor_sync(0xffffffffu, l1, 2);

    float inv0 = 1.0f / l0, inv1 = 1.0f / l1;
    float* Ob = O + ((size_t)(n * NP + qt * 128 + warp * 16)) * DMODEL + h * DH;
#pragma unroll
    for (int dt = 0; dt < 4; ++dt) {
        *(float2*)(Ob + (size_t)g       * DMODEL + dt * 8 + 2 * c) =
            make_float2(oacc[dt][0] * inv0, oacc[dt][1] * inv0);
        *(float2*)(Ob + (size_t)(g + 8) * DMODEL + dt * 8 + 2 * c) =
            make_float2(oacc[dt][2] * inv1, oacc[dt][3] * inv1);
    }
}

// ---------------- launch ------------------------------------------------------------
extern "C" void kernel_launch(void* const* d_in, const int* in_sizes, int n_in,
                              void* d_out, int out_size) {
    const float* local_feat  = (const float*)d_in[0];
    const float* global_feat = (const float*)d_in[1];
    const float* Wq = (const float*)d_in[2];
    const float* bq = (const float*)d_in[3];
    const float* Wk = (const float*)d_in[4];
    const float* bk = (const float*)d_in[5];
    const float* Wv = (const float*)d_in[6];
    const float* bv = (const float*)d_in[7];
    const float* Wo = (const float*)d_in[8];
    const float* bo = (const float*)d_in[9];
    float* out = (float*)d_out;

    float *lf_pe, *gf_pe, *q, *k, *attn, *wq, *wk, *wv;
    uint16_t* vt;
    cudaGetSymbolAddress((void**)&lf_pe, g_lf_pe);
    cudaGetSymbolAddress((void**)&gf_pe, g_gf_pe);
    cudaGetSymbolAddress((void**)&q,     g_q);
    cudaGetSymbolAddress((void**)&k,     g_k);
    cudaGetSymbolAddress((void**)&vt,    g_vt);
    cudaGetSymbolAddress((void**)&attn,  g_attn);
    cudaGetSymbolAddress((void**)&wq,    g_wq);
    cudaGetSymbolAddress((void**)&wk,    g_wk);
    cudaGetSymbolAddress((void**)&wv,    g_wv);

    const int GEMM_SMEM = (2 * 128 * 36 + 2 * 64 * 36) * (int)sizeof(float);    // 55296
    const int KV_SMEM   = (2 * 128 * 36 + 4 * 64 * 36) * (int)sizeof(float);    // 73728
    static bool attr_set = false;
    if (!attr_set) {
        cudaFuncSetAttribute(gemm_tf32_ca_kernel,
                             cudaFuncAttributeMaxDynamicSharedMemorySize, GEMM_SMEM);
        cudaFuncSetAttribute(gemm_kv_kernel,
                             cudaFuncAttributeMaxDynamicSharedMemorySize, KV_SMEM);
        attr_set = true;
    }

    // 0. round weights to tf32 once (off hot path)
    round_w_kernel<<<DMODEL * DMODEL / (256 * 4), 256>>>(Wq, Wk, Wv, wq, wk, wv);

    // 1. positional encodings (tf32-rounded outputs)
    pe_local_kernel<<<(NB * NP * DMODEL) / 256, 256>>>(local_feat, lf_pe);
    transpose_pe_kernel<<<dim3(HWG / 32, DMODEL / 32, NB), dim3(32, 8)>>>(global_feat, gf_pe);

    // 2. projections: Q (pre-scaled, rounded); K + V^T(bf16) fused
    gemm_tf32_ca_kernel<<<dim3((NB * NP) / 128, DMODEL / 64), 256, GEMM_SMEM>>>(
        lf_pe, wq, bq, q, QSCALE, 1);
    gemm_kv_kernel<<<dim3((NB * HWG) / 128, DMODEL / 64), 256, KV_SMEM>>>(
        gf_pe, wk, wv, bk, bv, k, vt);

    // 3. attention (tf32 QK, bf16 PV)
    flash_attn_mma3_kernel<<<dim3(NP / 128, NHEADS, NB), 256>>>(q, k, vt, attn);

    // 4. output projection with fused residual
    gemm_tf32_kernel<<<dim3((NB * NP) / 128, DMODEL / 64), 256>>>(lf_pe, attn, Wo, bo, out);
}

// round 14
// speedup vs baseline: 5.3825x; 1.1194x over previous
#include <cuda_runtime.h>
#include <cstdint>
#include <cstddef>

// Problem constants
#define NB   4        // batch
#define NP   1024     // local tokens (32x32)
#define DMODEL 256
#define HWG  4096     // global tokens (64x64)
#define NHEADS 8
#define DH   32
// -ln(10000)/256
#define NEG_LOG1E4_OVER_D (-0.035977892078030406f)
#define ATTN_SCALE 0.17677669529663687f            // 1/sqrt(32)
#define LOG2E 1.4426950408889634f
#define QSCALE (0.25501643154277775f)              // ATTN_SCALE * LOG2E

// ---------------- scratch (static device allocations; no cudaMalloc) ----------------
__device__ float g_lf_pe[NB * NP * DMODEL];
__device__ float g_gf_pe[NB * HWG * DMODEL];
__device__ uint16_t g_q[NB * NP * DMODEL];         // Q in bf16 (pre-scaled by QSCALE)
__device__ uint16_t g_k[NB * HWG * DMODEL];        // K in bf16 [key][d]
__device__ uint16_t g_vt[NB * DMODEL * HWG];       // V^T in bf16: [n][d][key]
__device__ float g_attn[NB * NP * DMODEL];
__device__ float g_wq[DMODEL * DMODEL];
__device__ float g_wk[DMODEL * DMODEL];
__device__ float g_wv[DMODEL * DMODEL];

// ---------------- helpers ------------------------------------------------------------
__device__ __forceinline__ float to_tf32(float x) {
    uint32_t u;
    asm("cvt.rna.tf32.f32 %0, %1;" : "=r"(u) : "f"(x));
    return __uint_as_float(u);
}
__device__ __forceinline__ float ex2(float x) {
    float y;
    asm("ex2.approx.f32 %0, %1;" : "=f"(y) : "f"(x));
    return y;
}
// pack two f32 into bf16x2: lo -> lower 16 bits, hi -> upper 16 bits
__device__ __forceinline__ uint32_t pack_bf16(float lo, float hi) {
    uint32_t r;
    asm("cvt.rn.bf16x2.f32 %0, %1, %2;" : "=r"(r) : "f"(hi), "f"(lo));
    return r;
}
__device__ __forceinline__ uint16_t bf16u(float x) {
    uint16_t r;
    asm("cvt.rn.bf16.f32 %0, %1;" : "=h"(r) : "f"(x));
    return r;
}
__device__ __forceinline__ void mma_tf32(float* d,
                                         uint32_t a0, uint32_t a1, uint32_t a2, uint32_t a3,
                                         uint32_t b0, uint32_t b1) {
    asm volatile(
        "mma.sync.aligned.m16n8k8.row.col.f32.tf32.tf32.f32 "
        "{%0,%1,%2,%3}, {%4,%5,%6,%7}, {%8,%9}, {%0,%1,%2,%3};\n"
        : "+f"(d[0]), "+f"(d[1]), "+f"(d[2]), "+f"(d[3])
        : "r"(a0), "r"(a1), "r"(a2), "r"(a3), "r"(b0), "r"(b1));
}
__device__ __forceinline__ void mma_bf16(float* d,
                                         uint32_t a0, uint32_t a1, uint32_t a2, uint32_t a3,
                                         uint32_t b0, uint32_t b1) {
    asm volatile(
        "mma.sync.aligned.m16n8k16.row.col.f32.bf16.bf16.f32 "
        "{%0,%1,%2,%3}, {%4,%5,%6,%7}, {%8,%9}, {%0,%1,%2,%3};\n"
        : "+f"(d[0]), "+f"(d[1]), "+f"(d[2]), "+f"(d[3])
        : "r"(a0), "r"(a1), "r"(a2), "r"(a3), "r"(b0), "r"(b1));
}
__device__ __forceinline__ void cp16(const void* smem_dst, const void* gmem_src) {
    uint32_t d = (uint32_t)__cvta_generic_to_shared(smem_dst);
    asm volatile("cp.async.ca.shared.global [%0], [%1], 16;" :: "r"(d), "l"(gmem_src));
}
__device__ __forceinline__ void cp_commit() { asm volatile("cp.async.commit_group;"); }
__device__ __forceinline__ void cp_wait1()  { asm volatile("cp.async.wait_group 1;"); }
__device__ __forceinline__ void cp_wait0()  { asm volatile("cp.async.wait_group 0;"); }

// ---------------- kernel 0: tf32-round Wq/Wk/Wv ---------------------------------------
__global__ __launch_bounds__(256) void round_w_kernel(const float* __restrict__ Wq,
                                                      const float* __restrict__ Wk,
                                                      const float* __restrict__ Wv,
                                                      float* __restrict__ wq,
                                                      float* __restrict__ wk,
                                                      float* __restrict__ wv) {
    int i = (blockIdx.x * 256 + threadIdx.x) * 4;
    float4 a = *(const float4*)(Wq + i);
    float4 b = *(const float4*)(Wk + i);
    float4 c = *(const float4*)(Wv + i);
    a.x = to_tf32(a.x); a.y = to_tf32(a.y); a.z = to_tf32(a.z); a.w = to_tf32(a.w);
    b.x = to_tf32(b.x); b.y = to_tf32(b.y); b.z = to_tf32(b.z); b.w = to_tf32(b.w);
    c.x = to_tf32(c.x); c.y = to_tf32(c.y); c.z = to_tf32(c.z); c.w = to_tf32(c.w);
    *(float4*)(wq + i) = a;
    *(float4*)(wk + i) = b;
    *(float4*)(wv + i) = c;
}

// ---------------- kernel 1: local_feat + positional encoding (tf32-rounded out) ------
__global__ __launch_bounds__(256) void pe_local_kernel(const float* __restrict__ in,
                                                       float* __restrict__ out) {
    int idx = blockIdx.x * 256 + threadIdx.x;
    int d = idx & (DMODEL - 1);
    int p = (idx >> 8) & (NP - 1);
    float x = (float)(p & 31) * (1.0f / 31.0f);
    float y = (float)(p >> 5) * (1.0f / 31.0f);
    float div = __expf((float)(d & ~1) * NEG_LOG1E4_OVER_D);
    float pe = (d & 1) ? __cosf(y * div) : __sinf(x * div);
    out[idx] = to_tf32(in[idx] + pe);
}

// ---------------- kernel 2: transpose global_feat + pos enc (tf32-rounded out) -------
__global__ __launch_bounds__(256) void transpose_pe_kernel(const float* __restrict__ gf,
                                                           float* __restrict__ out) {
    __shared__ float tile[32][33];
    int n  = blockIdx.z;
    int s0 = blockIdx.x * 32;
    int d0 = blockIdx.y * 32;
    int tx = threadIdx.x, ty = threadIdx.y;
    const float* g = gf + ((size_t)n * DMODEL + d0) * HWG + s0;
#pragma unroll
    for (int k = 0; k < 4; ++k)
        tile[ty + 8 * k][tx] = g[(size_t)(ty + 8 * k) * HWG + tx];
    __syncthreads();
#pragma unroll
    for (int k = 0; k < 4; ++k) {
        int s = s0 + ty + 8 * k;
        int d = d0 + tx;
        float x = (float)(s & 63) * (1.0f / 63.0f);
        float y = (float)(s >> 6) * (1.0f / 63.0f);
        float div = __expf((float)(d & ~1) * NEG_LOG1E4_OVER_D);
        float pe = (d & 1) ? __cosf(y * div) : __sinf(x * div);
        out[((size_t)n * HWG + s) * DMODEL + d] = to_tf32(tile[tx][ty + 8 * k] + pe);
    }
}

// ---------------- kernel 3a: Q projection -> bf16, pre-scaled by QSCALE --------------
__global__ __launch_bounds__(256, 2) void gemm_q_kernel(const float* __restrict__ A,
                                                        const float* __restrict__ W,
                                                        const float* __restrict__ bias,
                                                        uint32_t* __restrict__ Qb) {
    extern __shared__ float sm[];
    float (*As)[128][36] = (float(*)[128][36])sm;
    float (*Ws)[64][36]  = (float(*)[64][36])(sm + 2 * 128 * 36);

    int m0 = blockIdx.x * 128, o0 = blockIdx.y * 64;
    int tid = threadIdx.x;
    int warp = tid >> 5, lane = tid & 31;
    int g = lane >> 2, c = lane & 3;
    int wm = (warp & 3) * 32;
    int wn = (warp >> 2) * 32;

    int sr = tid >> 3;
    int sc4 = (tid & 7) * 4;

    const float* Ap = A + (size_t)(m0 + sr) * DMODEL + sc4;
    const float* Wp = W + (size_t)(o0 + sr) * DMODEL + sc4;

#pragma unroll
    for (int j = 0; j < 4; ++j)
        cp16(&As[0][sr + 32 * j][sc4], Ap + (size_t)(32 * j) * DMODEL);
#pragma unroll
    for (int j = 0; j < 2; ++j)
        cp16(&Ws[0][sr + 32 * j][sc4], Wp + (size_t)(32 * j) * DMODEL);
    cp_commit();

    float acc[2][4][4] = {};

    for (int kc = 0; kc < 8; ++kc) {
        int buf = kc & 1;
        __syncthreads();
        if (kc < 7) {
            int ko = (kc + 1) * 32;
#pragma unroll
            for (int j = 0; j < 4; ++j)
                cp16(&As[buf ^ 1][sr + 32 * j][sc4], Ap + ko + (size_t)(32 * j) * DMODEL);
#pragma unroll
            for (int j = 0; j < 2; ++j)
                cp16(&Ws[buf ^ 1][sr + 32 * j][sc4], Wp + ko + (size_t)(32 * j) * DMODEL);
            cp_commit();
            cp_wait1();
        } else {
            cp_wait0();
        }
        __syncthreads();

#pragma unroll
        for (int ks = 0; ks < 4; ++ks) {
            int k = ks * 8;
            uint32_t af[2][4];
#pragma unroll
            for (int mt = 0; mt < 2; ++mt) {
                int r = wm + mt * 16;
                af[mt][0] = __float_as_uint(As[buf][r + g    ][k + c    ]);
                af[mt][1] = __float_as_uint(As[buf][r + g + 8][k + c    ]);
                af[mt][2] = __float_as_uint(As[buf][r + g    ][k + c + 4]);
                af[mt][3] = __float_as_uint(As[buf][r + g + 8][k + c + 4]);
            }
#pragma unroll
            for (int nt = 0; nt < 4; ++nt) {
                uint32_t b0 = __float_as_uint(Ws[buf][wn + nt * 8 + g][k + c    ]);
                uint32_t b1 = __float_as_uint(Ws[buf][wn + nt * 8 + g][k + c + 4]);
                mma_tf32(acc[0][nt], af[0][0], af[0][1], af[0][2], af[0][3], b0, b1);
                mma_tf32(acc[1][nt], af[1][0], af[1][1], af[1][2], af[1][3], b0, b1);
            }
        }
    }

    // epilogue: bias, QSCALE, pack to bf16 pairs [token][d/2]
#pragma unroll
    for (int nt = 0; nt < 4; ++nt) {
        float2 bv = *(const float2*)(bias + o0 + wn + nt * 8 + 2 * c);
        int colp = (o0 + wn) / 2 + nt * 4 + c;
#pragma unroll
        for (int mt = 0; mt < 2; ++mt) {
            int row = m0 + wm + mt * 16 + g;
            Qb[(size_t)row * 128 + colp] =
                pack_bf16((acc[mt][nt][0] + bv.x) * QSCALE, (acc[mt][nt][1] + bv.y) * QSCALE);
            Qb[(size_t)(row + 8) * 128 + colp] =
                pack_bf16((acc[mt][nt][2] + bv.x) * QSCALE, (acc[mt][nt][3] + bv.y) * QSCALE);
        }
    }
}

// ---------------- kernel 3c: fused K+V projection --------------------------------------
// K -> bf16 [key][d] pairs;  V -> bf16 TRANSPOSED Vt[n][d][key] via smem transpose.
__global__ __launch_bounds__(256, 2) void gemm_kv_kernel(const float* __restrict__ A,
                                                         const float* __restrict__ Wk,
                                                         const float* __restrict__ Wv,
                                                         const float* __restrict__ bk,
                                                         const float* __restrict__ bv,
                                                         uint32_t* __restrict__ Kb,
                                                         uint16_t* __restrict__ Vt) {
    extern __shared__ float sm[];
    float (*As)[128][36]  = (float(*)[128][36])sm;                    // 2 stages
    float (*Wks)[64][36]  = (float(*)[64][36])(sm + 2 * 128 * 36);
    float (*Wvs)[64][36]  = (float(*)[64][36])(sm + 2 * 128 * 36 + 2 * 64 * 36);

    int m0 = blockIdx.x * 128, o0 = blockIdx.y * 64;
    int tid = threadIdx.x;
    int warp = tid >> 5, lane = tid & 31;
    int g = lane >> 2, c = lane & 3;
    int wm = (warp & 3) * 32;
    int wn = (warp >> 2) * 32;

    int sr = tid >> 3;
    int sc4 = (tid & 7) * 4;

    const float* Ap  = A + (size_t)(m0 + sr) * DMODEL + sc4;
    const float* Wkp = Wk + (size_t)(o0 + sr) * DMODEL + sc4;
    const float* Wvp = Wv + (size_t)(o0 + sr) * DMODEL + sc4;

#pragma unroll
    for (int j = 0; j < 4; ++j)
        cp16(&As[0][sr + 32 * j][sc4], Ap + (size_t)(32 * j) * DMODEL);
#pragma unroll
    for (int j = 0; j < 2; ++j) {
        cp16(&Wks[0][sr + 32 * j][sc4], Wkp + (size_t)(32 * j) * DMODEL);
        cp16(&Wvs[0][sr + 32 * j][sc4], Wvp + (size_t)(32 * j) * DMODEL);
    }
    cp_commit();

    float ack[2][4][4] = {};
    float acv[2][4][4] = {};

    for (int kc = 0; kc < 8; ++kc) {
        int buf = kc & 1;
        __syncthreads();
        if (kc < 7) {
            int ko = (kc + 1) * 32;
#pragma unroll
            for (int j = 0; j < 4; ++j)
                cp16(&As[buf ^ 1][sr + 32 * j][sc4], Ap + ko + (size_t)(32 * j) * DMODEL);
#pragma unroll
            for (int j = 0; j < 2; ++j) {
                cp16(&Wks[buf ^ 1][sr + 32 * j][sc4], Wkp + ko + (size_t)(32 * j) * DMODEL);
                cp16(&Wvs[buf ^ 1][sr + 32 * j][sc4], Wvp + ko + (size_t)(32 * j) * DMODEL);
            }
            cp_commit();
            cp_wait1();
        } else {
            cp_wait0();
        }
        __syncthreads();

#pragma unroll
        for (int ks = 0; ks < 4; ++ks) {
            int k = ks * 8;
            uint32_t af[2][4];
#pragma unroll
            for (int mt = 0; mt < 2; ++mt) {
                int r = wm + mt * 16;
                af[mt][0] = __float_as_uint(As[buf][r + g    ][k + c    ]);
                af[mt][1] = __float_as_uint(As[buf][r + g + 8][k + c    ]);
                af[mt][2] = __float_as_uint(As[buf][r + g    ][k + c + 4]);
                af[mt][3] = __float_as_uint(As[buf][r + g + 8][k + c + 4]);
            }
#pragma unroll
            for (int nt = 0; nt < 4; ++nt) {
                uint32_t k0 = __float_as_uint(Wks[buf][wn + nt * 8 + g][k + c    ]);
                uint32_t k1 = __float_as_uint(Wks[buf][wn + nt * 8 + g][k + c + 4]);
                uint32_t v0 = __float_as_uint(Wvs[buf][wn + nt * 8 + g][k + c    ]);
                uint32_t v1 = __float_as_uint(Wvs[buf][wn + nt * 8 + g][k + c + 4]);
                mma_tf32(ack[0][nt], af[0][0], af[0][1], af[0][2], af[0][3], k0, k1);
                mma_tf32(ack[1][nt], af[1][0], af[1][1], af[1][2], af[1][3], k0, k1);
                mma_tf32(acv[0][nt], af[0][0], af[0][1], af[0][2], af[0][3], v0, v1);
                mma_tf32(acv[1][nt], af[1][0], af[1][1], af[1][2], af[1][3], v0, v1);
            }
        }
    }

    // ---- K epilogue: bf16 pairs [key][d/2] ----
#pragma unroll
    for (int nt = 0; nt < 4; ++nt) {
        float2 bkv = *(const float2*)(bk + o0 + wn + nt * 8 + 2 * c);
        int colp = (o0 + wn) / 2 + nt * 4 + c;
#pragma unroll
        for (int mt = 0; mt < 2; ++mt) {
            int key = m0 + wm + mt * 16 + g;
            Kb[(size_t)key * 128 + colp] =
                pack_bf16(ack[mt][nt][0] + bkv.x, ack[mt][nt][1] + bkv.y);
            Kb[(size_t)(key + 8) * 128 + colp] =
                pack_bf16(ack[mt][nt][2] + bkv.x, ack[mt][nt][3] + bkv.y);
        }
    }

    // ---- V epilogue: bf16 transpose through smem (reuse As region) ----
    __syncthreads();
    uint16_t* vts = (uint16_t*)sm;     // [64][136] (d x key), stride 136 -> 16B-aligned rows
#pragma unroll
    for (int nt = 0; nt < 4; ++nt) {
        float2 bvv = *(const float2*)(bv + o0 + wn + nt * 8 + 2 * c);
        int d = wn + nt * 8 + 2 * c;
#pragma unroll
        for (int mt = 0; mt < 2; ++mt) {
            int key = wm + mt * 16 + g;
            vts[(d    ) * 136 + key    ] = bf16u(acv[mt][nt][0] + bvv.x);
            vts[(d + 1) * 136 + key    ] = bf16u(acv[mt][nt][1] + bvv.y);
            vts[(d    ) * 136 + key + 8] = bf16u(acv[mt][nt][2] + bvv.x);
            vts[(d + 1) * 136 + key + 8] = bf16u(acv[mt][nt][3] + bvv.y);
        }
    }
    __syncthreads();

    int dr = tid >> 2, kb = (tid & 3) * 32;
    int nb = m0 >> 12, key0 = m0 & (HWG - 1);
    uint16_t* dst = Vt + ((size_t)(nb * DMODEL + o0 + dr)) * HWG + key0 + kb;
#pragma unroll
    for (int j = 0; j < 4; ++j)
        *(uint4*)(dst + j * 8) = *(const uint4*)&vts[dr * 136 + kb + j * 8];
}

// ---------------- kernel 3b: register-prefetch tf32 GEMM with fused A2 add (O-proj) --
__global__ __launch_bounds__(256) void gemm_tf32_kernel(const float* __restrict__ A,
                                                        const float* __restrict__ A2,
                                                        const float* __restrict__ W,
                                                        const float* __restrict__ bias,
                                                        float* __restrict__ C) {
    __shared__ float As[128][36];
    __shared__ float Ws[64][36];

    int m0 = blockIdx.x * 128, o0 = blockIdx.y * 64;
    int tid = threadIdx.x;
    int warp = tid >> 5, lane = tid & 31;
    int g = lane >> 2, c = lane & 3;
    int wm = (warp & 3) * 32;
    int wn = (warp >> 2) * 32;

    int lr  = tid >> 3;
    int lk4 = (tid & 7) * 4;

    const float* Ap  = A + (size_t)(m0 + lr) * DMODEL + lk4;
    const float* A2p = A2 + (size_t)(m0 + lr) * DMODEL + lk4;
    const float* Wp  = W + (size_t)(o0 + lr) * DMODEL + lk4;

    float4 ra[4], rw[2];
#pragma unroll
    for (int i = 0; i < 4; ++i) {
        float4 v = *(const float4*)(Ap + (size_t)(32 * i) * DMODEL);
        float4 u = *(const float4*)(A2p + (size_t)(32 * i) * DMODEL);
        v.x += u.x; v.y += u.y; v.z += u.z; v.w += u.w;
        ra[i] = v;
    }
#pragma unroll
    for (int i = 0; i < 2; ++i)
        rw[i] = *(const float4*)(Wp + (size_t)(32 * i) * DMODEL);

    float acc[2][4][4] = {};

    for (int kc = 0; kc < 8; ++kc) {
#pragma unroll
        for (int i = 0; i < 4; ++i) {
            float4 v = ra[i];
            v.x = to_tf32(v.x); v.y = to_tf32(v.y); v.z = to_tf32(v.z); v.w = to_tf32(v.w);
            *(float4*)&As[lr + 32 * i][lk4] = v;
        }
#pragma unroll
        for (int i = 0; i < 2; ++i) {
            float4 v = rw[i];
            v.x = to_tf32(v.x); v.y = to_tf32(v.y); v.z = to_tf32(v.z); v.w = to_tf32(v.w);
            *(float4*)&Ws[lr + 32 * i][lk4] = v;
        }
        __syncthreads();

        if (kc < 7) {
            int ko = (kc + 1) * 32;
#pragma unroll
            for (int i = 0; i < 4; ++i) {
                float4 v = *(const float4*)(Ap + ko + (size_t)(32 * i) * DMODEL);
                float4 u = *(const float4*)(A2p + ko + (size_t)(32 * i) * DMODEL);
                v.x += u.x; v.y += u.y; v.z += u.z; v.w += u.w;
                ra[i] = v;
            }
#pragma unroll
            for (int i = 0; i < 2; ++i)
                rw[i] = *(const float4*)(Wp + ko + (size_t)(32 * i) * DMODEL);
        }

#pragma unroll
        for (int ks = 0; ks < 4; ++ks) {
            int k = ks * 8;
            uint32_t af[2][4];
#pragma unroll
            for (int mt = 0; mt < 2; ++mt) {
                int r = wm + mt * 16;
                af[mt][0] = __float_as_uint(As[r + g    ][k + c    ]);
                af[mt][1] = __float_as_uint(As[r + g + 8][k + c    ]);
                af[mt][2] = __float_as_uint(As[r + g    ][k + c + 4]);
                af[mt][3] = __float_as_uint(As[r + g + 8][k + c + 4]);
            }
#pragma unroll
            for (int nt = 0; nt < 4; ++nt) {
                uint32_t b0 = __float_as_uint(Ws[wn + nt * 8 + g][k + c    ]);
                uint32_t b1 = __float_as_uint(Ws[wn + nt * 8 + g][k + c + 4]);
                mma_tf32(acc[0][nt], af[0][0], af[0][1], af[0][2], af[0][3], b0, b1);
                mma_tf32(acc[1][nt], af[1][0], af[1][1], af[1][2], af[1][3], b0, b1);
            }
        }
        __syncthreads();
    }

#pragma unroll
    for (int nt = 0; nt < 4; ++nt) {
        float2 bv = *(const float2*)(bias + o0 + wn + nt * 8 + 2 * c);
#pragma unroll
        for (int mt = 0; mt < 2; ++mt) {
            int row = m0 + wm + mt * 16 + g;
            float* Cp = C + (size_t)row * DMODEL + o0 + wn + nt * 8 + 2 * c;
            *(float2*)Cp = make_float2(acc[mt][nt][0] + bv.x, acc[mt][nt][1] + bv.y);
            *(float2*)(Cp + (size_t)8 * DMODEL) =
                make_float2(acc[mt][nt][2] + bv.x, acc[mt][nt][3] + bv.y);
        }
    }
}

// ---------------- kernel 4: flash attention, full bf16 m16n8k16 ----------------------
__global__ __launch_bounds__(256, 2) void flash_attn_mma4_kernel(const uint32_t* __restrict__ Q,
                                                                 const uint16_t* __restrict__ K,
                                                                 const uint16_t* __restrict__ Vt,
                                                                 float* __restrict__ O) {
    __shared__ uint32_t Ks[2][64][20];     // [key][d-pair] bf16x2; stride 20 -> conflict-free
    __shared__ uint32_t Vs[2][32][36];     // [d][key-pair] bf16x2; conflict-free

    int qt = blockIdx.x, h = blockIdx.y, n = blockIdx.z;
    int tid  = threadIdx.x;
    int warp = tid >> 5, lane = tid & 31;
    int g = lane >> 2, c = lane & 3;

    // ---- preload Q fragments (bf16 pairs; pre-scaled by QSCALE) ----
    const uint32_t* Qb = Q + (size_t)(n * NP + qt * 128 + warp * 16) * 128 + h * (DH / 2);
    uint32_t qf[2][4];
#pragma unroll
    for (int ks = 0; ks < 2; ++ks) {
        qf[ks][0] = Qb[(size_t)g       * 128 + ks * 8 + c    ];
        qf[ks][1] = Qb[(size_t)(g + 8) * 128 + ks * 8 + c    ];
        qf[ks][2] = Qb[(size_t)g       * 128 + ks * 8 + c + 4];
        qf[ks][3] = Qb[(size_t)(g + 8) * 128 + ks * 8 + c + 4];
    }

    const uint16_t* Kb0 = K + (size_t)n * HWG * DMODEL + h * DH;
    const uint16_t* Vt0 = Vt + ((size_t)(n * DMODEL + h * DH)) * HWG;

    int ksr = tid >> 2;                // 0..63 (key)
    int ksc = (tid & 3) * 4;           // uint32 idx within row (4 per cp16)
    int vrow = tid >> 3;               // 0..31 (d)
    int vcol = (tid & 7) * 8;          // key offset (bf16)

    {
        cp16(&Ks[0][ksr][ksc], Kb0 + (size_t)ksr * DMODEL + ksc * 2);
        cp16(&Vs[0][vrow][vcol / 2], Vt0 + (size_t)vrow * HWG + vcol);
        cp_commit();
    }

    float m0 = -1e30f, m1 = -1e30f;
    float l0 = 0.0f, l1 = 0.0f;
    float oacc[4][4] = {};

    for (int kt = 0; kt < HWG / 64; ++kt) {
        int buf = kt & 1;
        __syncthreads();
        if (kt < HWG / 64 - 1) {
            const uint16_t* Kb = Kb0 + (size_t)(kt + 1) * 64 * DMODEL;
            const uint16_t* Vb = Vt0 + (kt + 1) * 64;
            cp16(&Ks[buf ^ 1][ksr][ksc], Kb + (size_t)ksr * DMODEL + ksc * 2);
            cp16(&Vs[buf ^ 1][vrow][vcol / 2], Vb + (size_t)vrow * HWG + vcol);
            cp_commit();
            cp_wait1();
        } else {
            cp_wait0();
        }
        __syncthreads();

        // ---- S = Q K^T (log2-scaled scores), bf16 m16n8k16 ----
        float sacc[8][4];
#pragma unroll
        for (int nt = 0; nt < 8; ++nt) {
            sacc[nt][0] = 0.f; sacc[nt][1] = 0.f; sacc[nt][2] = 0.f; sacc[nt][3] = 0.f;
#pragma unroll
            for (int ks = 0; ks < 2; ++ks) {
                uint32_t b0 = Ks[buf][nt * 8 + g][ks * 8 + c    ];
                uint32_t b1 = Ks[buf][nt * 8 + g][ks * 8 + c + 4];
                mma_bf16(sacc[nt], qf[ks][0], qf[ks][1], qf[ks][2], qf[ks][3], b0, b1);
            }
        }

        // ---- online softmax (log2 domain); l as per-thread partials ----
        float mx0 = -1e30f, mx1 = -1e30f;
#pragma unroll
        for (int nt = 0; nt < 8; ++nt) {
            mx0 = fmaxf(mx0, fmaxf(sacc[nt][0], sacc[nt][1]));
            mx1 = fmaxf(mx1, fmaxf(sacc[nt][2], sacc[nt][3]));
        }
        mx0 = fmaxf(mx0, __shfl_xor_sync(0xffffffffu, mx0, 1));
        mx0 = fmaxf(mx0, __shfl_xor_sync(0xffffffffu, mx0, 2));
        mx1 = fmaxf(mx1, __shfl_xor_sync(0xffffffffu, mx1, 1));
        mx1 = fmaxf(mx1, __shfl_xor_sync(0xffffffffu, mx1, 2));
        float nm0 = fmaxf(m0, mx0), nm1 = fmaxf(m1, mx1);
        float corr0 = ex2(m0 - nm0), corr1 = ex2(m1 - nm1);
        m0 = nm0; m1 = nm1;

        float s0 = 0.0f, s1 = 0.0f;
#pragma unroll
        for (int nt = 0; nt < 8; ++nt) {
            float p0 = ex2(sacc[nt][0] - m0);
            float p1 = ex2(sacc[nt][1] - m0);
            float p2 = ex2(sacc[nt][2] - m1);
            float p3 = ex2(sacc[nt][3] - m1);
            s0 += p0 + p1; s1 += p2 + p3;
            sacc[nt][0] = p0; sacc[nt][1] = p1; sacc[nt][2] = p2; sacc[nt][3] = p3;
        }
        l0 = l0 * corr0 + s0;
        l1 = l1 * corr1 + s1;
#pragma unroll
        for (int dt = 0; dt < 4; ++dt) {
            oacc[dt][0] *= corr0; oacc[dt][1] *= corr0;
            oacc[dt][2] *= corr1; oacc[dt][3] *= corr1;
        }

        // ---- O += P V : bf16 m16n8k16; C-frag packs DIRECTLY into A-frag ----
#pragma unroll
        for (int ks = 0; ks < 4; ++ks) {       // 4 k-steps of 16 keys
            uint32_t a0 = pack_bf16(sacc[2 * ks    ][0], sacc[2 * ks    ][1]);
            uint32_t a1 = pack_bf16(sacc[2 * ks    ][2], sacc[2 * ks    ][3]);
            uint32_t a2 = pack_bf16(sacc[2 * ks + 1][0], sacc[2 * ks + 1][1]);
            uint32_t a3 = pack_bf16(sacc[2 * ks + 1][2], sacc[2 * ks + 1][3]);
#pragma unroll
            for (int dt = 0; dt < 4; ++dt) {
                uint32_t b0 = Vs[buf][dt * 8 + g][ks * 8 + c    ];
                uint32_t b1 = Vs[buf][dt * 8 + g][ks * 8 + c + 4];
                mma_bf16(oacc[dt], a0, a1, a2, a3, b0, b1);
            }
        }
    }

    // ---- final l reduction across the 4 lanes of each row group ----
    l0 += __shfl_xor_sync(0xffffffffu, l0, 1);
    l0 += __shfl_xor_sync(0xffffffffu, l0, 2);
    l1 += __shfl_xor_sync(0xffffffffu, l1, 1);
    l1 += __shfl_xor_sync(0xffffffffu, l1, 2);

    float inv0 = 1.0f / l0, inv1 = 1.0f / l1;
    float* Ob = O + ((size_t)(n * NP + qt * 128 + warp * 16)) * DMODEL + h * DH;
#pragma unroll
    for (int dt = 0; dt < 4; ++dt) {
        *(float2*)(Ob + (size_t)g       * DMODEL + dt * 8 + 2 * c) =
            make_float2(oacc[dt][0] * inv0, oacc[dt][1] * inv0);
        *(float2*)(Ob + (size_t)(g + 8) * DMODEL + dt * 8 + 2 * c) =
            make_float2(oacc[dt][2] * inv1, oacc[dt][3] * inv1);
    }
}

// ---------------- launch ------------------------------------------------------------
extern "C" void kernel_launch(void* const* d_in, const int* in_sizes, int n_in,
                              void* d_out, int out_size) {
    const float* local_feat  = (const float*)d_in[0];
    const float* global_feat = (const float*)d_in[1];
    const float* Wq = (const float*)d_in[2];
    const float* bq = (const float*)d_in[3];
    const float* Wk = (const float*)d_in[4];
    const float* bk = (const float*)d_in[5];
    const float* Wv = (const float*)d_in[6];
    const float* bv = (const float*)d_in[7];
    const float* Wo = (const float*)d_in[8];
    const float* bo = (const float*)d_in[9];
    float* out = (float*)d_out;

    float *lf_pe, *gf_pe, *attn, *wq, *wk, *wv;
    uint16_t *q16, *k16, *vt;
    cudaGetSymbolAddress((void**)&lf_pe, g_lf_pe);
    cudaGetSymbolAddress((void**)&gf_pe, g_gf_pe);
    cudaGetSymbolAddress((void**)&q16,   g_q);
    cudaGetSymbolAddress((void**)&k16,   g_k);
    cudaGetSymbolAddress((void**)&vt,    g_vt);
    cudaGetSymbolAddress((void**)&attn,  g_attn);
    cudaGetSymbolAddress((void**)&wq,    g_wq);
    cudaGetSymbolAddress((void**)&wk,    g_wk);
    cudaGetSymbolAddress((void**)&wv,    g_wv);

    const int GEMM_SMEM = (2 * 128 * 36 + 2 * 64 * 36) * (int)sizeof(float);    // 55296
    const int KV_SMEM   = (2 * 128 * 36 + 4 * 64 * 36) * (int)sizeof(float);    // 73728
    static bool attr_set = false;
    if (!attr_set) {
        cudaFuncSetAttribute(gemm_q_kernel,
                             cudaFuncAttributeMaxDynamicSharedMemorySize, GEMM_SMEM);
        cudaFuncSetAttribute(gemm_kv_kernel,
                             cudaFuncAttributeMaxDynamicSharedMemorySize, KV_SMEM);
        attr_set = true;
    }

    // 0. round weights to tf32 once (off hot path)
    round_w_kernel<<<DMODEL * DMODEL / (256 * 4), 256>>>(Wq, Wk, Wv, wq, wk, wv);

    // 1. positional encodings (tf32-rounded outputs)
    pe_local_kernel<<<(NB * NP * DMODEL) / 256, 256>>>(local_feat, lf_pe);
    transpose_pe_kernel<<<dim3(HWG / 32, DMODEL / 32, NB), dim3(32, 8)>>>(global_feat, gf_pe);

    // 2. projections: Q -> bf16 (pre-scaled); K(bf16) + V^T(bf16) fused
    gemm_q_kernel<<<dim3((NB * NP) / 128, DMODEL / 64), 256, GEMM_SMEM>>>(
        lf_pe, wq, bq, (uint32_t*)q16);
    gemm_kv_kernel<<<dim3((NB * HWG) / 128, DMODEL / 64), 256, KV_SMEM>>>(
        gf_pe, wk, wv, bk, bv, (uint32_t*)k16, vt);

    // 3. attention (all-bf16 m16n8k16)
    flash_attn_mma4_kernel<<<dim3(NP / 128, NHEADS, NB), 256>>>(
        (const uint32_t*)q16, k16, vt, attn);

    // 4. output projection with fused residual
    gemm_tf32_kernel<<<dim3((NB * NP) / 128, DMODEL / 64), 256>>>(lf_pe, attn, Wo, bo, out);
}

// round 16
// speedup vs baseline: 6.6791x; 1.2409x over previous
#include <cuda_runtime.h>
#include <cstdint>
#include <cstddef>

// Problem constants
#define NB   4        // batch
#define NP   1024     // local tokens (32x32)
#define DMODEL 256
#define HWG  4096     // global tokens (64x64)
#define NHEADS 8
#define DH   32
// -ln(10000)/256
#define NEG_LOG1E4_OVER_D (-0.035977892078030406f)
#define ATTN_SCALE 0.17677669529663687f            // 1/sqrt(32)
#define LOG2E 1.4426950408889634f
#define QSCALE (0.25501643154277775f)              // ATTN_SCALE * LOG2E

// ---------------- scratch (static device allocations; no cudaMalloc) ----------------
__device__ float    g_lf_pe[NB * NP * DMODEL];     // fp32 (tf32-rounded) for O-proj
__device__ uint16_t g_lf16[NB * NP * DMODEL];      // bf16 copy for Q-proj
__device__ uint16_t g_gf16[NB * HWG * DMODEL];     // bf16 transposed global feat + PE
__device__ uint16_t g_q[NB * NP * DMODEL];         // Q bf16 (pre-scaled by QSCALE)
__device__ uint16_t g_k[NB * HWG * DMODEL];        // K bf16 [key][d]
__device__ uint16_t g_vt[NB * DMODEL * HWG];       // V^T bf16 [n][d][key]
__device__ float    g_attn[NB * NP * DMODEL];
__device__ uint32_t g_wq[DMODEL * 128];            // bf16-pair packed weights [n][k/2]
__device__ uint32_t g_wk[DMODEL * 128];
__device__ uint32_t g_wv[DMODEL * 128];

// ---------------- helpers ------------------------------------------------------------
__device__ __forceinline__ float to_tf32(float x) {
    uint32_t u;
    asm("cvt.rna.tf32.f32 %0, %1;" : "=r"(u) : "f"(x));
    return __uint_as_float(u);
}
__device__ __forceinline__ float ex2(float x) {
    float y;
    asm("ex2.approx.f32 %0, %1;" : "=f"(y) : "f"(x));
    return y;
}
// pack two f32 into bf16x2: lo -> lower 16 bits, hi -> upper 16 bits
__device__ __forceinline__ uint32_t pack_bf16(float lo, float hi) {
    uint32_t r;
    asm("cvt.rn.bf16x2.f32 %0, %1, %2;" : "=r"(r) : "f"(hi), "f"(lo));
    return r;
}
__device__ __forceinline__ uint16_t bf16u(float x) {
    uint16_t r;
    asm("cvt.rn.bf16.f32 %0, %1;" : "=h"(r) : "f"(x));
    return r;
}
__device__ __forceinline__ void mma_tf32(float* d,
                                         uint32_t a0, uint32_t a1, uint32_t a2, uint32_t a3,
                                         uint32_t b0, uint32_t b1) {
    asm volatile(
        "mma.sync.aligned.m16n8k8.row.col.f32.tf32.tf32.f32 "
        "{%0,%1,%2,%3}, {%4,%5,%6,%7}, {%8,%9}, {%0,%1,%2,%3};\n"
        : "+f"(d[0]), "+f"(d[1]), "+f"(d[2]), "+f"(d[3])
        : "r"(a0), "r"(a1), "r"(a2), "r"(a3), "r"(b0), "r"(b1));
}
__device__ __forceinline__ void mma_bf16(float* d,
                                         uint32_t a0, uint32_t a1, uint32_t a2, uint32_t a3,
                                         uint32_t b0, uint32_t b1) {
    asm volatile(
        "mma.sync.aligned.m16n8k16.row.col.f32.bf16.bf16.f32 "
        "{%0,%1,%2,%3}, {%4,%5,%6,%7}, {%8,%9}, {%0,%1,%2,%3};\n"
        : "+f"(d[0]), "+f"(d[1]), "+f"(d[2]), "+f"(d[3])
        : "r"(a0), "r"(a1), "r"(a2), "r"(a3), "r"(b0), "r"(b1));
}
__device__ __forceinline__ void cp16(const void* smem_dst, const void* gmem_src) {
    uint32_t d = (uint32_t)__cvta_generic_to_shared(smem_dst);
    asm volatile("cp.async.ca.shared.global [%0], [%1], 16;" :: "r"(d), "l"(gmem_src));
}
__device__ __forceinline__ void cp_commit() { asm volatile("cp.async.commit_group;"); }
__device__ __forceinline__ void cp_wait1()  { asm volatile("cp.async.wait_group 1;"); }
__device__ __forceinline__ void cp_wait0()  { asm volatile("cp.async.wait_group 0;"); }

// ---------------- kernel 0: pack Wq/Wk/Wv to bf16 pairs ------------------------------
__global__ __launch_bounds__(256) void round_w_kernel(const float* __restrict__ Wq,
                                                      const float* __restrict__ Wk,
                                                      const float* __restrict__ Wv,
                                                      uint32_t* __restrict__ wq,
                                                      uint32_t* __restrict__ wk,
                                                      uint32_t* __restrict__ wv) {
    int i = (blockIdx.x * 256 + threadIdx.x) * 4;      // element index, 65536 total
    float4 a = *(const float4*)(Wq + i);
    float4 b = *(const float4*)(Wk + i);
    float4 c = *(const float4*)(Wv + i);
    int p = i >> 1;
    wq[p] = pack_bf16(a.x, a.y); wq[p + 1] = pack_bf16(a.z, a.w);
    wk[p] = pack_bf16(b.x, b.y); wk[p + 1] = pack_bf16(b.z, b.w);
    wv[p] = pack_bf16(c.x, c.y); wv[p + 1] = pack_bf16(c.z, c.w);
}

// ---------------- kernel 1: local_feat + PE -> fp32(tf32) + bf16 ---------------------
__global__ __launch_bounds__(256) void pe_local_kernel(const float* __restrict__ in,
                                                       float* __restrict__ out,
                                                       uint16_t* __restrict__ out16) {
    int idx = blockIdx.x * 256 + threadIdx.x;
    int d = idx & (DMODEL - 1);
    int p = (idx >> 8) & (NP - 1);
    float x = (float)(p & 31) * (1.0f / 31.0f);
    float y = (float)(p >> 5) * (1.0f / 31.0f);
    float div = __expf((float)(d & ~1) * NEG_LOG1E4_OVER_D);
    float pe = (d & 1) ? __cosf(y * div) : __sinf(x * div);
    float v = in[idx] + pe;
    out[idx] = to_tf32(v);
    out16[idx] = bf16u(v);
}

// ---------------- kernel 2: transpose global_feat + PE -> bf16 -----------------------
__global__ __launch_bounds__(256) void transpose_pe_kernel(const float* __restrict__ gf,
                                                           uint16_t* __restrict__ out16) {
    __shared__ float tile[32][33];
    int n  = blockIdx.z;
    int s0 = blockIdx.x * 32;
    int d0 = blockIdx.y * 32;
    int tx = threadIdx.x, ty = threadIdx.y;
    const float* g = gf + ((size_t)n * DMODEL + d0) * HWG + s0;
#pragma unroll
    for (int k = 0; k < 4; ++k)
        tile[ty + 8 * k][tx] = g[(size_t)(ty + 8 * k) * HWG + tx];
    __syncthreads();
#pragma unroll
    for (int k = 0; k < 4; ++k) {
        int s = s0 + ty + 8 * k;
        int d = d0 + tx;
        float x = (float)(s & 63) * (1.0f / 63.0f);
        float y = (float)(s >> 6) * (1.0f / 63.0f);
        float div = __expf((float)(d & ~1) * NEG_LOG1E4_OVER_D);
        float pe = (d & 1) ? __cosf(y * div) : __sinf(x * div);
        out16[((size_t)n * HWG + s) * DMODEL + d] = bf16u(tile[tx][ty + 8 * k] + pe);
    }
}

// ---------------- kernel 3a: bf16 Q projection (m16n8k16) ----------------------------
// A: bf16 [M][256], W: bf16 pairs [256][128]. Out: bf16 pairs, scaled by QSCALE.
__global__ __launch_bounds__(256, 2) void gemm_q_bf16_kernel(const uint16_t* __restrict__ A,
                                                             const uint32_t* __restrict__ W,
                                                             const float* __restrict__ bias,
                                                             uint32_t* __restrict__ Qb) {
    extern __shared__ uint32_t smq[];
    uint32_t (*As)[128][20] = (uint32_t(*)[128][20])smq;
    uint32_t (*Ws)[64][20]  = (uint32_t(*)[64][20])(smq + 2 * 128 * 20);

    int m0 = blockIdx.x * 128, o0 = blockIdx.y * 64;
    int tid = threadIdx.x;
    int warp = tid >> 5, lane = tid & 31;
    int g = lane >> 2, c = lane & 3;
    int wm = (warp & 3) * 32;
    int wn = (warp >> 2) * 32;

    int ar = tid >> 1, ah = tid & 1;       // A staging: row, half
    int wr = tid >> 2, wsg = tid & 3;      // W staging: row, quarter

    const uint16_t* Ap = A + (size_t)(m0 + ar) * DMODEL + ah * 16;
    const uint32_t* Wp = W + (size_t)(o0 + wr) * 128 + wsg * 4;

    // stage chunk 0
    cp16(&As[0][ar][ah * 8],     Ap);
    cp16(&As[0][ar][ah * 8 + 4], Ap + 8);
    cp16(&Ws[0][wr][wsg * 4],    Wp);
    cp_commit();

    float acc[2][4][4] = {};

    for (int kc = 0; kc < 8; ++kc) {
        int buf = kc & 1;
        __syncthreads();
        if (kc < 7) {
            cp16(&As[buf ^ 1][ar][ah * 8],     Ap + (kc + 1) * 32);
            cp16(&As[buf ^ 1][ar][ah * 8 + 4], Ap + (kc + 1) * 32 + 8);
            cp16(&Ws[buf ^ 1][wr][wsg * 4],    Wp + (kc + 1) * 16);
            cp_commit();
            cp_wait1();
        } else {
            cp_wait0();
        }
        __syncthreads();

#pragma unroll
        for (int ks = 0; ks < 2; ++ks) {
            uint32_t af[2][4];
#pragma unroll
            for (int mt = 0; mt < 2; ++mt) {
                int r = wm + mt * 16;
                af[mt][0] = As[buf][r + g    ][ks * 8 + c    ];
                af[mt][1] = As[buf][r + g + 8][ks * 8 + c    ];
                af[mt][2] = As[buf][r + g    ][ks * 8 + c + 4];
                af[mt][3] = As[buf][r + g + 8][ks * 8 + c + 4];
            }
#pragma unroll
            for (int nt = 0; nt < 4; ++nt) {
                uint32_t b0 = Ws[buf][wn + nt * 8 + g][ks * 8 + c    ];
                uint32_t b1 = Ws[buf][wn + nt * 8 + g][ks * 8 + c + 4];
                mma_bf16(acc[0][nt], af[0][0], af[0][1], af[0][2], af[0][3], b0, b1);
                mma_bf16(acc[1][nt], af[1][0], af[1][1], af[1][2], af[1][3], b0, b1);
            }
        }
    }

    // epilogue: bias, QSCALE, pack to bf16 pairs [token][d/2]
#pragma unroll
    for (int nt = 0; nt < 4; ++nt) {
        float2 bv = *(const float2*)(bias + o0 + wn + nt * 8 + 2 * c);
        int colp = (o0 + wn) / 2 + nt * 4 + c;
#pragma unroll
        for (int mt = 0; mt < 2; ++mt) {
            int row = m0 + wm + mt * 16 + g;
            Qb[(size_t)row * 128 + colp] =
                pack_bf16((acc[mt][nt][0] + bv.x) * QSCALE, (acc[mt][nt][1] + bv.y) * QSCALE);
            Qb[(size_t)(row + 8) * 128 + colp] =
                pack_bf16((acc[mt][nt][2] + bv.x) * QSCALE, (acc[mt][nt][3] + bv.y) * QSCALE);
        }
    }
}

// ---------------- kernel 3c: fused bf16 K+V projection -------------------------------
// K -> bf16 pairs [key][d/2];  V -> bf16 transposed Vt[n][d][key] via smem transpose.
__global__ __launch_bounds__(256, 2) void gemm_kv_bf16_kernel(const uint16_t* __restrict__ A,
                                                              const uint32_t* __restrict__ Wk,
                                                              const uint32_t* __restrict__ Wv,
                                                              const float* __restrict__ bk,
                                                              const float* __restrict__ bv,
                                                              uint32_t* __restrict__ Kb,
                                                              uint16_t* __restrict__ Vt) {
    extern __shared__ uint32_t smkv[];
    uint32_t (*As)[128][20]  = (uint32_t(*)[128][20])smkv;
    uint32_t (*Wks)[64][20]  = (uint32_t(*)[64][20])(smkv + 2 * 128 * 20);
    uint32_t (*Wvs)[64][20]  = (uint32_t(*)[64][20])(smkv + 2 * 128 * 20 + 2 * 64 * 20);

    int m0 = blockIdx.x * 128, o0 = blockIdx.y * 64;
    int tid = threadIdx.x;
    int warp = tid >> 5, lane = tid & 31;
    int g = lane >> 2, c = lane & 3;
    int wm = (warp & 3) * 32;
    int wn = (warp >> 2) * 32;

    int ar = tid >> 1, ah = tid & 1;
    int wr = tid >> 2, wsg = tid & 3;

    const uint16_t* Ap  = A + (size_t)(m0 + ar) * DMODEL + ah * 16;
    const uint32_t* Wkp = Wk + (size_t)(o0 + wr) * 128 + wsg * 4;
    const uint32_t* Wvp = Wv + (size_t)(o0 + wr) * 128 + wsg * 4;

    cp16(&As[0][ar][ah * 8],     Ap);
    cp16(&As[0][ar][ah * 8 + 4], Ap + 8);
    cp16(&Wks[0][wr][wsg * 4],   Wkp);
    cp16(&Wvs[0][wr][wsg * 4],   Wvp);
    cp_commit();

    float ack[2][4][4] = {};
    float acv[2][4][4] = {};

    for (int kc = 0; kc < 8; ++kc) {
        int buf = kc & 1;
        __syncthreads();
        if (kc < 7) {
            cp16(&As[buf ^ 1][ar][ah * 8],     Ap + (kc + 1) * 32);
            cp16(&As[buf ^ 1][ar][ah * 8 + 4], Ap + (kc + 1) * 32 + 8);
            cp16(&Wks[buf ^ 1][wr][wsg * 4],   Wkp + (kc + 1) * 16);
            cp16(&Wvs[buf ^ 1][wr][wsg * 4],   Wvp + (kc + 1) * 16);
            cp_commit();
            cp_wait1();
        } else {
            cp_wait0();
        }
        __syncthreads();

#pragma unroll
        for (int ks = 0; ks < 2; ++ks) {
            uint32_t af[2][4];
#pragma unroll
            for (int mt = 0; mt < 2; ++mt) {
                int r = wm + mt * 16;
                af[mt][0] = As[buf][r + g    ][ks * 8 + c    ];
                af[mt][1] = As[buf][r + g + 8][ks * 8 + c    ];
                af[mt][2] = As[buf][r + g    ][ks * 8 + c + 4];
                af[mt][3] = As[buf][r + g + 8][ks * 8 + c + 4];
            }
#pragma unroll
            for (int nt = 0; nt < 4; ++nt) {
                uint32_t k0 = Wks[buf][wn + nt * 8 + g][ks * 8 + c    ];
                uint32_t k1 = Wks[buf][wn + nt * 8 + g][ks * 8 + c + 4];
                uint32_t v0 = Wvs[buf][wn + nt * 8 + g][ks * 8 + c    ];
                uint32_t v1 = Wvs[buf][wn + nt * 8 + g][ks * 8 + c + 4];
                mma_bf16(ack[0][nt], af[0][0], af[0][1], af[0][2], af[0][3], k0, k1);
                mma_bf16(ack[1][nt], af[1][0], af[1][1], af[1][2], af[1][3], k0, k1);
                mma_bf16(acv[0][nt], af[0][0], af[0][1], af[0][2], af[0][3], v0, v1);
                mma_bf16(acv[1][nt], af[1][0], af[1][1], af[1][2], af[1][3], v0, v1);
            }
        }
    }

    // ---- K epilogue: bf16 pairs [key][d/2] ----
#pragma unroll
    for (int nt = 0; nt < 4; ++nt) {
        float2 bkv = *(const float2*)(bk + o0 + wn + nt * 8 + 2 * c);
        int colp = (o0 + wn) / 2 + nt * 4 + c;
#pragma unroll
        for (int mt = 0; mt < 2; ++mt) {
            int key = m0 + wm + mt * 16 + g;
            Kb[(size_t)key * 128 + colp] =
                pack_bf16(ack[mt][nt][0] + bkv.x, ack[mt][nt][1] + bkv.y);
            Kb[(size_t)(key + 8) * 128 + colp] =
                pack_bf16(ack[mt][nt][2] + bkv.x, ack[mt][nt][3] + bkv.y);
        }
    }

    // ---- V epilogue: bf16 transpose through smem (reuse As region) ----
    __syncthreads();
    uint16_t* vts = (uint16_t*)smkv;   // [64][136] (d x key) = 17408 B <= 40960 B
#pragma unroll
    for (int nt = 0; nt < 4; ++nt) {
        float2 bvv = *(const float2*)(bv + o0 + wn + nt * 8 + 2 * c);
        int d = wn + nt * 8 + 2 * c;
#pragma unroll
        for (int mt = 0; mt < 2; ++mt) {
            int key = wm + mt * 16 + g;
            vts[(d    ) * 136 + key    ] = bf16u(acv[mt][nt][0] + bvv.x);
            vts[(d + 1) * 136 + key    ] = bf16u(acv[mt][nt][1] + bvv.y);
            vts[(d    ) * 136 + key + 8] = bf16u(acv[mt][nt][2] + bvv.x);
            vts[(d + 1) * 136 + key + 8] = bf16u(acv[mt][nt][3] + bvv.y);
        }
    }
    __syncthreads();

    int dr = tid >> 2, kb = (tid & 3) * 32;
    int nb = m0 >> 12, key0 = m0 & (HWG - 1);
    uint16_t* dst = Vt + ((size_t)(nb * DMODEL + o0 + dr)) * HWG + key0 + kb;
#pragma unroll
    for (int j = 0; j < 4; ++j)
        *(uint4*)(dst + j * 8) = *(const uint4*)&vts[dr * 136 + kb + j * 8];
}

// ---------------- kernel 3b: tf32 O-projection with fused residual (precision path) --
__global__ __launch_bounds__(256) void gemm_tf32_kernel(const float* __restrict__ A,
                                                        const float* __restrict__ A2,
                                                        const float* __restrict__ W,
                                                        const float* __restrict__ bias,
                                                        float* __restrict__ C) {
    __shared__ float As[128][36];
    __shared__ float Ws[64][36];

    int m0 = blockIdx.x * 128, o0 = blockIdx.y * 64;
    int tid = threadIdx.x;
    int warp = tid >> 5, lane = tid & 31;
    int g = lane >> 2, c = lane & 3;
    int wm = (warp & 3) * 32;
    int wn = (warp >> 2) * 32;

    int lr  = tid >> 3;
    int lk4 = (tid & 7) * 4;

    const float* Ap  = A + (size_t)(m0 + lr) * DMODEL + lk4;
    const float* A2p = A2 + (size_t)(m0 + lr) * DMODEL + lk4;
    const float* Wp  = W + (size_t)(o0 + lr) * DMODEL + lk4;

    float4 ra[4], rw[2];
#pragma unroll
    for (int i = 0; i < 4; ++i) {
        float4 v = *(const float4*)(Ap + (size_t)(32 * i) * DMODEL);
        float4 u = *(const float4*)(A2p + (size_t)(32 * i) * DMODEL);
        v.x += u.x; v.y += u.y; v.z += u.z; v.w += u.w;
        ra[i] = v;
    }
#pragma unroll
    for (int i = 0; i < 2; ++i)
        rw[i] = *(const float4*)(Wp + (size_t)(32 * i) * DMODEL);

    float acc[2][4][4] = {};

    for (int kc = 0; kc < 8; ++kc) {
#pragma unroll
        for (int i = 0; i < 4; ++i) {
            float4 v = ra[i];
            v.x = to_tf32(v.x); v.y = to_tf32(v.y); v.z = to_tf32(v.z); v.w = to_tf32(v.w);
            *(float4*)&As[lr + 32 * i][lk4] = v;
        }
#pragma unroll
        for (int i = 0; i < 2; ++i) {
            float4 v = rw[i];
            v.x = to_tf32(v.x); v.y = to_tf32(v.y); v.z = to_tf32(v.z); v.w = to_tf32(v.w);
            *(float4*)&Ws[lr + 32 * i][lk4] = v;
        }
        __syncthreads();

        if (kc < 7) {
            int ko = (kc + 1) * 32;
#pragma unroll
            for (int i = 0; i < 4; ++i) {
                float4 v = *(const float4*)(Ap + ko + (size_t)(32 * i) * DMODEL);
                float4 u = *(const float4*)(A2p + ko + (size_t)(32 * i) * DMODEL);
                v.x += u.x; v.y += u.y; v.z += u.z; v.w += u.w;
                ra[i] = v;
            }
#pragma unroll
            for (int i = 0; i < 2; ++i)
                rw[i] = *(const float4*)(Wp + ko + (size_t)(32 * i) * DMODEL);
        }

#pragma unroll
        for (int ks = 0; ks < 4; ++ks) {
            int k = ks * 8;
            uint32_t af[2][4];
#pragma unroll
            for (int mt = 0; mt < 2; ++mt) {
                int r = wm + mt * 16;
                af[mt][0] = __float_as_uint(As[r + g    ][k + c    ]);
                af[mt][1] = __float_as_uint(As[r + g + 8][k + c    ]);
                af[mt][2] = __float_as_uint(As[r + g    ][k + c + 4]);
                af[mt][3] = __float_as_uint(As[r + g + 8][k + c + 4]);
            }
#pragma unroll
            for (int nt = 0; nt < 4; ++nt) {
                uint32_t b0 = __float_as_uint(Ws[wn + nt * 8 + g][k + c    ]);
                uint32_t b1 = __float_as_uint(Ws[wn + nt * 8 + g][k + c + 4]);
                mma_tf32(acc[0][nt], af[0][0], af[0][1], af[0][2], af[0][3], b0, b1);
                mma_tf32(acc[1][nt], af[1][0], af[1][1], af[1][2], af[1][3], b0, b1);
            }
        }
        __syncthreads();
    }

#pragma unroll
    for (int nt = 0; nt < 4; ++nt) {
        float2 bv = *(const float2*)(bias + o0 + wn + nt * 8 + 2 * c);
#pragma unroll
        for (int mt = 0; mt < 2; ++mt) {
            int row = m0 + wm + mt * 16 + g;
            float* Cp = C + (size_t)row * DMODEL + o0 + wn + nt * 8 + 2 * c;
            *(float2*)Cp = make_float2(acc[mt][nt][0] + bv.x, acc[mt][nt][1] + bv.y);
            *(float2*)(Cp + (size_t)8 * DMODEL) =
                make_float2(acc[mt][nt][2] + bv.x, acc[mt][nt][3] + bv.y);
        }
    }
}

// ---------------- kernel 4: flash attention, bf16, NO running max --------------------
// Scores bounded: |s_log2| <= ~9 (Cauchy-Schwarz on q,k norms), so p = 2^s, l, oacc all
// stay comfortably in fp32 range without max subtraction -> no shfl/corr chain in loop.
__global__ __launch_bounds__(256, 2) void flash_attn_mma5_kernel(const uint32_t* __restrict__ Q,
                                                                 const uint16_t* __restrict__ K,
                                                                 const uint16_t* __restrict__ Vt,
                                                                 float* __restrict__ O) {
    __shared__ uint32_t Ks[2][64][20];     // [key][d-pair] bf16x2; conflict-free
    __shared__ uint32_t Vs[2][32][36];     // [d][key-pair] bf16x2; conflict-free

    int qt = blockIdx.x, h = blockIdx.y, n = blockIdx.z;
    int tid  = threadIdx.x;
    int warp = tid >> 5, lane = tid & 31;
    int g = lane >> 2, c = lane & 3;

    // ---- preload Q fragments (bf16 pairs; pre-scaled by QSCALE) ----
    const uint32_t* Qb = Q + (size_t)(n * NP + qt * 128 + warp * 16) * 128 + h * (DH / 2);
    uint32_t qf[2][4];
#pragma unroll
    for (int ks = 0; ks < 2; ++ks) {
        qf[ks][0] = Qb[(size_t)g       * 128 + ks * 8 + c    ];
        qf[ks][1] = Qb[(size_t)(g + 8) * 128 + ks * 8 + c    ];
        qf[ks][2] = Qb[(size_t)g       * 128 + ks * 8 + c + 4];
        qf[ks][3] = Qb[(size_t)(g + 8) * 128 + ks * 8 + c + 4];
    }

    const uint16_t* Kb0 = K + (size_t)n * HWG * DMODEL + h * DH;
    const uint16_t* Vt0 = Vt + ((size_t)(n * DMODEL + h * DH)) * HWG;

    int ksr = tid >> 2;                // 0..63 (key)
    int ksc = (tid & 3) * 4;           // uint32 idx within row
    int vrow = tid >> 3;               // 0..31 (d)
    int vcol = (tid & 7) * 8;          // key offset (bf16)

    {
        cp16(&Ks[0][ksr][ksc], Kb0 + (size_t)ksr * DMODEL + ksc * 2);
        cp16(&Vs[0][vrow][vcol / 2], Vt0 + (size_t)vrow * HWG + vcol);
        cp_commit();
    }

    float l0 = 0.0f, l1 = 0.0f;        // per-thread partial sums
    float oacc[4][4] = {};

    for (int kt = 0; kt < HWG / 64; ++kt) {
        int buf = kt & 1;
        __syncthreads();
        if (kt < HWG / 64 - 1) {
            const uint16_t* Kb = Kb0 + (size_t)(kt + 1) * 64 * DMODEL;
            const uint16_t* Vb = Vt0 + (kt + 1) * 64;
            cp16(&Ks[buf ^ 1][ksr][ksc], Kb + (size_t)ksr * DMODEL + ksc * 2);
            cp16(&Vs[buf ^ 1][vrow][vcol / 2], Vb + (size_t)vrow * HWG + vcol);
            cp_commit();
            cp_wait1();
        } else {
            cp_wait0();
        }
        __syncthreads();

        // ---- S = Q K^T (log2-scaled scores), bf16 m16n8k16 ----
        float sacc[8][4];
#pragma unroll
        for (int nt = 0; nt < 8; ++nt) {
            sacc[nt][0] = 0.f; sacc[nt][1] = 0.f; sacc[nt][2] = 0.f; sacc[nt][3] = 0.f;
#pragma unroll
            for (int ks = 0; ks < 2; ++ks) {
                uint32_t b0 = Ks[buf][nt * 8 + g][ks * 8 + c    ];
                uint32_t b1 = Ks[buf][nt * 8 + g][ks * 8 + c + 4];
                mma_bf16(sacc[nt], qf[ks][0], qf[ks][1], qf[ks][2], qf[ks][3], b0, b1);
            }
        }

        // ---- softmax numerators, fixed reference m=0: p = 2^s ----
#pragma unroll
        for (int nt = 0; nt < 8; ++nt) {
            float p0 = ex2(sacc[nt][0]);
            float p1 = ex2(sacc[nt][1]);
            float p2 = ex2(sacc[nt][2]);
            float p3 = ex2(sacc[nt][3]);
            l0 += p0 + p1; l1 += p2 + p3;
            sacc[nt][0] = p0; sacc[nt][1] = p1; sacc[nt][2] = p2; sacc[nt][3] = p3;
        }

        // ---- O += P V : bf16 m16n8k16; C-frag packs DIRECTLY into A-frag ----
#pragma unroll
        for (int ks = 0; ks < 4; ++ks) {       // 4 k-steps of 16 keys
            uint32_t a0 = pack_bf16(sacc[2 * ks    ][0], sacc[2 * ks    ][1]);
            uint32_t a1 = pack_bf16(sacc[2 * ks    ][2], sacc[2 * ks    ][3]);
            uint32_t a2 = pack_bf16(sacc[2 * ks + 1][0], sacc[2 * ks + 1][1]);
            uint32_t a3 = pack_bf16(sacc[2 * ks + 1][2], sacc[2 * ks + 1][3]);
#pragma unroll
            for (int dt = 0; dt < 4; ++dt) {
                uint32_t b0 = Vs[buf][dt * 8 + g][ks * 8 + c    ];
                uint32_t b1 = Vs[buf][dt * 8 + g][ks * 8 + c + 4];
                mma_bf16(oacc[dt], a0, a1, a2, a3, b0, b1);
            }
        }
    }

    // ---- final l reduction across the 4 lanes of each row group ----
    l0 += __shfl_xor_sync(0xffffffffu, l0, 1);
    l0 += __shfl_xor_sync(0xffffffffu, l0, 2);
    l1 += __shfl_xor_sync(0xffffffffu, l1, 1);
    l1 += __shfl_xor_sync(0xffffffffu, l1, 2);

    float inv0 = 1.0f / l0, inv1 = 1.0f / l1;
    float* Ob = O + ((size_t)(n * NP + qt * 128 + warp * 16)) * DMODEL + h * DH;
#pragma unroll
    for (int dt = 0; dt < 4; ++dt) {
        *(float2*)(Ob + (size_t)g       * DMODEL + dt * 8 + 2 * c) =
            make_float2(oacc[dt][0] * inv0, oacc[dt][1] * inv0);
        *(float2*)(Ob + (size_t)(g + 8) * DMODEL + dt * 8 + 2 * c) =
            make_float2(oacc[dt][2] * inv1, oacc[dt][3] * inv1);
    }
}

// ---------------- launch ------------------------------------------------------------
extern "C" void kernel_launch(void* const* d_in, const int* in_sizes, int n_in,
                              void* d_out, int out_size) {
    const float* local_feat  = (const float*)d_in[0];
    const float* global_feat = (const float*)d_in[1];
    const float* Wq = (const float*)d_in[2];
    const float* bq = (const float*)d_in[3];
    const float* Wk = (const float*)d_in[4];
    const float* bk = (const float*)d_in[5];
    const float* Wv = (const float*)d_in[6];
    const float* bv = (const float*)d_in[7];
    const float* Wo = (const float*)d_in[8];
    const float* bo = (const float*)d_in[9];
    float* out = (float*)d_out;

    float *lf_pe, *attn;
    uint16_t *lf16, *gf16, *q16, *k16, *vt;
    uint32_t *wq, *wk, *wv;
    cudaGetSymbolAddress((void**)&lf_pe, g_lf_pe);
    cudaGetSymbolAddress((void**)&lf16,  g_lf16);
    cudaGetSymbolAddress((void**)&gf16,  g_gf16);
    cudaGetSymbolAddress((void**)&q16,   g_q);
    cudaGetSymbolAddress((void**)&k16,   g_k);
    cudaGetSymbolAddress((void**)&vt,    g_vt);
    cudaGetSymbolAddress((void**)&attn,  g_attn);
    cudaGetSymbolAddress((void**)&wq,    g_wq);
    cudaGetSymbolAddress((void**)&wk,    g_wk);
    cudaGetSymbolAddress((void**)&wv,    g_wv);

    const int Q_SMEM  = (2 * 128 * 20 + 2 * 64 * 20) * (int)sizeof(uint32_t);   // 30720
    const int KV_SMEM = (2 * 128 * 20 + 4 * 64 * 20) * (int)sizeof(uint32_t);   // 40960
    static bool attr_set = false;
    if (!attr_set) {
        cudaFuncSetAttribute(gemm_q_bf16_kernel,
                             cudaFuncAttributeMaxDynamicSharedMemorySize, Q_SMEM);
        cudaFuncSetAttribute(gemm_kv_bf16_kernel,
                             cudaFuncAttributeMaxDynamicSharedMemorySize, KV_SMEM);
        attr_set = true;
    }

    // 0. pack weights to bf16 pairs
    round_w_kernel<<<DMODEL * DMODEL / (256 * 4), 256>>>(Wq, Wk, Wv, wq, wk, wv);

    // 1. positional encodings
    pe_local_kernel<<<(NB * NP * DMODEL) / 256, 256>>>(local_feat, lf_pe, lf16);
    transpose_pe_kernel<<<dim3(HWG / 32, DMODEL / 32, NB), dim3(32, 8)>>>(global_feat, gf16);

    // 2. projections (bf16 tensor cores)
    gemm_q_bf16_kernel<<<dim3((NB * NP) / 128, DMODEL / 64), 256, Q_SMEM>>>(
        lf16, wq, bq, (uint32_t*)q16);
    gemm_kv_bf16_kernel<<<dim3((NB * HWG) / 128, DMODEL / 64), 256, KV_SMEM>>>(
        gf16, wk, wv, bk, bv, (uint32_t*)k16, vt);

    // 3. attention (bf16, no-max softmax)
    flash_attn_mma5_kernel<<<dim3(NP / 128, NHEADS, NB), 256>>>(
        (const uint32_t*)q16, k16, vt, attn);

    // 4. output projection with fused residual (tf32 — precision-critical)
    gemm_tf32_kernel<<<dim3((NB * NP) / 128, DMODEL / 64), 256>>>(lf_pe, attn, Wo, bo, out);
}